// round 10
// baseline (speedup 1.0000x reference)
#include <cuda_runtime.h>
#include <cuda_bf16.h>
#include <cstdint>

// ---------------------------------------------------------------------------
// DAGCondGNNEncoder (sm_103 HMMA path): split-bf16 mma.sync GEMMs.
// R10: k_edge / k_edgeout as 2-CTA-per-SM kernels (256 thr, M=64 tiles) for
//      emergent GEMM/epilogue overlap; direct LDG+convert A loads; k_node and
//      the rest identical to the proven R8 components.
// ---------------------------------------------------------------------------

#define H 128
#define VMAX 50000
#define EMAX 625000
#define NT 512

// ---- device scratch ----
__device__ __align__(16) float g_colpack[(size_t)VMAX * 256];  // [Vn | Ah]
__device__ __align__(16) float g_rowpack[(size_t)VMAX * 256];  // [Bh | agg]
__device__ __align__(16) float g_epre[(size_t)EMAX * H];
__device__ __align__(16) float g_stats[4 * H];
__device__ __align__(16) float g_cvec[H];
__device__ __align__(16) float g_scale_h[H];
__device__ __align__(16) float g_shift_h[H];
__device__ __align__(16) float g_scale_e[H];
__device__ __align__(16) float g_shift_e[H];
__device__ __align__(16) unsigned char g_Bimg[6 * 65536];

// ---- smem layout: k_node (512 thr, M=128) ----
#define SM_A     4096
#define CSTRIDE  132
#define SM_STAGE 71680
#define SM_B     137216
#define SMEM_BYTES 202752

// ---- smem layout: 2-CTA kernels (256 thr, M=64) ----
#define E_IDX   0            // rI[64] | cI[64]  (512 B)
#define E_SCSH  512          // scale 512B + shift 512B (k_edgeout)
#define E_C     2048         // C 64x132x4 = 33792 ; A overlay: hi@E_C, lo@+16384
#define E_B     36864        // B hi 32KB + lo 32KB
#define E_SMEM  102400

// ---- helpers ----
__device__ __forceinline__ uint32_t smem_u32(const void* p) {
    uint32_t a;
    asm("{ .reg .u64 t; cvta.to.shared.u64 t, %1; cvt.u32.u64 %0, t; }" : "=r"(a) : "l"(p));
    return a;
}
__device__ __forceinline__ uint32_t bpack(float a, float b) {
    __nv_bfloat162 t = __floats2bfloat162_rn(a, b);
    return *reinterpret_cast<uint32_t*>(&t);
}
__device__ __forceinline__ float bres(float a) {
    __nv_bfloat16 hh = __float2bfloat16_rn(a);
    return a - __bfloat162float(hh);
}
__device__ __forceinline__ void storeA8(char* hiP, char* loP, uint32_t off, const float* v) {
    uint4 hv, lv;
    hv.x = bpack(v[0], v[1]); hv.y = bpack(v[2], v[3]);
    hv.z = bpack(v[4], v[5]); hv.w = bpack(v[6], v[7]);
    lv.x = bpack(bres(v[0]), bres(v[1])); lv.y = bpack(bres(v[2]), bres(v[3]));
    lv.z = bpack(bres(v[4]), bres(v[5])); lv.w = bpack(bres(v[6]), bres(v[7]));
    *(uint4*)(hiP + off) = hv;
    *(uint4*)(loP + off) = lv;
}
__device__ __forceinline__ void ldsm4(uint32_t r[4], uint32_t addr) {
    asm volatile("ldmatrix.sync.aligned.m8n8.x4.shared.b16 {%0,%1,%2,%3}, [%4];"
        : "=r"(r[0]), "=r"(r[1]), "=r"(r[2]), "=r"(r[3]) : "r"(addr));
}
__device__ __forceinline__ void mma16816(float c[4], const uint32_t a[4], uint32_t b0, uint32_t b1) {
    asm volatile("mma.sync.aligned.m16n8k16.row.col.f32.bf16.bf16.f32 "
        "{%0,%1,%2,%3},{%4,%5,%6,%7},{%8,%9},{%0,%1,%2,%3};"
        : "+f"(c[0]), "+f"(c[1]), "+f"(c[2]), "+f"(c[3])
        : "r"(a[0]), "r"(a[1]), "r"(a[2]), "r"(a[3]), "r"(b0), "r"(b1));
}
__device__ __forceinline__ void redv4(float* p, float a, float b, float c, float d) {
    asm volatile("red.global.add.v4.f32 [%0], {%1, %2, %3, %4};"
        :: "l"(p), "f"(a), "f"(b), "f"(c), "f"(d) : "memory");
}
__device__ __forceinline__ void pf_l2(const void* p) {
    asm volatile("prefetch.global.L2 [%0];" :: "l"(p));
}
__device__ __forceinline__ void cpa16(uint32_t dst, const void* src, int pred) {
    asm volatile("{ .reg .pred p; setp.ne.b32 p, %2, 0;\n\t"
        "@p cp.async.cg.shared.global [%0], [%1], 16; }"
        :: "r"(dst), "l"(src), "r"(pred));
}
#define CP_COMMIT() asm volatile("cp.async.commit_group;" ::: "memory")
#define CP_WAIT0()  asm volatile("cp.async.wait_group 0;" ::: "memory")

// ---- GEMM core: 128x128 tile, 16 warps (k_node) ----
__device__ __forceinline__ void gemm_compute(uint32_t sAu, uint32_t sBu, float C[8][4]) {
    int tid = threadIdx.x, lane = tid & 31, wid = tid >> 5;
    int rm = (wid & 7) * 16, cn = (wid >> 3) * 64;
#pragma unroll
    for (int nf = 0; nf < 8; nf++)
#pragma unroll
        for (int q = 0; q < 4; q++) C[nf][q] = 0.f;

    int xr = lane & 7;
    int arow = xr + ((lane >> 3) & 1) * 8;
    int ahs = lane >> 4;
    int bhs = (lane >> 3) & 1;
    int bnr = xr + (lane >> 4) * 8;
    uint32_t aB = sAu + (uint32_t)(rm + arow) * 256;
    uint32_t bB[4];
#pragma unroll
    for (int g = 0; g < 4; g++) bB[g] = sBu + (uint32_t)(cn + g * 16 + bnr) * 256;

#pragma unroll
    for (int ks = 0; ks < 8; ks++) {
        uint32_t oA = (uint32_t)(((ks * 2 + ahs) ^ xr) << 4);
        uint32_t oB = (uint32_t)(((ks * 2 + bhs) ^ xr) << 4);
        uint32_t aH[4], aL[4];
        ldsm4(aH, aB + oA);
        ldsm4(aL, aB + 32768 + oA);
        uint32_t bH[4][4], bL[4][4];
#pragma unroll
        for (int g = 0; g < 4; g++) {
            ldsm4(bH[g], bB[g] + oB);
            ldsm4(bL[g], bB[g] + 32768 + oB);
        }
#pragma unroll
        for (int g = 0; g < 4; g++) {
            mma16816(C[2*g],   aH, bH[g][0], bH[g][1]);
            mma16816(C[2*g+1], aH, bH[g][2], bH[g][3]);
            mma16816(C[2*g],   aH, bL[g][0], bL[g][1]);
            mma16816(C[2*g+1], aH, bL[g][2], bL[g][3]);
            mma16816(C[2*g],   aL, bH[g][0], bH[g][1]);
            mma16816(C[2*g+1], aL, bH[g][2], bH[g][3]);
        }
    }
}

// ---- GEMM core: 64x128 tile, 8 warps (2-CTA kernels); A lo at +16384 ----
__device__ __forceinline__ void gemm_compute64(uint32_t sAu, uint32_t sBu, float C[8][4]) {
    int tid = threadIdx.x, lane = tid & 31, wid = tid >> 5;  // wid 0..7
    int rm = (wid & 3) * 16, cn = (wid >> 2) * 64;
#pragma unroll
    for (int nf = 0; nf < 8; nf++)
#pragma unroll
        for (int q = 0; q < 4; q++) C[nf][q] = 0.f;

    int xr = lane & 7;
    int arow = xr + ((lane >> 3) & 1) * 8;
    int ahs = lane >> 4;
    int bhs = (lane >> 3) & 1;
    int bnr = xr + (lane >> 4) * 8;
    uint32_t aB = sAu + (uint32_t)(rm + arow) * 256;
    uint32_t bB[4];
#pragma unroll
    for (int g = 0; g < 4; g++) bB[g] = sBu + (uint32_t)(cn + g * 16 + bnr) * 256;

#pragma unroll
    for (int ks = 0; ks < 8; ks++) {
        uint32_t oA = (uint32_t)(((ks * 2 + ahs) ^ xr) << 4);
        uint32_t oB = (uint32_t)(((ks * 2 + bhs) ^ xr) << 4);
        uint32_t aH[4], aL[4];
        ldsm4(aH, aB + oA);
        ldsm4(aL, aB + 16384 + oA);
        uint32_t bH[4][4], bL[4][4];
#pragma unroll
        for (int g = 0; g < 4; g++) {
            ldsm4(bH[g], bB[g] + oB);
            ldsm4(bL[g], bB[g] + 32768 + oB);
        }
#pragma unroll
        for (int g = 0; g < 4; g++) {
            mma16816(C[2*g],   aH, bH[g][0], bH[g][1]);
            mma16816(C[2*g+1], aH, bH[g][2], bH[g][3]);
            mma16816(C[2*g],   aH, bL[g][0], bL[g][1]);
            mma16816(C[2*g+1], aH, bL[g][2], bL[g][3]);
            mma16816(C[2*g],   aL, bH[g][0], bH[g][1]);
            mma16816(C[2*g+1], aL, bH[g][2], bH[g][3]);
        }
    }
}

__device__ __forceinline__ void storeC64(float* Cs, float C[8][4]) {
    int tid = threadIdx.x, lane = tid & 31, wid = tid >> 5;
    int rm = (wid & 3) * 16, cn = (wid >> 2) * 64;
    int r = lane >> 2, c2 = 2 * (lane & 3);
#pragma unroll
    for (int nf = 0; nf < 8; nf++) {
        int col = cn + nf * 8 + c2;
        *(float2*)(Cs + (rm + r) * CSTRIDE + col)     = make_float2(C[nf][0], C[nf][1]);
        *(float2*)(Cs + (rm + r + 8) * CSTRIDE + col) = make_float2(C[nf][2], C[nf][3]);
    }
}

// ---- k_node pipeline pieces (512 thr) ----
__device__ __forceinline__ void stage_A(uint32_t sb, const float* src, int r0, int limit) {
    int tid = threadIdx.x;
    uint32_t dst = sb + SM_STAGE;
#pragma unroll
    for (int it = 0; it < 8; it++) {
        int c = it * NT + tid;
        int row = c >> 5, part = c & 31;
        cpa16(dst + c * 16, src + (size_t)(r0 + row) * H + part * 4, (r0 + row) < limit);
    }
    CP_COMMIT();
}

__device__ __forceinline__ void convert_plain(char* sm) {
    const float* stg = (const float*)(sm + SM_STAGE);
    char* sA = sm + SM_A;
    int tid = threadIdx.x;
#pragma unroll
    for (int it = 0; it < 4; it++) {
        int s = it * NT + tid;
        int row = s >> 4, kseg = s & 15;
        const float4* p = (const float4*)(stg + row * 128 + kseg * 8);
        float4 f0 = p[0], f1 = p[1];
        float v[8] = {f0.x, f0.y, f0.z, f0.w, f1.x, f1.y, f1.z, f1.w};
        uint32_t off = (uint32_t)row * 256 + (uint32_t)((kseg ^ (row & 7)) << 4);
        storeA8(sA, sA + 32768, off, v);
    }
}

__device__ __forceinline__ void copy_B(int widx, char* sB) {
    const uint4* g = (const uint4*)(g_Bimg + (size_t)widx * 65536);
    uint4* d = (uint4*)sB;
    int tid = threadIdx.x;
#pragma unroll
    for (int it = 0; it < 8; it++) d[it * NT + tid] = g[it * NT + tid];
}

// ---- 2-CTA kernel pieces (256 thr, M=64) ----
__device__ __forceinline__ void copy_B256(int widx, char* sB) {
    const uint4* g = (const uint4*)(g_Bimg + (size_t)widx * 65536);
    uint4* d = (uint4*)sB;
    int tid = threadIdx.x;
#pragma unroll
    for (int it = 0; it < 16; it++) d[it * 256 + tid] = g[it * 256 + tid];
}

// direct LDG + split-bf16 convert into A overlay (hi @ E_C, lo @ +16384)
__device__ __forceinline__ void loadA64(const float* src, int r0, int limit, char* sm) {
    char* sA = sm + E_C;
    int tid = threadIdx.x;
#pragma unroll
    for (int it = 0; it < 4; it++) {
        int s = it * 256 + tid;           // 1024 slots = 64 rows x 16 ksegs
        int row = s >> 4, kseg = s & 15;
        float v[8] = {0.f, 0.f, 0.f, 0.f, 0.f, 0.f, 0.f, 0.f};
        if (r0 + row < limit) {
            const float* p = src + (size_t)(r0 + row) * H + kseg * 8;
            float4 f0 = *(const float4*)p;
            float4 f1 = *(const float4*)(p + 4);
            v[0] = f0.x; v[1] = f0.y; v[2] = f0.z; v[3] = f0.w;
            v[4] = f1.x; v[5] = f1.y; v[6] = f1.z; v[7] = f1.w;
        }
        uint32_t off = (uint32_t)row * 256 + (uint32_t)((kseg ^ (row & 7)) << 4);
        storeA8(sA, sA + 16384, off, v);
    }
}

__device__ __forceinline__ void loadA64_bn(const float* src, int r0, int limit, char* sm) {
    char* sA = sm + E_C;
    const float4* sc4 = (const float4*)(sm + E_SCSH);
    const float4* sh4 = (const float4*)(sm + E_SCSH + 512);
    int tid = threadIdx.x;
#pragma unroll
    for (int it = 0; it < 4; it++) {
        int s = it * 256 + tid;
        int row = s >> 4, kseg = s & 15;
        float v[8] = {0.f, 0.f, 0.f, 0.f, 0.f, 0.f, 0.f, 0.f};
        if (r0 + row < limit) {
            const float* p = src + (size_t)(r0 + row) * H + kseg * 8;
            float4 f0 = *(const float4*)p;
            float4 f1 = *(const float4*)(p + 4);
            float4 s0 = sc4[kseg * 2], s1 = sc4[kseg * 2 + 1];
            float4 t0 = sh4[kseg * 2], t1 = sh4[kseg * 2 + 1];
            v[0] = fmaxf(fmaf(f0.x, s0.x, t0.x), 0.f);
            v[1] = fmaxf(fmaf(f0.y, s0.y, t0.y), 0.f);
            v[2] = fmaxf(fmaf(f0.z, s0.z, t0.z), 0.f);
            v[3] = fmaxf(fmaf(f0.w, s0.w, t0.w), 0.f);
            v[4] = fmaxf(fmaf(f1.x, s1.x, t1.x), 0.f);
            v[5] = fmaxf(fmaf(f1.y, s1.y, t1.y), 0.f);
            v[6] = fmaxf(fmaf(f1.z, s1.z, t1.z), 0.f);
            v[7] = fmaxf(fmaf(f1.w, s1.w, t1.w), 0.f);
        }
        uint32_t off = (uint32_t)row * 256 + (uint32_t)((kseg ^ (row & 7)) << 4);
        storeA8(sA, sA + 16384, off, v);
    }
}

// ---------------------------------------------------------------------------
__global__ void k_init(const float* __restrict__ time_emb,
                       const float* __restrict__ Wt, const float* __restrict__ bt,
                       const float* __restrict__ Wo, const float* __restrict__ bo) {
    int j = threadIdx.x;
    for (int i = j; i < 4 * H; i += H) g_stats[i] = 0.0f;
    __shared__ float tv[H];
    float acc = bt[j];
    for (int k = 0; k < H; k++) acc += time_emb[k] * Wt[k * H + j];
    tv[j] = acc;
    __syncthreads();
    float c = bo[j];
    for (int k = 0; k < H; k++) c += tv[k] * Wo[k * H + j];
    g_cvec[j] = c;
}

// ---------------------------------------------------------------------------
__global__ void k_prep(const float* __restrict__ WU, const float* __restrict__ WV,
                       const float* __restrict__ WA, const float* __restrict__ WB,
                       const float* __restrict__ WC, const float* __restrict__ Wo) {
    const float* Ws[6] = {WU, WV, WA, WB, WC, Wo};
    const float* W = Ws[blockIdx.x];
    unsigned char* img = g_Bimg + (size_t)blockIdx.x * 65536;
    int tid = threadIdx.x;
    for (int it = 0; it < 64; it++) {
        int idx = it * 256 + tid;
        int k = idx >> 7, n = idx & 127;
        float v = W[k * H + n];
        __nv_bfloat16 hi = __float2bfloat16_rn(v);
        __nv_bfloat16 lo = __float2bfloat16_rn(v - __bfloat162float(hi));
        uint32_t off = (uint32_t)n * 256 + (uint32_t)((((k >> 3) ^ (n & 7))) << 4) + (k & 7) * 2;
        *(__nv_bfloat16*)(img + off) = hi;
        *(__nv_bfloat16*)(img + 32768 + off) = lo;
    }
}

// ---------------------------------------------------------------------------
// k_node: persistent, cp.async pipeline, direct fragment epilogue (R8 proven)
// ---------------------------------------------------------------------------
__global__ __launch_bounds__(NT, 1) void k_node(
        const float* __restrict__ h,
        const float* __restrict__ bU, const float* __restrict__ bV,
        const float* __restrict__ bA, const float* __restrict__ bB,
        int V, int nTiles) {
    extern __shared__ char sm[];
    uint32_t sb = smem_u32(sm);
    int tid = threadIdx.x, lane = tid & 31, wid = tid >> 5;
    int rm = (wid & 7) * 16, cn = (wid >> 3) * 64;
    int r_in = lane >> 2, c2 = 2 * (lane & 3);
    int widx = blockIdx.y;

    copy_B(widx, sm + SM_B);
    float* out; const float* bias;
    switch (widx) {
        case 0:  out = g_rowpack + 128; bias = bU; break;
        case 1:  out = g_colpack;       bias = bV; break;
        case 2:  out = g_colpack + 128; bias = bA; break;
        default: out = g_rowpack;       bias = bB; break;
    }
    float2 bv[8];
#pragma unroll
    for (int nf = 0; nf < 8; nf++) bv[nf] = *(const float2*)(bias + cn + nf * 8 + c2);

    int t = blockIdx.x;
    if (t >= nTiles) return;
    stage_A(sb, h, t * 128, V);
    CP_WAIT0(); __syncthreads();
    convert_plain(sm);
    __syncthreads();

    while (t < nTiles) {
        int nxt = t + gridDim.x;
        if (nxt < nTiles) stage_A(sb, h, nxt * 128, V);

        float C[8][4];
        gemm_compute(sb + SM_A, sb + SM_B, C);

        int r0 = t * 128;
#pragma unroll
        for (int nf = 0; nf < 8; nf++) {
#pragma unroll
            for (int hf = 0; hf < 2; hf++) {
                int row = r0 + rm + hf * 8 + r_in;
                if (row < V) {
                    float2 o = make_float2(C[nf][2 * hf] + bv[nf].x,
                                           C[nf][2 * hf + 1] + bv[nf].y);
                    *(float2*)(out + (size_t)row * 256 + cn + nf * 8 + c2) = o;
                }
            }
        }
        CP_WAIT0();
        __syncthreads();
        if (nxt < nTiles) convert_plain(sm);
        __syncthreads();
        t = nxt;
    }
}

// ---------------------------------------------------------------------------
// k_edge: 2 CTAs/SM, 256 thr, M=64 tiles, persistent. R8 epilogue components.
// ---------------------------------------------------------------------------
__global__ __launch_bounds__(256, 2) void k_edge(
        const float* __restrict__ e, const float* __restrict__ bC,
        const int* __restrict__ eidx, int E, int nTiles) {
    extern __shared__ char sm[];
    uint32_t sb = smem_u32(sm);
    int tid = threadIdx.x, lane = tid & 31, w = tid >> 5;  // 8 warps

    copy_B256(4, sm + E_B);
    float4 bc = *(const float4*)(bC + lane * 4);
    float ss[4] = {0.f, 0.f, 0.f, 0.f}, sq[4] = {0.f, 0.f, 0.f, 0.f};

    int* rI = (int*)(sm + E_IDX);
    int* cI = rI + 64;

    for (int t = blockIdx.x; t < nTiles; t += gridDim.x) {
        int e0 = t * 64;
        __syncthreads();  // protect C/A overlay + idx from previous iteration

        if (tid < 64) {
            int ei = e0 + tid;
            rI[tid] = (ei < E) ? eidx[ei] : 0;
        } else if (tid < 128) {
            int q = tid - 64, ei = e0 + q;
            cI[q] = (ei < E) ? eidx[(size_t)E + ei] : 0;
        }
        loadA64(e, e0, E, sm);
        __syncthreads();

        // L2 prefetch of this tile's gather rows; overlaps the GEMM
#pragma unroll
        for (int i = tid; i < 768; i += 256) {
            int m = i & 63, sel = i >> 6;
            const float* ptr;
            if (sel < 8) ptr = g_colpack + (size_t)cI[m] * 256 + sel * 32;
            else         ptr = g_rowpack + (size_t)rI[m] * 256 + (sel - 8) * 32;
            pf_l2(ptr);
        }

        float C[8][4];
        gemm_compute64(sb + E_C, sb + E_B, C);
        __syncthreads();
        storeC64((float*)(sm + E_C), C);
        __syncthreads();

        const float* Cs = (const float*)(sm + E_C);
        int m0 = w * 8;

        // pipelined gather epilogue (8 edges per warp)
        float4 cc, vn, ah, bh;
        float* rp_cur;
        {
            int m = m0;
            int rv = rI[m], cv = cI[m];
            const float* cp = g_colpack + (size_t)cv * 256;
            rp_cur = g_rowpack + (size_t)rv * 256;
            cc = *(const float4*)(Cs + m * CSTRIDE + lane * 4);
            vn = *(const float4*)(cp + lane * 4);
            ah = *(const float4*)(cp + 128 + lane * 4);
            bh = *(const float4*)(rp_cur + lane * 4);
        }
#pragma unroll
        for (int k = 0; k < 8; k++) {
            int m = m0 + k;
            int ei = e0 + m;
            float4 ccn, vnn, ahn, bhn;
            float* rp_nxt = rp_cur;
            if (k < 7) {
                int mn = m + 1;
                int rv = rI[mn], cv = cI[mn];
                const float* cp = g_colpack + (size_t)cv * 256;
                rp_nxt = g_rowpack + (size_t)rv * 256;
                ccn = *(const float4*)(Cs + mn * CSTRIDE + lane * 4);
                vnn = *(const float4*)(cp + lane * 4);
                ahn = *(const float4*)(cp + 128 + lane * 4);
                bhn = *(const float4*)(rp_nxt + lane * 4);
            }
            if (ei < E) {
                float4 x;
                x.x = cc.x + bc.x + ah.x + bh.x;
                x.y = cc.y + bc.y + ah.y + bh.y;
                x.z = cc.z + bc.z + ah.z + bh.z;
                x.w = cc.w + bc.w + ah.w + bh.w;
                *(float4*)(g_epre + (size_t)ei * H + lane * 4) = x;
                float ga = vn.x / (1.f + __expf(-x.x));
                float gb = vn.y / (1.f + __expf(-x.y));
                float gc = vn.z / (1.f + __expf(-x.z));
                float gd = vn.w / (1.f + __expf(-x.w));
                redv4(rp_cur + 128 + lane * 4, ga, gb, gc, gd);
                ss[0] += x.x; ss[1] += x.y; ss[2] += x.z; ss[3] += x.w;
                sq[0] += x.x * x.x; sq[1] += x.y * x.y;
                sq[2] += x.z * x.z; sq[3] += x.w * x.w;
            }
            cc = ccn; vn = vnn; ah = ahn; bh = bhn; rp_cur = rp_nxt;
        }
    }

    // stats block reduction (reuse C region)
    __syncthreads();
    float* sr = (float*)(sm + E_C);
    float* qr = sr + 1024;
    *(float4*)(sr + w * 128 + lane * 4) = make_float4(ss[0], ss[1], ss[2], ss[3]);
    *(float4*)(qr + w * 128 + lane * 4) = make_float4(sq[0], sq[1], sq[2], sq[3]);
    __syncthreads();
    if (tid < 128) {
        float a = 0.f, b = 0.f;
#pragma unroll
        for (int ww = 0; ww < 8; ww++) { a += sr[ww * 128 + tid]; b += qr[ww * 128 + tid]; }
        atomicAdd(&g_stats[2 * H + tid], a);
        atomicAdd(&g_stats[3 * H + tid], b);
    }
}

// ---------------------------------------------------------------------------
// k_edgeout: 2 CTAs/SM, 256 thr, M=64 tiles, direct fragment epilogue
// ---------------------------------------------------------------------------
__global__ __launch_bounds__(256, 2) void k_edgeout(
        const float* __restrict__ e, float* __restrict__ out, int E, int nTiles) {
    extern __shared__ char sm[];
    uint32_t sb = smem_u32(sm);
    int tid = threadIdx.x, lane = tid & 31, wid = tid >> 5;
    int rm = (wid & 3) * 16, cn = (wid >> 2) * 64;
    int r_in = lane >> 2, c2 = 2 * (lane & 3);

    copy_B256(5, sm + E_B);
    if (tid < 128) {
        ((float*)(sm + E_SCSH))[tid] = g_scale_e[tid];
        ((float*)(sm + E_SCSH + 512))[tid] = g_shift_e[tid];
    }
    float2 cv2[8];
#pragma unroll
    for (int nf = 0; nf < 8; nf++) cv2[nf] = *(const float2*)(g_cvec + cn + nf * 8 + c2);
    __syncthreads();  // scale/shift visible

    for (int t = blockIdx.x; t < nTiles; t += gridDim.x) {
        int e0 = t * 64;
        __syncthreads();  // protect A overlay across iterations

        loadA64_bn(g_epre, e0, E, sm);
        // prefetch this tile's e rows for the epilogue residual read
        {
            int row = tid >> 2, part = (tid & 3) * 32;
            if (row < 64 && e0 + row < E) pf_l2(e + (size_t)(e0 + row) * H + part);
        }
        __syncthreads();

        float C[8][4];
        gemm_compute64(sb + E_C, sb + E_B, C);

#pragma unroll
        for (int nf = 0; nf < 8; nf++) {
#pragma unroll
            for (int hf = 0; hf < 2; hf++) {
                int ei = e0 + rm + hf * 8 + r_in;
                if (ei < E) {
                    int col = cn + nf * 8 + c2;
                    float2 ev = *(const float2*)(e + (size_t)ei * H + col);
                    float2 o = make_float2(ev.x + C[nf][2 * hf] + cv2[nf].x,
                                           ev.y + C[nf][2 * hf + 1] + cv2[nf].y);
                    *(float2*)(out + (size_t)ei * H + col) = o;
                }
            }
        }
    }
}

// ---------------------------------------------------------------------------
__global__ void k_nstats(int rows) {
    int tid = threadIdx.x;
    int cg = tid & 31, wr = tid >> 5;
    float4 s = make_float4(0.f, 0.f, 0.f, 0.f);
    float4 qq = make_float4(0.f, 0.f, 0.f, 0.f);
    const float4* s4 = (const float4*)g_rowpack;
    for (int r = blockIdx.x * 8 + wr; r < rows; r += gridDim.x * 8) {
        float4 x = s4[(size_t)r * 64 + 32 + cg];
        s.x += x.x; s.y += x.y; s.z += x.z; s.w += x.w;
        qq.x += x.x * x.x; qq.y += x.y * x.y; qq.z += x.z * x.z; qq.w += x.w * x.w;
    }
    __shared__ float sh1[8][128], sh2[8][128];
    *(float4*)&sh1[wr][cg * 4] = s;
    *(float4*)&sh2[wr][cg * 4] = qq;
    __syncthreads();
    if (tid < 128) {
        float a = 0.f, b = 0.f;
#pragma unroll
        for (int ww = 0; ww < 8; ww++) { a += sh1[ww][tid]; b += sh2[ww][tid]; }
        atomicAdd(&g_stats[tid], a);
        atomicAdd(&g_stats[H + tid], b);
    }
}

// ---------------------------------------------------------------------------
__global__ void k_finalize(const float* __restrict__ gh, const float* __restrict__ bh,
                           const float* __restrict__ ge, const float* __restrict__ be,
                           int V, int E) {
    int j = threadIdx.x;
    float invV = 1.0f / (float)V, invE = 1.0f / (float)E;
    float mh = g_stats[j] * invV;
    float vh = g_stats[H + j] * invV - mh * mh;
    float sc = gh[j] * rsqrtf(vh + 1e-5f);
    g_scale_h[j] = sc;
    g_shift_h[j] = bh[j] - mh * sc;
    float me = g_stats[2 * H + j] * invE;
    float ve = g_stats[3 * H + j] * invE - me * me;
    float se = ge[j] * rsqrtf(ve + 1e-5f);
    g_scale_e[j] = se;
    g_shift_e[j] = be[j] - me * se;
}

// ---------------------------------------------------------------------------
__global__ void k_nodeout(const float* __restrict__ h, float* __restrict__ out, int V) {
    int idx = blockIdx.x * blockDim.x + threadIdx.x;
    int total = V * (H / 4);
    if (idx >= total) return;
    int row = idx >> 5, cs = idx & 31;
    int j = cs * 4;
    float4 a  = *(const float4*)&g_rowpack[(size_t)row * 256 + 128 + j];
    float4 sc = *(const float4*)&g_scale_h[j];
    float4 sh = *(const float4*)&g_shift_h[j];
    float4 hv = *(const float4*)&h[(size_t)idx * 4];
    float4 r;
    r.x = hv.x + fmaxf(fmaf(a.x, sc.x, sh.x), 0.f);
    r.y = hv.y + fmaxf(fmaf(a.y, sc.y, sh.y), 0.f);
    r.z = hv.z + fmaxf(fmaf(a.z, sc.z, sh.z), 0.f);
    r.w = hv.w + fmaxf(fmaf(a.w, sc.w, sh.w), 0.f);
    *(float4*)&out[(size_t)idx * 4] = r;
}

// ---------------------------------------------------------------------------
extern "C" void kernel_launch(void* const* d_in, const int* in_sizes, int n_in,
                              void* d_out, int out_size) {
    const float* h        = (const float*)d_in[0];
    const float* e        = (const float*)d_in[1];
    const float* time_emb = (const float*)d_in[2];
    const int*   eidx     = (const int*)d_in[3];
    const float* WU = (const float*)d_in[4];  const float* bU = (const float*)d_in[5];
    const float* WV = (const float*)d_in[6];  const float* bV = (const float*)d_in[7];
    const float* WA = (const float*)d_in[8];  const float* bA = (const float*)d_in[9];
    const float* WB = (const float*)d_in[10]; const float* bB = (const float*)d_in[11];
    const float* WC = (const float*)d_in[12]; const float* bC = (const float*)d_in[13];
    const float* Wt = (const float*)d_in[14]; const float* bt = (const float*)d_in[15];
    const float* Wo = (const float*)d_in[16]; const float* bo = (const float*)d_in[17];
    const float* gh = (const float*)d_in[18]; const float* bh = (const float*)d_in[19];
    const float* ge = (const float*)d_in[20]; const float* be = (const float*)d_in[21];

    int V = in_sizes[0] / H;
    int E = in_sizes[3] / 2;

    float* xout = (float*)d_out;
    float* eout = xout + (size_t)V * H;

    cudaFuncSetAttribute(k_node,    cudaFuncAttributeMaxDynamicSharedMemorySize, SMEM_BYTES);
    cudaFuncSetAttribute(k_edge,    cudaFuncAttributeMaxDynamicSharedMemorySize, E_SMEM);
    cudaFuncSetAttribute(k_edgeout, cudaFuncAttributeMaxDynamicSharedMemorySize, E_SMEM);

    int vTiles   = (V + 127) / 128;
    int eTiles64 = (E + 63) / 64;
    int gxNode = vTiles < 37 ? vTiles : 37;
    int gxE = eTiles64 < 296 ? eTiles64 : 296;

    k_init<<<1, 128>>>(time_emb, Wt, bt, Wo, bo);
    k_prep<<<6, 256>>>(WU, WV, WA, WB, WC, Wo);
    k_node<<<dim3(gxNode, 4), NT, SMEM_BYTES>>>(h, bU, bV, bA, bB, V, vTiles);
    k_edge<<<gxE, 256, E_SMEM>>>(e, bC, eidx, E, eTiles64);
    k_nstats<<<512, 256>>>(V);
    k_finalize<<<1, 128>>>(gh, bh, ge, be, V, E);
    k_nodeout<<<(V * (H / 4) + 255) / 256, 256>>>(h, xout, V);
    k_edgeout<<<gxE, 256, E_SMEM>>>(e, eout, E, eTiles64);
}

// round 11
// speedup vs baseline: 1.0650x; 1.0650x over previous
#include <cuda_runtime.h>
#include <cuda_bf16.h>
#include <cuda_fp16.h>
#include <cstdint>

// ---------------------------------------------------------------------------
// DAGCondGNNEncoder (sm_103 HMMA path): split-bf16 mma.sync GEMMs.
// R11: hybrid best-of — k_edge from R10 (2 CTAs/SM, M=64), k_edgeout from R8
//      (512 thr persistent cp.async) — plus e_pre stored as fp16 (halves the
//      dominant scratch traffic: 640 MB -> 320 MB round trip).
// ---------------------------------------------------------------------------

#define H 128
#define VMAX 50000
#define EMAX 625000
#define NT 512

// ---- device scratch ----
__device__ __align__(16) float g_colpack[(size_t)VMAX * 256];  // [Vn | Ah]
__device__ __align__(16) float g_rowpack[(size_t)VMAX * 256];  // [Bh | agg]
__device__ __align__(16) __half g_epre[(size_t)EMAX * H];      // fp16 e_pre
__device__ __align__(16) float g_stats[4 * H];
__device__ __align__(16) float g_cvec[H];
__device__ __align__(16) float g_scale_h[H];
__device__ __align__(16) float g_shift_h[H];
__device__ __align__(16) float g_scale_e[H];
__device__ __align__(16) float g_shift_e[H];
__device__ __align__(16) unsigned char g_Bimg[6 * 65536];

// ---- smem layout: 512-thr kernels (k_node / k_edgeout) ----
#define SM_SC    2048
#define SM_SH    2560
#define SM_A     4096
#define CSTRIDE  132
#define SM_STAGE 71680       // k_node: 64KB fp32 stage; k_edgeout: 32KB half stage
#define SM_B     137216
#define SMEM_BYTES 202752

// ---- smem layout: k_edge (2 CTAs/SM, 256 thr, M=64) ----
#define E_IDX   0
#define E_C     2048         // C 64x132x4 = 33792 ; A overlay: hi@E_C, lo@+16384
#define E_B     36864        // B hi 32KB + lo 32KB
#define E_SMEM  102400

// ---- helpers ----
__device__ __forceinline__ uint32_t smem_u32(const void* p) {
    uint32_t a;
    asm("{ .reg .u64 t; cvta.to.shared.u64 t, %1; cvt.u32.u64 %0, t; }" : "=r"(a) : "l"(p));
    return a;
}
__device__ __forceinline__ uint32_t bpack(float a, float b) {
    __nv_bfloat162 t = __floats2bfloat162_rn(a, b);
    return *reinterpret_cast<uint32_t*>(&t);
}
__device__ __forceinline__ float bres(float a) {
    __nv_bfloat16 hh = __float2bfloat16_rn(a);
    return a - __bfloat162float(hh);
}
__device__ __forceinline__ void storeA8(char* hiP, char* loP, uint32_t off, const float* v) {
    uint4 hv, lv;
    hv.x = bpack(v[0], v[1]); hv.y = bpack(v[2], v[3]);
    hv.z = bpack(v[4], v[5]); hv.w = bpack(v[6], v[7]);
    lv.x = bpack(bres(v[0]), bres(v[1])); lv.y = bpack(bres(v[2]), bres(v[3]));
    lv.z = bpack(bres(v[4]), bres(v[5])); lv.w = bpack(bres(v[6]), bres(v[7]));
    *(uint4*)(hiP + off) = hv;
    *(uint4*)(loP + off) = lv;
}
__device__ __forceinline__ void ldsm4(uint32_t r[4], uint32_t addr) {
    asm volatile("ldmatrix.sync.aligned.m8n8.x4.shared.b16 {%0,%1,%2,%3}, [%4];"
        : "=r"(r[0]), "=r"(r[1]), "=r"(r[2]), "=r"(r[3]) : "r"(addr));
}
__device__ __forceinline__ void mma16816(float c[4], const uint32_t a[4], uint32_t b0, uint32_t b1) {
    asm volatile("mma.sync.aligned.m16n8k16.row.col.f32.bf16.bf16.f32 "
        "{%0,%1,%2,%3},{%4,%5,%6,%7},{%8,%9},{%0,%1,%2,%3};"
        : "+f"(c[0]), "+f"(c[1]), "+f"(c[2]), "+f"(c[3])
        : "r"(a[0]), "r"(a[1]), "r"(a[2]), "r"(a[3]), "r"(b0), "r"(b1));
}
__device__ __forceinline__ void redv4(float* p, float a, float b, float c, float d) {
    asm volatile("red.global.add.v4.f32 [%0], {%1, %2, %3, %4};"
        :: "l"(p), "f"(a), "f"(b), "f"(c), "f"(d) : "memory");
}
__device__ __forceinline__ void pf_l2(const void* p) {
    asm volatile("prefetch.global.L2 [%0];" :: "l"(p));
}
__device__ __forceinline__ void cpa16(uint32_t dst, const void* src, int pred) {
    asm volatile("{ .reg .pred p; setp.ne.b32 p, %2, 0;\n\t"
        "@p cp.async.cg.shared.global [%0], [%1], 16; }"
        :: "r"(dst), "l"(src), "r"(pred));
}
#define CP_COMMIT() asm volatile("cp.async.commit_group;" ::: "memory")
#define CP_WAIT0()  asm volatile("cp.async.wait_group 0;" ::: "memory")

// ---- GEMM core: 128x128 tile, 16 warps ----
__device__ __forceinline__ void gemm_compute(uint32_t sAu, uint32_t sBu, float C[8][4]) {
    int tid = threadIdx.x, lane = tid & 31, wid = tid >> 5;
    int rm = (wid & 7) * 16, cn = (wid >> 3) * 64;
#pragma unroll
    for (int nf = 0; nf < 8; nf++)
#pragma unroll
        for (int q = 0; q < 4; q++) C[nf][q] = 0.f;

    int xr = lane & 7;
    int arow = xr + ((lane >> 3) & 1) * 8;
    int ahs = lane >> 4;
    int bhs = (lane >> 3) & 1;
    int bnr = xr + (lane >> 4) * 8;
    uint32_t aB = sAu + (uint32_t)(rm + arow) * 256;
    uint32_t bB[4];
#pragma unroll
    for (int g = 0; g < 4; g++) bB[g] = sBu + (uint32_t)(cn + g * 16 + bnr) * 256;

#pragma unroll
    for (int ks = 0; ks < 8; ks++) {
        uint32_t oA = (uint32_t)(((ks * 2 + ahs) ^ xr) << 4);
        uint32_t oB = (uint32_t)(((ks * 2 + bhs) ^ xr) << 4);
        uint32_t aH[4], aL[4];
        ldsm4(aH, aB + oA);
        ldsm4(aL, aB + 32768 + oA);
        uint32_t bH[4][4], bL[4][4];
#pragma unroll
        for (int g = 0; g < 4; g++) {
            ldsm4(bH[g], bB[g] + oB);
            ldsm4(bL[g], bB[g] + 32768 + oB);
        }
#pragma unroll
        for (int g = 0; g < 4; g++) {
            mma16816(C[2*g],   aH, bH[g][0], bH[g][1]);
            mma16816(C[2*g+1], aH, bH[g][2], bH[g][3]);
            mma16816(C[2*g],   aH, bL[g][0], bL[g][1]);
            mma16816(C[2*g+1], aH, bL[g][2], bL[g][3]);
            mma16816(C[2*g],   aL, bH[g][0], bH[g][1]);
            mma16816(C[2*g+1], aL, bH[g][2], bH[g][3]);
        }
    }
}

// ---- GEMM core: 64x128 tile, 8 warps (k_edge); A lo at +16384 ----
__device__ __forceinline__ void gemm_compute64(uint32_t sAu, uint32_t sBu, float C[8][4]) {
    int tid = threadIdx.x, lane = tid & 31, wid = tid >> 5;
    int rm = (wid & 3) * 16, cn = (wid >> 2) * 64;
#pragma unroll
    for (int nf = 0; nf < 8; nf++)
#pragma unroll
        for (int q = 0; q < 4; q++) C[nf][q] = 0.f;

    int xr = lane & 7;
    int arow = xr + ((lane >> 3) & 1) * 8;
    int ahs = lane >> 4;
    int bhs = (lane >> 3) & 1;
    int bnr = xr + (lane >> 4) * 8;
    uint32_t aB = sAu + (uint32_t)(rm + arow) * 256;
    uint32_t bB[4];
#pragma unroll
    for (int g = 0; g < 4; g++) bB[g] = sBu + (uint32_t)(cn + g * 16 + bnr) * 256;

#pragma unroll
    for (int ks = 0; ks < 8; ks++) {
        uint32_t oA = (uint32_t)(((ks * 2 + ahs) ^ xr) << 4);
        uint32_t oB = (uint32_t)(((ks * 2 + bhs) ^ xr) << 4);
        uint32_t aH[4], aL[4];
        ldsm4(aH, aB + oA);
        ldsm4(aL, aB + 16384 + oA);
        uint32_t bH[4][4], bL[4][4];
#pragma unroll
        for (int g = 0; g < 4; g++) {
            ldsm4(bH[g], bB[g] + oB);
            ldsm4(bL[g], bB[g] + 32768 + oB);
        }
#pragma unroll
        for (int g = 0; g < 4; g++) {
            mma16816(C[2*g],   aH, bH[g][0], bH[g][1]);
            mma16816(C[2*g+1], aH, bH[g][2], bH[g][3]);
            mma16816(C[2*g],   aH, bL[g][0], bL[g][1]);
            mma16816(C[2*g+1], aH, bL[g][2], bL[g][3]);
            mma16816(C[2*g],   aL, bH[g][0], bH[g][1]);
            mma16816(C[2*g+1], aL, bH[g][2], bH[g][3]);
        }
    }
}

__device__ __forceinline__ void storeC64(float* Cs, float C[8][4]) {
    int tid = threadIdx.x, lane = tid & 31, wid = tid >> 5;
    int rm = (wid & 3) * 16, cn = (wid >> 2) * 64;
    int r = lane >> 2, c2 = 2 * (lane & 3);
#pragma unroll
    for (int nf = 0; nf < 8; nf++) {
        int col = cn + nf * 8 + c2;
        *(float2*)(Cs + (rm + r) * CSTRIDE + col)     = make_float2(C[nf][0], C[nf][1]);
        *(float2*)(Cs + (rm + r + 8) * CSTRIDE + col) = make_float2(C[nf][2], C[nf][3]);
    }
}

// ---- 512-thr pipeline pieces ----
__device__ __forceinline__ void stage_A(uint32_t sb, const float* src, int r0, int limit) {
    int tid = threadIdx.x;
    uint32_t dst = sb + SM_STAGE;
#pragma unroll
    for (int it = 0; it < 8; it++) {
        int c = it * NT + tid;
        int row = c >> 5, part = c & 31;
        cpa16(dst + c * 16, src + (size_t)(r0 + row) * H + part * 4, (r0 + row) < limit);
    }
    CP_COMMIT();
}

// stage 128 rows of fp16 e_pre (32 KB)
__device__ __forceinline__ void stage_A_h(uint32_t sb, const __half* src, int r0, int limit) {
    int tid = threadIdx.x;
    uint32_t dst = sb + SM_STAGE;
#pragma unroll
    for (int it = 0; it < 4; it++) {
        int c = it * NT + tid;             // 2048 x 16B chunks
        int row = c >> 4, part = c & 15;   // 16 chunks per 256B row
        cpa16(dst + c * 16, src + (size_t)(r0 + row) * H + part * 8, (r0 + row) < limit);
    }
    CP_COMMIT();
}

__device__ __forceinline__ void convert_plain(char* sm) {
    const float* stg = (const float*)(sm + SM_STAGE);
    char* sA = sm + SM_A;
    int tid = threadIdx.x;
#pragma unroll
    for (int it = 0; it < 4; it++) {
        int s = it * NT + tid;
        int row = s >> 4, kseg = s & 15;
        const float4* p = (const float4*)(stg + row * 128 + kseg * 8);
        float4 f0 = p[0], f1 = p[1];
        float v[8] = {f0.x, f0.y, f0.z, f0.w, f1.x, f1.y, f1.z, f1.w};
        uint32_t off = (uint32_t)row * 256 + (uint32_t)((kseg ^ (row & 7)) << 4);
        storeA8(sA, sA + 32768, off, v);
    }
}

// convert fp16 stage with BN+relu into split-bf16 A
__device__ __forceinline__ void convert_bn_h(char* sm) {
    const __half* stg = (const __half*)(sm + SM_STAGE);
    const float4* sc4 = (const float4*)(sm + SM_SC);
    const float4* sh4 = (const float4*)(sm + SM_SH);
    char* sA = sm + SM_A;
    int tid = threadIdx.x;
#pragma unroll
    for (int it = 0; it < 4; it++) {
        int s = it * NT + tid;
        int row = s >> 4, kseg = s & 15;
        const __half2* p = (const __half2*)(stg + row * 128 + kseg * 8);
        float2 a0 = __half22float2(p[0]);
        float2 a1 = __half22float2(p[1]);
        float2 a2 = __half22float2(p[2]);
        float2 a3 = __half22float2(p[3]);
        float4 s0 = sc4[kseg * 2], s1 = sc4[kseg * 2 + 1];
        float4 t0 = sh4[kseg * 2], t1 = sh4[kseg * 2 + 1];
        float v[8];
        v[0] = fmaxf(fmaf(a0.x, s0.x, t0.x), 0.f);
        v[1] = fmaxf(fmaf(a0.y, s0.y, t0.y), 0.f);
        v[2] = fmaxf(fmaf(a1.x, s0.z, t0.z), 0.f);
        v[3] = fmaxf(fmaf(a1.y, s0.w, t0.w), 0.f);
        v[4] = fmaxf(fmaf(a2.x, s1.x, t1.x), 0.f);
        v[5] = fmaxf(fmaf(a2.y, s1.y, t1.y), 0.f);
        v[6] = fmaxf(fmaf(a3.x, s1.z, t1.z), 0.f);
        v[7] = fmaxf(fmaf(a3.y, s1.w, t1.w), 0.f);
        uint32_t off = (uint32_t)row * 256 + (uint32_t)((kseg ^ (row & 7)) << 4);
        storeA8(sA, sA + 32768, off, v);
    }
}

__device__ __forceinline__ void copy_B(int widx, char* sB) {
    const uint4* g = (const uint4*)(g_Bimg + (size_t)widx * 65536);
    uint4* d = (uint4*)sB;
    int tid = threadIdx.x;
#pragma unroll
    for (int it = 0; it < 8; it++) d[it * NT + tid] = g[it * NT + tid];
}

// ---- k_edge pieces (256 thr, M=64) ----
__device__ __forceinline__ void copy_B256(int widx, char* sB) {
    const uint4* g = (const uint4*)(g_Bimg + (size_t)widx * 65536);
    uint4* d = (uint4*)sB;
    int tid = threadIdx.x;
#pragma unroll
    for (int it = 0; it < 16; it++) d[it * 256 + tid] = g[it * 256 + tid];
}

__device__ __forceinline__ void loadA64(const float* src, int r0, int limit, char* sm) {
    char* sA = sm + E_C;
    int tid = threadIdx.x;
#pragma unroll
    for (int it = 0; it < 4; it++) {
        int s = it * 256 + tid;
        int row = s >> 4, kseg = s & 15;
        float v[8] = {0.f, 0.f, 0.f, 0.f, 0.f, 0.f, 0.f, 0.f};
        if (r0 + row < limit) {
            const float* p = src + (size_t)(r0 + row) * H + kseg * 8;
            float4 f0 = *(const float4*)p;
            float4 f1 = *(const float4*)(p + 4);
            v[0] = f0.x; v[1] = f0.y; v[2] = f0.z; v[3] = f0.w;
            v[4] = f1.x; v[5] = f1.y; v[6] = f1.z; v[7] = f1.w;
        }
        uint32_t off = (uint32_t)row * 256 + (uint32_t)((kseg ^ (row & 7)) << 4);
        storeA8(sA, sA + 16384, off, v);
    }
}

// ---------------------------------------------------------------------------
__global__ void k_init(const float* __restrict__ time_emb,
                       const float* __restrict__ Wt, const float* __restrict__ bt,
                       const float* __restrict__ Wo, const float* __restrict__ bo) {
    int j = threadIdx.x;
    for (int i = j; i < 4 * H; i += H) g_stats[i] = 0.0f;
    __shared__ float tv[H];
    float acc = bt[j];
    for (int k = 0; k < H; k++) acc += time_emb[k] * Wt[k * H + j];
    tv[j] = acc;
    __syncthreads();
    float c = bo[j];
    for (int k = 0; k < H; k++) c += tv[k] * Wo[k * H + j];
    g_cvec[j] = c;
}

// ---------------------------------------------------------------------------
__global__ void k_prep(const float* __restrict__ WU, const float* __restrict__ WV,
                       const float* __restrict__ WA, const float* __restrict__ WB,
                       const float* __restrict__ WC, const float* __restrict__ Wo) {
    const float* Ws[6] = {WU, WV, WA, WB, WC, Wo};
    const float* W = Ws[blockIdx.x];
    unsigned char* img = g_Bimg + (size_t)blockIdx.x * 65536;
    int tid = threadIdx.x;
    for (int it = 0; it < 64; it++) {
        int idx = it * 256 + tid;
        int k = idx >> 7, n = idx & 127;
        float v = W[k * H + n];
        __nv_bfloat16 hi = __float2bfloat16_rn(v);
        __nv_bfloat16 lo = __float2bfloat16_rn(v - __bfloat162float(hi));
        uint32_t off = (uint32_t)n * 256 + (uint32_t)((((k >> 3) ^ (n & 7))) << 4) + (k & 7) * 2;
        *(__nv_bfloat16*)(img + off) = hi;
        *(__nv_bfloat16*)(img + 32768 + off) = lo;
    }
}

// ---------------------------------------------------------------------------
// k_node: persistent, cp.async pipeline, direct fragment epilogue (R8 proven)
// ---------------------------------------------------------------------------
__global__ __launch_bounds__(NT, 1) void k_node(
        const float* __restrict__ h,
        const float* __restrict__ bU, const float* __restrict__ bV,
        const float* __restrict__ bA, const float* __restrict__ bB,
        int V, int nTiles) {
    extern __shared__ char sm[];
    uint32_t sb = smem_u32(sm);
    int tid = threadIdx.x, lane = tid & 31, wid = tid >> 5;
    int rm = (wid & 7) * 16, cn = (wid >> 3) * 64;
    int r_in = lane >> 2, c2 = 2 * (lane & 3);
    int widx = blockIdx.y;

    copy_B(widx, sm + SM_B);
    float* out; const float* bias;
    switch (widx) {
        case 0:  out = g_rowpack + 128; bias = bU; break;
        case 1:  out = g_colpack;       bias = bV; break;
        case 2:  out = g_colpack + 128; bias = bA; break;
        default: out = g_rowpack;       bias = bB; break;
    }
    float2 bv[8];
#pragma unroll
    for (int nf = 0; nf < 8; nf++) bv[nf] = *(const float2*)(bias + cn + nf * 8 + c2);

    int t = blockIdx.x;
    if (t >= nTiles) return;
    stage_A(sb, h, t * 128, V);
    CP_WAIT0(); __syncthreads();
    convert_plain(sm);
    __syncthreads();

    while (t < nTiles) {
        int nxt = t + gridDim.x;
        if (nxt < nTiles) stage_A(sb, h, nxt * 128, V);

        float C[8][4];
        gemm_compute(sb + SM_A, sb + SM_B, C);

        int r0 = t * 128;
#pragma unroll
        for (int nf = 0; nf < 8; nf++) {
#pragma unroll
            for (int hf = 0; hf < 2; hf++) {
                int row = r0 + rm + hf * 8 + r_in;
                if (row < V) {
                    float2 o = make_float2(C[nf][2 * hf] + bv[nf].x,
                                           C[nf][2 * hf + 1] + bv[nf].y);
                    *(float2*)(out + (size_t)row * 256 + cn + nf * 8 + c2) = o;
                }
            }
        }
        CP_WAIT0();
        __syncthreads();
        if (nxt < nTiles) convert_plain(sm);
        __syncthreads();
        t = nxt;
    }
}

// ---------------------------------------------------------------------------
// k_edge: 2 CTAs/SM, 256 thr, M=64 tiles, persistent (R10 proven) + fp16 epre
// ---------------------------------------------------------------------------
__global__ __launch_bounds__(256, 2) void k_edge(
        const float* __restrict__ e, const float* __restrict__ bC,
        const int* __restrict__ eidx, int E, int nTiles) {
    extern __shared__ char sm[];
    uint32_t sb = smem_u32(sm);
    int tid = threadIdx.x, lane = tid & 31, w = tid >> 5;

    copy_B256(4, sm + E_B);
    float4 bc = *(const float4*)(bC + lane * 4);
    float ss[4] = {0.f, 0.f, 0.f, 0.f}, sq[4] = {0.f, 0.f, 0.f, 0.f};

    int* rI = (int*)(sm + E_IDX);
    int* cI = rI + 64;

    for (int t = blockIdx.x; t < nTiles; t += gridDim.x) {
        int e0 = t * 64;
        __syncthreads();

        if (tid < 64) {
            int ei = e0 + tid;
            rI[tid] = (ei < E) ? eidx[ei] : 0;
        } else if (tid < 128) {
            int q = tid - 64, ei = e0 + q;
            cI[q] = (ei < E) ? eidx[(size_t)E + ei] : 0;
        }
        loadA64(e, e0, E, sm);
        __syncthreads();

#pragma unroll
        for (int i = tid; i < 768; i += 256) {
            int m = i & 63, sel = i >> 6;
            const float* ptr;
            if (sel < 8) ptr = g_colpack + (size_t)cI[m] * 256 + sel * 32;
            else         ptr = g_rowpack + (size_t)rI[m] * 256 + (sel - 8) * 32;
            pf_l2(ptr);
        }

        float C[8][4];
        gemm_compute64(sb + E_C, sb + E_B, C);
        __syncthreads();
        storeC64((float*)(sm + E_C), C);
        __syncthreads();

        const float* Cs = (const float*)(sm + E_C);
        int m0 = w * 8;

        float4 cc, vn, ah, bh;
        float* rp_cur;
        {
            int m = m0;
            int rv = rI[m], cv = cI[m];
            const float* cp = g_colpack + (size_t)cv * 256;
            rp_cur = g_rowpack + (size_t)rv * 256;
            cc = *(const float4*)(Cs + m * CSTRIDE + lane * 4);
            vn = *(const float4*)(cp + lane * 4);
            ah = *(const float4*)(cp + 128 + lane * 4);
            bh = *(const float4*)(rp_cur + lane * 4);
        }
#pragma unroll
        for (int k = 0; k < 8; k++) {
            int m = m0 + k;
            int ei = e0 + m;
            float4 ccn, vnn, ahn, bhn;
            float* rp_nxt = rp_cur;
            if (k < 7) {
                int mn = m + 1;
                int rv = rI[mn], cv = cI[mn];
                const float* cp = g_colpack + (size_t)cv * 256;
                rp_nxt = g_rowpack + (size_t)rv * 256;
                ccn = *(const float4*)(Cs + mn * CSTRIDE + lane * 4);
                vnn = *(const float4*)(cp + lane * 4);
                ahn = *(const float4*)(cp + 128 + lane * 4);
                bhn = *(const float4*)(rp_nxt + lane * 4);
            }
            if (ei < E) {
                float4 x;
                x.x = cc.x + bc.x + ah.x + bh.x;
                x.y = cc.y + bc.y + ah.y + bh.y;
                x.z = cc.z + bc.z + ah.z + bh.z;
                x.w = cc.w + bc.w + ah.w + bh.w;
                __half2 h01 = __floats2half2_rn(x.x, x.y);
                __half2 h23 = __floats2half2_rn(x.z, x.w);
                uint2 u;
                u.x = *reinterpret_cast<uint32_t*>(&h01);
                u.y = *reinterpret_cast<uint32_t*>(&h23);
                *(uint2*)(g_epre + (size_t)ei * H + lane * 4) = u;
                float ga = vn.x / (1.f + __expf(-x.x));
                float gb = vn.y / (1.f + __expf(-x.y));
                float gc = vn.z / (1.f + __expf(-x.z));
                float gd = vn.w / (1.f + __expf(-x.w));
                redv4(rp_cur + 128 + lane * 4, ga, gb, gc, gd);
                ss[0] += x.x; ss[1] += x.y; ss[2] += x.z; ss[3] += x.w;
                sq[0] += x.x * x.x; sq[1] += x.y * x.y;
                sq[2] += x.z * x.z; sq[3] += x.w * x.w;
            }
            cc = ccn; vn = vnn; ah = ahn; bh = bhn; rp_cur = rp_nxt;
        }
    }

    __syncthreads();
    float* sr = (float*)(sm + E_C);
    float* qr = sr + 1024;
    *(float4*)(sr + w * 128 + lane * 4) = make_float4(ss[0], ss[1], ss[2], ss[3]);
    *(float4*)(qr + w * 128 + lane * 4) = make_float4(sq[0], sq[1], sq[2], sq[3]);
    __syncthreads();
    if (tid < 128) {
        float a = 0.f, b = 0.f;
#pragma unroll
        for (int ww = 0; ww < 8; ww++) { a += sr[ww * 128 + tid]; b += qr[ww * 128 + tid]; }
        atomicAdd(&g_stats[2 * H + tid], a);
        atomicAdd(&g_stats[3 * H + tid], b);
    }
}

// ---------------------------------------------------------------------------
// k_edgeout: 512 thr persistent cp.async pipeline (R8 proven), fp16 epre in
// ---------------------------------------------------------------------------
__global__ __launch_bounds__(NT, 1) void k_edgeout(
        const float* __restrict__ e, float* __restrict__ out, int E, int nTiles) {
    extern __shared__ char sm[];
    uint32_t sb = smem_u32(sm);
    int tid = threadIdx.x, lane = tid & 31, wid = tid >> 5;
    int rm = (wid & 7) * 16, cn = (wid >> 3) * 64;
    int r_in = lane >> 2, c2 = 2 * (lane & 3);

    copy_B(5, sm + SM_B);
    if (tid < 128) {
        ((float*)(sm + SM_SC))[tid] = g_scale_e[tid];
        ((float*)(sm + SM_SH))[tid] = g_shift_e[tid];
    }
    float2 cv2[8];
#pragma unroll
    for (int nf = 0; nf < 8; nf++) cv2[nf] = *(const float2*)(g_cvec + cn + nf * 8 + c2);

    int t = blockIdx.x;
    if (t >= nTiles) return;

    stage_A_h(sb, g_epre, t * 128, E);
    {
        int row = tid >> 2, part = (tid & 3) * 32;
        if (t * 128 + row < E) pf_l2(e + (size_t)(t * 128 + row) * H + part);
    }
    CP_WAIT0(); __syncthreads();
    convert_bn_h(sm);
    __syncthreads();

    while (t < nTiles) {
        int nxt = t + gridDim.x;
        if (nxt < nTiles) {
            stage_A_h(sb, g_epre, nxt * 128, E);
            int row = tid >> 2, part = (tid & 3) * 32;
            if (nxt * 128 + row < E) pf_l2(e + (size_t)(nxt * 128 + row) * H + part);
        }

        float C[8][4];
        gemm_compute(sb + SM_A, sb + SM_B, C);

        int e0 = t * 128;
#pragma unroll
        for (int nf = 0; nf < 8; nf++) {
#pragma unroll
            for (int hf = 0; hf < 2; hf++) {
                int ei = e0 + rm + hf * 8 + r_in;
                if (ei < E) {
                    int col = cn + nf * 8 + c2;
                    float2 ev = *(const float2*)(e + (size_t)ei * H + col);
                    float2 o = make_float2(ev.x + C[nf][2 * hf] + cv2[nf].x,
                                           ev.y + C[nf][2 * hf + 1] + cv2[nf].y);
                    *(float2*)(out + (size_t)ei * H + col) = o;
                }
            }
        }
        CP_WAIT0();
        __syncthreads();
        if (nxt < nTiles) convert_bn_h(sm);
        __syncthreads();
        t = nxt;
    }
}

// ---------------------------------------------------------------------------
__global__ void k_nstats(int rows) {
    int tid = threadIdx.x;
    int cg = tid & 31, wr = tid >> 5;
    float4 s = make_float4(0.f, 0.f, 0.f, 0.f);
    float4 qq = make_float4(0.f, 0.f, 0.f, 0.f);
    const float4* s4 = (const float4*)g_rowpack;
    for (int r = blockIdx.x * 8 + wr; r < rows; r += gridDim.x * 8) {
        float4 x = s4[(size_t)r * 64 + 32 + cg];
        s.x += x.x; s.y += x.y; s.z += x.z; s.w += x.w;
        qq.x += x.x * x.x; qq.y += x.y * x.y; qq.z += x.z * x.z; qq.w += x.w * x.w;
    }
    __shared__ float sh1[8][128], sh2[8][128];
    *(float4*)&sh1[wr][cg * 4] = s;
    *(float4*)&sh2[wr][cg * 4] = qq;
    __syncthreads();
    if (tid < 128) {
        float a = 0.f, b = 0.f;
#pragma unroll
        for (int ww = 0; ww < 8; ww++) { a += sh1[ww][tid]; b += sh2[ww][tid]; }
        atomicAdd(&g_stats[tid], a);
        atomicAdd(&g_stats[H + tid], b);
    }
}

// ---------------------------------------------------------------------------
__global__ void k_finalize(const float* __restrict__ gh, const float* __restrict__ bh,
                           const float* __restrict__ ge, const float* __restrict__ be,
                           int V, int E) {
    int j = threadIdx.x;
    float invV = 1.0f / (float)V, invE = 1.0f / (float)E;
    float mh = g_stats[j] * invV;
    float vh = g_stats[H + j] * invV - mh * mh;
    float sc = gh[j] * rsqrtf(vh + 1e-5f);
    g_scale_h[j] = sc;
    g_shift_h[j] = bh[j] - mh * sc;
    float me = g_stats[2 * H + j] * invE;
    float ve = g_stats[3 * H + j] * invE - me * me;
    float se = ge[j] * rsqrtf(ve + 1e-5f);
    g_scale_e[j] = se;
    g_shift_e[j] = be[j] - me * se;
}

// ---------------------------------------------------------------------------
__global__ void k_nodeout(const float* __restrict__ h, float* __restrict__ out, int V) {
    int idx = blockIdx.x * blockDim.x + threadIdx.x;
    int total = V * (H / 4);
    if (idx >= total) return;
    int row = idx >> 5, cs = idx & 31;
    int j = cs * 4;
    float4 a  = *(const float4*)&g_rowpack[(size_t)row * 256 + 128 + j];
    float4 sc = *(const float4*)&g_scale_h[j];
    float4 sh = *(const float4*)&g_shift_h[j];
    float4 hv = *(const float4*)&h[(size_t)idx * 4];
    float4 r;
    r.x = hv.x + fmaxf(fmaf(a.x, sc.x, sh.x), 0.f);
    r.y = hv.y + fmaxf(fmaf(a.y, sc.y, sh.y), 0.f);
    r.z = hv.z + fmaxf(fmaf(a.z, sc.z, sh.z), 0.f);
    r.w = hv.w + fmaxf(fmaf(a.w, sc.w, sh.w), 0.f);
    *(float4*)&out[(size_t)idx * 4] = r;
}

// ---------------------------------------------------------------------------
extern "C" void kernel_launch(void* const* d_in, const int* in_sizes, int n_in,
                              void* d_out, int out_size) {
    const float* h        = (const float*)d_in[0];
    const float* e        = (const float*)d_in[1];
    const float* time_emb = (const float*)d_in[2];
    const int*   eidx     = (const int*)d_in[3];
    const float* WU = (const float*)d_in[4];  const float* bU = (const float*)d_in[5];
    const float* WV = (const float*)d_in[6];  const float* bV = (const float*)d_in[7];
    const float* WA = (const float*)d_in[8];  const float* bA = (const float*)d_in[9];
    const float* WB = (const float*)d_in[10]; const float* bB = (const float*)d_in[11];
    const float* WC = (const float*)d_in[12]; const float* bC = (const float*)d_in[13];
    const float* Wt = (const float*)d_in[14]; const float* bt = (const float*)d_in[15];
    const float* Wo = (const float*)d_in[16]; const float* bo = (const float*)d_in[17];
    const float* gh = (const float*)d_in[18]; const float* bh = (const float*)d_in[19];
    const float* ge = (const float*)d_in[20]; const float* be = (const float*)d_in[21];

    int V = in_sizes[0] / H;
    int E = in_sizes[3] / 2;

    float* xout = (float*)d_out;
    float* eout = xout + (size_t)V * H;

    cudaFuncSetAttribute(k_node,    cudaFuncAttributeMaxDynamicSharedMemorySize, SMEM_BYTES);
    cudaFuncSetAttribute(k_edge,    cudaFuncAttributeMaxDynamicSharedMemorySize, E_SMEM);
    cudaFuncSetAttribute(k_edgeout, cudaFuncAttributeMaxDynamicSharedMemorySize, SMEM_BYTES);

    int vTiles   = (V + 127) / 128;
    int eTiles   = (E + 127) / 128;
    int eTiles64 = (E + 63) / 64;
    int gxNode = vTiles < 37 ? vTiles : 37;
    int gxE64 = eTiles64 < 296 ? eTiles64 : 296;
    int gxE = eTiles < 148 ? eTiles : 148;

    k_init<<<1, 128>>>(time_emb, Wt, bt, Wo, bo);
    k_prep<<<6, 256>>>(WU, WV, WA, WB, WC, Wo);
    k_node<<<dim3(gxNode, 4), NT, SMEM_BYTES>>>(h, bU, bV, bA, bB, V, vTiles);
    k_edge<<<gxE64, 256, E_SMEM>>>(e, bC, eidx, E, eTiles64);
    k_nstats<<<512, 256>>>(V);
    k_finalize<<<1, 128>>>(gh, bh, ge, be, V, E);
    k_nodeout<<<(V * (H / 4) + 255) / 256, 256>>>(h, xout, V);
    k_edgeout<<<gxE, NT, SMEM_BYTES>>>(e, eout, E, eTiles);
}

// round 12
// speedup vs baseline: 1.0875x; 1.0211x over previous
#include <cuda_runtime.h>
#include <cuda_bf16.h>
#include <cuda_fp16.h>
#include <cstdint>

// ---------------------------------------------------------------------------
// DAGCondGNNEncoder (sm_103 HMMA path): split-bf16 mma.sync GEMMs.
// R12: fp16 gather operands — colpack_h=[Vn|Ah] (512B/row), Bh_h (256B/row),
//      agg stays fp32 for exact atomics. e_pre fp16 (R11). k_edge 2 CTA/SM,
//      k_edgeout 512-thr cp.async pipeline, k_node persistent (all proven).
// ---------------------------------------------------------------------------

#define H 128
#define VMAX 50000
#define EMAX 625000
#define NT 512

// ---- device scratch ----
__device__ __align__(16) __half g_colpack_h[(size_t)VMAX * 256];  // [Vn|Ah] fp16
__device__ __align__(16) __half g_Bh_h[(size_t)VMAX * 128];       // Bh fp16
__device__ __align__(16) float  g_agg[(size_t)VMAX * 128];        // Uh + scatter
__device__ __align__(16) __half g_epre[(size_t)EMAX * H];         // fp16 e_pre
__device__ __align__(16) float g_stats[4 * H];
__device__ __align__(16) float g_cvec[H];
__device__ __align__(16) float g_scale_h[H];
__device__ __align__(16) float g_shift_h[H];
__device__ __align__(16) float g_scale_e[H];
__device__ __align__(16) float g_shift_e[H];
__device__ __align__(16) unsigned char g_Bimg[6 * 65536];

// ---- smem layout: 512-thr kernels (k_node / k_edgeout) ----
#define SM_SC    2048
#define SM_SH    2560
#define SM_A     4096
#define CSTRIDE  132
#define SM_STAGE 71680
#define SM_B     137216
#define SMEM_BYTES 202752

// ---- smem layout: k_edge (2 CTAs/SM, 256 thr, M=64) ----
#define E_IDX   0
#define E_C     2048
#define E_B     36864
#define E_SMEM  102400

// ---- helpers ----
__device__ __forceinline__ uint32_t smem_u32(const void* p) {
    uint32_t a;
    asm("{ .reg .u64 t; cvta.to.shared.u64 t, %1; cvt.u32.u64 %0, t; }" : "=r"(a) : "l"(p));
    return a;
}
__device__ __forceinline__ uint32_t bpack(float a, float b) {
    __nv_bfloat162 t = __floats2bfloat162_rn(a, b);
    return *reinterpret_cast<uint32_t*>(&t);
}
__device__ __forceinline__ float bres(float a) {
    __nv_bfloat16 hh = __float2bfloat16_rn(a);
    return a - __bfloat162float(hh);
}
__device__ __forceinline__ void storeA8(char* hiP, char* loP, uint32_t off, const float* v) {
    uint4 hv, lv;
    hv.x = bpack(v[0], v[1]); hv.y = bpack(v[2], v[3]);
    hv.z = bpack(v[4], v[5]); hv.w = bpack(v[6], v[7]);
    lv.x = bpack(bres(v[0]), bres(v[1])); lv.y = bpack(bres(v[2]), bres(v[3]));
    lv.z = bpack(bres(v[4]), bres(v[5])); lv.w = bpack(bres(v[6]), bres(v[7]));
    *(uint4*)(hiP + off) = hv;
    *(uint4*)(loP + off) = lv;
}
__device__ __forceinline__ void ldsm4(uint32_t r[4], uint32_t addr) {
    asm volatile("ldmatrix.sync.aligned.m8n8.x4.shared.b16 {%0,%1,%2,%3}, [%4];"
        : "=r"(r[0]), "=r"(r[1]), "=r"(r[2]), "=r"(r[3]) : "r"(addr));
}
__device__ __forceinline__ void mma16816(float c[4], const uint32_t a[4], uint32_t b0, uint32_t b1) {
    asm volatile("mma.sync.aligned.m16n8k16.row.col.f32.bf16.bf16.f32 "
        "{%0,%1,%2,%3},{%4,%5,%6,%7},{%8,%9},{%0,%1,%2,%3};"
        : "+f"(c[0]), "+f"(c[1]), "+f"(c[2]), "+f"(c[3])
        : "r"(a[0]), "r"(a[1]), "r"(a[2]), "r"(a[3]), "r"(b0), "r"(b1));
}
__device__ __forceinline__ void redv4(float* p, float a, float b, float c, float d) {
    asm volatile("red.global.add.v4.f32 [%0], {%1, %2, %3, %4};"
        :: "l"(p), "f"(a), "f"(b), "f"(c), "f"(d) : "memory");
}
__device__ __forceinline__ void pf_l2(const void* p) {
    asm volatile("prefetch.global.L2 [%0];" :: "l"(p));
}
__device__ __forceinline__ void cpa16(uint32_t dst, const void* src, int pred) {
    asm volatile("{ .reg .pred p; setp.ne.b32 p, %2, 0;\n\t"
        "@p cp.async.cg.shared.global [%0], [%1], 16; }"
        :: "r"(dst), "l"(src), "r"(pred));
}
#define CP_COMMIT() asm volatile("cp.async.commit_group;" ::: "memory")
#define CP_WAIT0()  asm volatile("cp.async.wait_group 0;" ::: "memory")

// ---- GEMM core: 128x128 tile, 16 warps ----
__device__ __forceinline__ void gemm_compute(uint32_t sAu, uint32_t sBu, float C[8][4]) {
    int tid = threadIdx.x, lane = tid & 31, wid = tid >> 5;
    int rm = (wid & 7) * 16, cn = (wid >> 3) * 64;
#pragma unroll
    for (int nf = 0; nf < 8; nf++)
#pragma unroll
        for (int q = 0; q < 4; q++) C[nf][q] = 0.f;

    int xr = lane & 7;
    int arow = xr + ((lane >> 3) & 1) * 8;
    int ahs = lane >> 4;
    int bhs = (lane >> 3) & 1;
    int bnr = xr + (lane >> 4) * 8;
    uint32_t aB = sAu + (uint32_t)(rm + arow) * 256;
    uint32_t bB[4];
#pragma unroll
    for (int g = 0; g < 4; g++) bB[g] = sBu + (uint32_t)(cn + g * 16 + bnr) * 256;

#pragma unroll
    for (int ks = 0; ks < 8; ks++) {
        uint32_t oA = (uint32_t)(((ks * 2 + ahs) ^ xr) << 4);
        uint32_t oB = (uint32_t)(((ks * 2 + bhs) ^ xr) << 4);
        uint32_t aH[4], aL[4];
        ldsm4(aH, aB + oA);
        ldsm4(aL, aB + 32768 + oA);
        uint32_t bH[4][4], bL[4][4];
#pragma unroll
        for (int g = 0; g < 4; g++) {
            ldsm4(bH[g], bB[g] + oB);
            ldsm4(bL[g], bB[g] + 32768 + oB);
        }
#pragma unroll
        for (int g = 0; g < 4; g++) {
            mma16816(C[2*g],   aH, bH[g][0], bH[g][1]);
            mma16816(C[2*g+1], aH, bH[g][2], bH[g][3]);
            mma16816(C[2*g],   aH, bL[g][0], bL[g][1]);
            mma16816(C[2*g+1], aH, bL[g][2], bL[g][3]);
            mma16816(C[2*g],   aL, bH[g][0], bH[g][1]);
            mma16816(C[2*g+1], aL, bH[g][2], bH[g][3]);
        }
    }
}

// ---- GEMM core: 64x128 tile, 8 warps (k_edge); A lo at +16384 ----
__device__ __forceinline__ void gemm_compute64(uint32_t sAu, uint32_t sBu, float C[8][4]) {
    int tid = threadIdx.x, lane = tid & 31, wid = tid >> 5;
    int rm = (wid & 3) * 16, cn = (wid >> 2) * 64;
#pragma unroll
    for (int nf = 0; nf < 8; nf++)
#pragma unroll
        for (int q = 0; q < 4; q++) C[nf][q] = 0.f;

    int xr = lane & 7;
    int arow = xr + ((lane >> 3) & 1) * 8;
    int ahs = lane >> 4;
    int bhs = (lane >> 3) & 1;
    int bnr = xr + (lane >> 4) * 8;
    uint32_t aB = sAu + (uint32_t)(rm + arow) * 256;
    uint32_t bB[4];
#pragma unroll
    for (int g = 0; g < 4; g++) bB[g] = sBu + (uint32_t)(cn + g * 16 + bnr) * 256;

#pragma unroll
    for (int ks = 0; ks < 8; ks++) {
        uint32_t oA = (uint32_t)(((ks * 2 + ahs) ^ xr) << 4);
        uint32_t oB = (uint32_t)(((ks * 2 + bhs) ^ xr) << 4);
        uint32_t aH[4], aL[4];
        ldsm4(aH, aB + oA);
        ldsm4(aL, aB + 16384 + oA);
        uint32_t bH[4][4], bL[4][4];
#pragma unroll
        for (int g = 0; g < 4; g++) {
            ldsm4(bH[g], bB[g] + oB);
            ldsm4(bL[g], bB[g] + 32768 + oB);
        }
#pragma unroll
        for (int g = 0; g < 4; g++) {
            mma16816(C[2*g],   aH, bH[g][0], bH[g][1]);
            mma16816(C[2*g+1], aH, bH[g][2], bH[g][3]);
            mma16816(C[2*g],   aH, bL[g][0], bL[g][1]);
            mma16816(C[2*g+1], aH, bL[g][2], bL[g][3]);
            mma16816(C[2*g],   aL, bH[g][0], bH[g][1]);
            mma16816(C[2*g+1], aL, bH[g][2], bH[g][3]);
        }
    }
}

__device__ __forceinline__ void storeC64(float* Cs, float C[8][4]) {
    int tid = threadIdx.x, lane = tid & 31, wid = tid >> 5;
    int rm = (wid & 3) * 16, cn = (wid >> 2) * 64;
    int r = lane >> 2, c2 = 2 * (lane & 3);
#pragma unroll
    for (int nf = 0; nf < 8; nf++) {
        int col = cn + nf * 8 + c2;
        *(float2*)(Cs + (rm + r) * CSTRIDE + col)     = make_float2(C[nf][0], C[nf][1]);
        *(float2*)(Cs + (rm + r + 8) * CSTRIDE + col) = make_float2(C[nf][2], C[nf][3]);
    }
}

// ---- 512-thr pipeline pieces ----
__device__ __forceinline__ void stage_A(uint32_t sb, const float* src, int r0, int limit) {
    int tid = threadIdx.x;
    uint32_t dst = sb + SM_STAGE;
#pragma unroll
    for (int it = 0; it < 8; it++) {
        int c = it * NT + tid;
        int row = c >> 5, part = c & 31;
        cpa16(dst + c * 16, src + (size_t)(r0 + row) * H + part * 4, (r0 + row) < limit);
    }
    CP_COMMIT();
}

__device__ __forceinline__ void stage_A_h(uint32_t sb, const __half* src, int r0, int limit) {
    int tid = threadIdx.x;
    uint32_t dst = sb + SM_STAGE;
#pragma unroll
    for (int it = 0; it < 4; it++) {
        int c = it * NT + tid;
        int row = c >> 4, part = c & 15;
        cpa16(dst + c * 16, src + (size_t)(r0 + row) * H + part * 8, (r0 + row) < limit);
    }
    CP_COMMIT();
}

__device__ __forceinline__ void convert_plain(char* sm) {
    const float* stg = (const float*)(sm + SM_STAGE);
    char* sA = sm + SM_A;
    int tid = threadIdx.x;
#pragma unroll
    for (int it = 0; it < 4; it++) {
        int s = it * NT + tid;
        int row = s >> 4, kseg = s & 15;
        const float4* p = (const float4*)(stg + row * 128 + kseg * 8);
        float4 f0 = p[0], f1 = p[1];
        float v[8] = {f0.x, f0.y, f0.z, f0.w, f1.x, f1.y, f1.z, f1.w};
        uint32_t off = (uint32_t)row * 256 + (uint32_t)((kseg ^ (row & 7)) << 4);
        storeA8(sA, sA + 32768, off, v);
    }
}

__device__ __forceinline__ void convert_bn_h(char* sm) {
    const __half* stg = (const __half*)(sm + SM_STAGE);
    const float4* sc4 = (const float4*)(sm + SM_SC);
    const float4* sh4 = (const float4*)(sm + SM_SH);
    char* sA = sm + SM_A;
    int tid = threadIdx.x;
#pragma unroll
    for (int it = 0; it < 4; it++) {
        int s = it * NT + tid;
        int row = s >> 4, kseg = s & 15;
        const __half2* p = (const __half2*)(stg + row * 128 + kseg * 8);
        float2 a0 = __half22float2(p[0]);
        float2 a1 = __half22float2(p[1]);
        float2 a2 = __half22float2(p[2]);
        float2 a3 = __half22float2(p[3]);
        float4 s0 = sc4[kseg * 2], s1 = sc4[kseg * 2 + 1];
        float4 t0 = sh4[kseg * 2], t1 = sh4[kseg * 2 + 1];
        float v[8];
        v[0] = fmaxf(fmaf(a0.x, s0.x, t0.x), 0.f);
        v[1] = fmaxf(fmaf(a0.y, s0.y, t0.y), 0.f);
        v[2] = fmaxf(fmaf(a1.x, s0.z, t0.z), 0.f);
        v[3] = fmaxf(fmaf(a1.y, s0.w, t0.w), 0.f);
        v[4] = fmaxf(fmaf(a2.x, s1.x, t1.x), 0.f);
        v[5] = fmaxf(fmaf(a2.y, s1.y, t1.y), 0.f);
        v[6] = fmaxf(fmaf(a3.x, s1.z, t1.z), 0.f);
        v[7] = fmaxf(fmaf(a3.y, s1.w, t1.w), 0.f);
        uint32_t off = (uint32_t)row * 256 + (uint32_t)((kseg ^ (row & 7)) << 4);
        storeA8(sA, sA + 32768, off, v);
    }
}

__device__ __forceinline__ void copy_B(int widx, char* sB) {
    const uint4* g = (const uint4*)(g_Bimg + (size_t)widx * 65536);
    uint4* d = (uint4*)sB;
    int tid = threadIdx.x;
#pragma unroll
    for (int it = 0; it < 8; it++) d[it * NT + tid] = g[it * NT + tid];
}

// ---- k_edge pieces (256 thr, M=64) ----
__device__ __forceinline__ void copy_B256(int widx, char* sB) {
    const uint4* g = (const uint4*)(g_Bimg + (size_t)widx * 65536);
    uint4* d = (uint4*)sB;
    int tid = threadIdx.x;
#pragma unroll
    for (int it = 0; it < 16; it++) d[it * 256 + tid] = g[it * 256 + tid];
}

__device__ __forceinline__ void loadA64(const float* src, int r0, int limit, char* sm) {
    char* sA = sm + E_C;
    int tid = threadIdx.x;
#pragma unroll
    for (int it = 0; it < 4; it++) {
        int s = it * 256 + tid;
        int row = s >> 4, kseg = s & 15;
        float v[8] = {0.f, 0.f, 0.f, 0.f, 0.f, 0.f, 0.f, 0.f};
        if (r0 + row < limit) {
            const float* p = src + (size_t)(r0 + row) * H + kseg * 8;
            float4 f0 = *(const float4*)p;
            float4 f1 = *(const float4*)(p + 4);
            v[0] = f0.x; v[1] = f0.y; v[2] = f0.z; v[3] = f0.w;
            v[4] = f1.x; v[5] = f1.y; v[6] = f1.z; v[7] = f1.w;
        }
        uint32_t off = (uint32_t)row * 256 + (uint32_t)((kseg ^ (row & 7)) << 4);
        storeA8(sA, sA + 16384, off, v);
    }
}

__device__ __forceinline__ float2 h2f(uint32_t u) {
    __half2 h = *reinterpret_cast<__half2*>(&u);
    return __half22float2(h);
}

// ---------------------------------------------------------------------------
__global__ void k_init(const float* __restrict__ time_emb,
                       const float* __restrict__ Wt, const float* __restrict__ bt,
                       const float* __restrict__ Wo, const float* __restrict__ bo) {
    int j = threadIdx.x;
    for (int i = j; i < 4 * H; i += H) g_stats[i] = 0.0f;
    __shared__ float tv[H];
    float acc = bt[j];
    for (int k = 0; k < H; k++) acc += time_emb[k] * Wt[k * H + j];
    tv[j] = acc;
    __syncthreads();
    float c = bo[j];
    for (int k = 0; k < H; k++) c += tv[k] * Wo[k * H + j];
    g_cvec[j] = c;
}

// ---------------------------------------------------------------------------
__global__ void k_prep(const float* __restrict__ WU, const float* __restrict__ WV,
                       const float* __restrict__ WA, const float* __restrict__ WB,
                       const float* __restrict__ WC, const float* __restrict__ Wo) {
    const float* Ws[6] = {WU, WV, WA, WB, WC, Wo};
    const float* W = Ws[blockIdx.x];
    unsigned char* img = g_Bimg + (size_t)blockIdx.x * 65536;
    int tid = threadIdx.x;
    for (int it = 0; it < 64; it++) {
        int idx = it * 256 + tid;
        int k = idx >> 7, n = idx & 127;
        float v = W[k * H + n];
        __nv_bfloat16 hi = __float2bfloat16_rn(v);
        __nv_bfloat16 lo = __float2bfloat16_rn(v - __bfloat162float(hi));
        uint32_t off = (uint32_t)n * 256 + (uint32_t)((((k >> 3) ^ (n & 7))) << 4) + (k & 7) * 2;
        *(__nv_bfloat16*)(img + off) = hi;
        *(__nv_bfloat16*)(img + 32768 + off) = lo;
    }
}

// ---------------------------------------------------------------------------
// k_node: persistent; Uh->agg fp32, Vn/Ah->colpack_h fp16, Bh->Bh_h fp16
// ---------------------------------------------------------------------------
__global__ __launch_bounds__(NT, 1) void k_node(
        const float* __restrict__ h,
        const float* __restrict__ bU, const float* __restrict__ bV,
        const float* __restrict__ bA, const float* __restrict__ bB,
        int V, int nTiles) {
    extern __shared__ char sm[];
    uint32_t sb = smem_u32(sm);
    int tid = threadIdx.x, lane = tid & 31, wid = tid >> 5;
    int rm = (wid & 7) * 16, cn = (wid >> 3) * 64;
    int r_in = lane >> 2, c2 = 2 * (lane & 3);
    int widx = blockIdx.y;

    copy_B(widx, sm + SM_B);
    const float* bias;
    switch (widx) {
        case 0:  bias = bU; break;
        case 1:  bias = bV; break;
        case 2:  bias = bA; break;
        default: bias = bB; break;
    }
    float2 bv[8];
#pragma unroll
    for (int nf = 0; nf < 8; nf++) bv[nf] = *(const float2*)(bias + cn + nf * 8 + c2);

    int t = blockIdx.x;
    if (t >= nTiles) return;
    stage_A(sb, h, t * 128, V);
    CP_WAIT0(); __syncthreads();
    convert_plain(sm);
    __syncthreads();

    while (t < nTiles) {
        int nxt = t + gridDim.x;
        if (nxt < nTiles) stage_A(sb, h, nxt * 128, V);

        float C[8][4];
        gemm_compute(sb + SM_A, sb + SM_B, C);

        int r0 = t * 128;
#pragma unroll
        for (int nf = 0; nf < 8; nf++) {
#pragma unroll
            for (int hf = 0; hf < 2; hf++) {
                int row = r0 + rm + hf * 8 + r_in;
                if (row < V) {
                    int col = cn + nf * 8 + c2;
                    float ox = C[nf][2 * hf] + bv[nf].x;
                    float oy = C[nf][2 * hf + 1] + bv[nf].y;
                    if (widx == 0) {
                        *(float2*)(g_agg + (size_t)row * 128 + col) = make_float2(ox, oy);
                    } else {
                        __half2 hv = __floats2half2_rn(ox, oy);
                        __half* dst;
                        if (widx == 1)      dst = g_colpack_h + (size_t)row * 256 + col;
                        else if (widx == 2) dst = g_colpack_h + (size_t)row * 256 + 128 + col;
                        else                dst = g_Bh_h + (size_t)row * 128 + col;
                        *(__half2*)dst = hv;
                    }
                }
            }
        }
        CP_WAIT0();
        __syncthreads();
        if (nxt < nTiles) convert_plain(sm);
        __syncthreads();
        t = nxt;
    }
}

// ---------------------------------------------------------------------------
// k_edge: 2 CTAs/SM, M=64, fp16 gathers + fp16 epre store + fp32 agg atomics
// ---------------------------------------------------------------------------
__global__ __launch_bounds__(256, 2) void k_edge(
        const float* __restrict__ e, const float* __restrict__ bC,
        const int* __restrict__ eidx, int E, int nTiles) {
    extern __shared__ char sm[];
    uint32_t sb = smem_u32(sm);
    int tid = threadIdx.x, lane = tid & 31, w = tid >> 5;

    copy_B256(4, sm + E_B);
    float4 bc = *(const float4*)(bC + lane * 4);
    float ss[4] = {0.f, 0.f, 0.f, 0.f}, sq[4] = {0.f, 0.f, 0.f, 0.f};

    int* rI = (int*)(sm + E_IDX);
    int* cI = rI + 64;

    for (int t = blockIdx.x; t < nTiles; t += gridDim.x) {
        int e0 = t * 64;
        __syncthreads();

        if (tid < 64) {
            int ei = e0 + tid;
            rI[tid] = (ei < E) ? eidx[ei] : 0;
        } else if (tid < 128) {
            int q = tid - 64, ei = e0 + q;
            cI[q] = (ei < E) ? eidx[(size_t)E + ei] : 0;
        }
        loadA64(e, e0, E, sm);
        __syncthreads();

        // prefetch gather rows: colpack_h 512B (4 lines), Bh_h 256B (2), agg 512B (4)
#pragma unroll
        for (int i = tid; i < 640; i += 256) {
            int m = i & 63, sel = i >> 6;  // 0..9
            const char* ptr;
            if (sel < 4)      ptr = (const char*)g_colpack_h + (size_t)cI[m] * 512 + sel * 128;
            else if (sel < 6) ptr = (const char*)g_Bh_h + (size_t)rI[m] * 256 + (sel - 4) * 128;
            else              ptr = (const char*)g_agg + (size_t)rI[m] * 512 + (sel - 6) * 128;
            pf_l2(ptr);
        }

        float C[8][4];
        gemm_compute64(sb + E_C, sb + E_B, C);
        __syncthreads();
        storeC64((float*)(sm + E_C), C);
        __syncthreads();

        const float* Cs = (const float*)(sm + E_C);
        int m0 = w * 8;

        // pipelined fp16 gather epilogue
        float4 cc; uint2 vnu, ahu, bhu;
        float* agp_cur;
        {
            int m = m0;
            int rv = rI[m], cv = cI[m];
            const __half* cp = g_colpack_h + (size_t)cv * 256;
            agp_cur = g_agg + (size_t)rv * 128;
            cc  = *(const float4*)(Cs + m * CSTRIDE + lane * 4);
            vnu = *(const uint2*)(cp + lane * 4);
            ahu = *(const uint2*)(cp + 128 + lane * 4);
            bhu = *(const uint2*)(g_Bh_h + (size_t)rv * 128 + lane * 4);
        }
#pragma unroll
        for (int k = 0; k < 8; k++) {
            int m = m0 + k;
            int ei = e0 + m;
            float4 ccn; uint2 vnn, ahn, bhn;
            float* agp_nxt = agp_cur;
            if (k < 7) {
                int mn = m + 1;
                int rv = rI[mn], cv = cI[mn];
                const __half* cp = g_colpack_h + (size_t)cv * 256;
                agp_nxt = g_agg + (size_t)rv * 128;
                ccn = *(const float4*)(Cs + mn * CSTRIDE + lane * 4);
                vnn = *(const uint2*)(cp + lane * 4);
                ahn = *(const uint2*)(cp + 128 + lane * 4);
                bhn = *(const uint2*)(g_Bh_h + (size_t)rv * 128 + lane * 4);
            }
            if (ei < E) {
                float2 vn0 = h2f(vnu.x), vn1 = h2f(vnu.y);
                float2 ah0 = h2f(ahu.x), ah1 = h2f(ahu.y);
                float2 bh0 = h2f(bhu.x), bh1 = h2f(bhu.y);
                float4 x;
                x.x = cc.x + bc.x + ah0.x + bh0.x;
                x.y = cc.y + bc.y + ah0.y + bh0.y;
                x.z = cc.z + bc.z + ah1.x + bh1.x;
                x.w = cc.w + bc.w + ah1.y + bh1.y;
                __half2 h01 = __floats2half2_rn(x.x, x.y);
                __half2 h23 = __floats2half2_rn(x.z, x.w);
                uint2 u;
                u.x = *reinterpret_cast<uint32_t*>(&h01);
                u.y = *reinterpret_cast<uint32_t*>(&h23);
                *(uint2*)(g_epre + (size_t)ei * H + lane * 4) = u;
                float ga = vn0.x / (1.f + __expf(-x.x));
                float gb = vn0.y / (1.f + __expf(-x.y));
                float gc = vn1.x / (1.f + __expf(-x.z));
                float gd = vn1.y / (1.f + __expf(-x.w));
                redv4(agp_cur + lane * 4, ga, gb, gc, gd);
                ss[0] += x.x; ss[1] += x.y; ss[2] += x.z; ss[3] += x.w;
                sq[0] += x.x * x.x; sq[1] += x.y * x.y;
                sq[2] += x.z * x.z; sq[3] += x.w * x.w;
            }
            cc = ccn; vnu = vnn; ahu = ahn; bhu = bhn; agp_cur = agp_nxt;
        }
    }

    __syncthreads();
    float* sr = (float*)(sm + E_C);
    float* qr = sr + 1024;
    *(float4*)(sr + w * 128 + lane * 4) = make_float4(ss[0], ss[1], ss[2], ss[3]);
    *(float4*)(qr + w * 128 + lane * 4) = make_float4(sq[0], sq[1], sq[2], sq[3]);
    __syncthreads();
    if (tid < 128) {
        float a = 0.f, b = 0.f;
#pragma unroll
        for (int ww = 0; ww < 8; ww++) { a += sr[ww * 128 + tid]; b += qr[ww * 128 + tid]; }
        atomicAdd(&g_stats[2 * H + tid], a);
        atomicAdd(&g_stats[3 * H + tid], b);
    }
}

// ---------------------------------------------------------------------------
// k_edgeout: 512 thr persistent cp.async pipeline, fp16 epre in (R11 proven)
// ---------------------------------------------------------------------------
__global__ __launch_bounds__(NT, 1) void k_edgeout(
        const float* __restrict__ e, float* __restrict__ out, int E, int nTiles) {
    extern __shared__ char sm[];
    uint32_t sb = smem_u32(sm);
    int tid = threadIdx.x, lane = tid & 31, wid = tid >> 5;
    int rm = (wid & 7) * 16, cn = (wid >> 3) * 64;
    int r_in = lane >> 2, c2 = 2 * (lane & 3);

    copy_B(5, sm + SM_B);
    if (tid < 128) {
        ((float*)(sm + SM_SC))[tid] = g_scale_e[tid];
        ((float*)(sm + SM_SH))[tid] = g_shift_e[tid];
    }
    float2 cv2[8];
#pragma unroll
    for (int nf = 0; nf < 8; nf++) cv2[nf] = *(const float2*)(g_cvec + cn + nf * 8 + c2);

    int t = blockIdx.x;
    if (t >= nTiles) return;

    stage_A_h(sb, g_epre, t * 128, E);
    {
        int row = tid >> 2, part = (tid & 3) * 32;
        if (t * 128 + row < E) pf_l2(e + (size_t)(t * 128 + row) * H + part);
    }
    CP_WAIT0(); __syncthreads();
    convert_bn_h(sm);
    __syncthreads();

    while (t < nTiles) {
        int nxt = t + gridDim.x;
        if (nxt < nTiles) {
            stage_A_h(sb, g_epre, nxt * 128, E);
            int row = tid >> 2, part = (tid & 3) * 32;
            if (nxt * 128 + row < E) pf_l2(e + (size_t)(nxt * 128 + row) * H + part);
        }

        float C[8][4];
        gemm_compute(sb + SM_A, sb + SM_B, C);

        int e0 = t * 128;
#pragma unroll
        for (int nf = 0; nf < 8; nf++) {
#pragma unroll
            for (int hf = 0; hf < 2; hf++) {
                int ei = e0 + rm + hf * 8 + r_in;
                if (ei < E) {
                    int col = cn + nf * 8 + c2;
                    float2 ev = *(const float2*)(e + (size_t)ei * H + col);
                    float2 o = make_float2(ev.x + C[nf][2 * hf] + cv2[nf].x,
                                           ev.y + C[nf][2 * hf + 1] + cv2[nf].y);
                    *(float2*)(out + (size_t)ei * H + col) = o;
                }
            }
        }
        CP_WAIT0();
        __syncthreads();
        if (nxt < nTiles) convert_bn_h(sm);
        __syncthreads();
        t = nxt;
    }
}

// ---------------------------------------------------------------------------
__global__ void k_nstats(int rows) {
    int tid = threadIdx.x;
    int cg = tid & 31, wr = tid >> 5;
    float4 s = make_float4(0.f, 0.f, 0.f, 0.f);
    float4 qq = make_float4(0.f, 0.f, 0.f, 0.f);
    const float4* s4 = (const float4*)g_agg;
    for (int r = blockIdx.x * 8 + wr; r < rows; r += gridDim.x * 8) {
        float4 x = s4[(size_t)r * 32 + cg];
        s.x += x.x; s.y += x.y; s.z += x.z; s.w += x.w;
        qq.x += x.x * x.x; qq.y += x.y * x.y; qq.z += x.z * x.z; qq.w += x.w * x.w;
    }
    __shared__ float sh1[8][128], sh2[8][128];
    *(float4*)&sh1[wr][cg * 4] = s;
    *(float4*)&sh2[wr][cg * 4] = qq;
    __syncthreads();
    if (tid < 128) {
        float a = 0.f, b = 0.f;
#pragma unroll
        for (int ww = 0; ww < 8; ww++) { a += sh1[ww][tid]; b += sh2[ww][tid]; }
        atomicAdd(&g_stats[tid], a);
        atomicAdd(&g_stats[H + tid], b);
    }
}

// ---------------------------------------------------------------------------
__global__ void k_finalize(const float* __restrict__ gh, const float* __restrict__ bh,
                           const float* __restrict__ ge, const float* __restrict__ be,
                           int V, int E) {
    int j = threadIdx.x;
    float invV = 1.0f / (float)V, invE = 1.0f / (float)E;
    float mh = g_stats[j] * invV;
    float vh = g_stats[H + j] * invV - mh * mh;
    float sc = gh[j] * rsqrtf(vh + 1e-5f);
    g_scale_h[j] = sc;
    g_shift_h[j] = bh[j] - mh * sc;
    float me = g_stats[2 * H + j] * invE;
    float ve = g_stats[3 * H + j] * invE - me * me;
    float se = ge[j] * rsqrtf(ve + 1e-5f);
    g_scale_e[j] = se;
    g_shift_e[j] = be[j] - me * se;
}

// ---------------------------------------------------------------------------
__global__ void k_nodeout(const float* __restrict__ h, float* __restrict__ out, int V) {
    int idx = blockIdx.x * blockDim.x + threadIdx.x;
    int total = V * (H / 4);
    if (idx >= total) return;
    int j = (idx & 31) * 4;
    float4 a  = *(const float4*)&g_agg[(size_t)idx * 4];
    float4 sc = *(const float4*)&g_scale_h[j];
    float4 sh = *(const float4*)&g_shift_h[j];
    float4 hv = *(const float4*)&h[(size_t)idx * 4];
    float4 r;
    r.x = hv.x + fmaxf(fmaf(a.x, sc.x, sh.x), 0.f);
    r.y = hv.y + fmaxf(fmaf(a.y, sc.y, sh.y), 0.f);
    r.z = hv.z + fmaxf(fmaf(a.z, sc.z, sh.z), 0.f);
    r.w = hv.w + fmaxf(fmaf(a.w, sc.w, sh.w), 0.f);
    *(float4*)&out[(size_t)idx * 4] = r;
}

// ---------------------------------------------------------------------------
extern "C" void kernel_launch(void* const* d_in, const int* in_sizes, int n_in,
                              void* d_out, int out_size) {
    const float* h        = (const float*)d_in[0];
    const float* e        = (const float*)d_in[1];
    const float* time_emb = (const float*)d_in[2];
    const int*   eidx     = (const int*)d_in[3];
    const float* WU = (const float*)d_in[4];  const float* bU = (const float*)d_in[5];
    const float* WV = (const float*)d_in[6];  const float* bV = (const float*)d_in[7];
    const float* WA = (const float*)d_in[8];  const float* bA = (const float*)d_in[9];
    const float* WB = (const float*)d_in[10]; const float* bB = (const float*)d_in[11];
    const float* WC = (const float*)d_in[12]; const float* bC = (const float*)d_in[13];
    const float* Wt = (const float*)d_in[14]; const float* bt = (const float*)d_in[15];
    const float* Wo = (const float*)d_in[16]; const float* bo = (const float*)d_in[17];
    const float* gh = (const float*)d_in[18]; const float* bh = (const float*)d_in[19];
    const float* ge = (const float*)d_in[20]; const float* be = (const float*)d_in[21];

    int V = in_sizes[0] / H;
    int E = in_sizes[3] / 2;

    float* xout = (float*)d_out;
    float* eout = xout + (size_t)V * H;

    cudaFuncSetAttribute(k_node,    cudaFuncAttributeMaxDynamicSharedMemorySize, SMEM_BYTES);
    cudaFuncSetAttribute(k_edge,    cudaFuncAttributeMaxDynamicSharedMemorySize, E_SMEM);
    cudaFuncSetAttribute(k_edgeout, cudaFuncAttributeMaxDynamicSharedMemorySize, SMEM_BYTES);

    int vTiles   = (V + 127) / 128;
    int eTiles   = (E + 127) / 128;
    int eTiles64 = (E + 63) / 64;
    int gxNode = vTiles < 37 ? vTiles : 37;
    int gxE64 = eTiles64 < 296 ? eTiles64 : 296;
    int gxE = eTiles < 148 ? eTiles : 148;

    k_init<<<1, 128>>>(time_emb, Wt, bt, Wo, bo);
    k_prep<<<6, 256>>>(WU, WV, WA, WB, WC, Wo);
    k_node<<<dim3(gxNode, 4), NT, SMEM_BYTES>>>(h, bU, bV, bA, bB, V, vTiles);
    k_edge<<<gxE64, 256, E_SMEM>>>(e, bC, eidx, E, eTiles64);
    k_nstats<<<512, 256>>>(V);
    k_finalize<<<1, 128>>>(gh, bh, ge, be, V, E);
    k_nodeout<<<(V * (H / 4) + 255) / 256, 256>>>(h, xout, V);
    k_edgeout<<<gxE, NT, SMEM_BYTES>>>(e, eout, E, eTiles);
}

// round 13
// speedup vs baseline: 1.2743x; 1.1718x over previous
#include <cuda_runtime.h>
#include <cuda_bf16.h>
#include <cuda_fp16.h>
#include <cstdint>

// ---------------------------------------------------------------------------
// DAGCondGNNEncoder (sm_103 HMMA path).
// R13: single-pass fp16 MMA for the two edge GEMMs (Ce, @Wo) — 3x fewer MMAs
//      and ~2.5x less SMEM/ldsm traffic; k_node keeps 3-term split-bf16.
//      fp16 e_pre + fp16 gather operands (R11/R12 proven).
// ---------------------------------------------------------------------------

#define H 128
#define VMAX 50000
#define EMAX 625000
#define NT 512

// ---- device scratch ----
__device__ __align__(16) __half g_colpack_h[(size_t)VMAX * 256];  // [Vn|Ah] fp16
__device__ __align__(16) __half g_Bh_h[(size_t)VMAX * 128];       // Bh fp16
__device__ __align__(16) float  g_agg[(size_t)VMAX * 128];        // Uh + scatter
__device__ __align__(16) __half g_epre[(size_t)EMAX * H];         // fp16 e_pre
__device__ __align__(16) float g_stats[4 * H];
__device__ __align__(16) float g_cvec[H];
__device__ __align__(16) float g_scale_h[H];
__device__ __align__(16) float g_shift_h[H];
__device__ __align__(16) float g_scale_e[H];
__device__ __align__(16) float g_shift_e[H];
__device__ __align__(16) unsigned char g_Bimg[6 * 65536];   // split-bf16 hi/lo
__device__ __align__(16) unsigned char g_Bimg_h[2 * 32768]; // fp16: [0]=WC [1]=Wo

// ---- smem layout: 512-thr kernels (k_node / k_edgeout) ----
#define SM_SC    2048
#define SM_SH    2560
#define SM_A     4096
#define CSTRIDE  132
#define SM_STAGE 71680
#define SM_B     137216
#define SMEM_BYTES 202752

// ---- smem layout: k_edge (2 CTAs/SM, 256 thr, M=64, fp16) ----
#define E_IDX   0
#define E_C     2048         // A fp16 16KB / C fp32 33792 overlay
#define E_B     36864        // B fp16 32KB
#define E_SMEM  69632

// ---- helpers ----
__device__ __forceinline__ uint32_t smem_u32(const void* p) {
    uint32_t a;
    asm("{ .reg .u64 t; cvta.to.shared.u64 t, %1; cvt.u32.u64 %0, t; }" : "=r"(a) : "l"(p));
    return a;
}
__device__ __forceinline__ uint32_t bpack(float a, float b) {
    __nv_bfloat162 t = __floats2bfloat162_rn(a, b);
    return *reinterpret_cast<uint32_t*>(&t);
}
__device__ __forceinline__ float bres(float a) {
    __nv_bfloat16 hh = __float2bfloat16_rn(a);
    return a - __bfloat162float(hh);
}
__device__ __forceinline__ uint32_t hpack(float a, float b) {
    __half2 t = __floats2half2_rn(a, b);
    return *reinterpret_cast<uint32_t*>(&t);
}
__device__ __forceinline__ void storeA8(char* hiP, char* loP, uint32_t off, const float* v) {
    uint4 hv, lv;
    hv.x = bpack(v[0], v[1]); hv.y = bpack(v[2], v[3]);
    hv.z = bpack(v[4], v[5]); hv.w = bpack(v[6], v[7]);
    lv.x = bpack(bres(v[0]), bres(v[1])); lv.y = bpack(bres(v[2]), bres(v[3]));
    lv.z = bpack(bres(v[4]), bres(v[5])); lv.w = bpack(bres(v[6]), bres(v[7]));
    *(uint4*)(hiP + off) = hv;
    *(uint4*)(loP + off) = lv;
}
__device__ __forceinline__ void storeA8h(char* dst, uint32_t off, const float* v) {
    uint4 hv;
    hv.x = hpack(v[0], v[1]); hv.y = hpack(v[2], v[3]);
    hv.z = hpack(v[4], v[5]); hv.w = hpack(v[6], v[7]);
    *(uint4*)(dst + off) = hv;
}
__device__ __forceinline__ void ldsm4(uint32_t r[4], uint32_t addr) {
    asm volatile("ldmatrix.sync.aligned.m8n8.x4.shared.b16 {%0,%1,%2,%3}, [%4];"
        : "=r"(r[0]), "=r"(r[1]), "=r"(r[2]), "=r"(r[3]) : "r"(addr));
}
__device__ __forceinline__ void mma16816(float c[4], const uint32_t a[4], uint32_t b0, uint32_t b1) {
    asm volatile("mma.sync.aligned.m16n8k16.row.col.f32.bf16.bf16.f32 "
        "{%0,%1,%2,%3},{%4,%5,%6,%7},{%8,%9},{%0,%1,%2,%3};"
        : "+f"(c[0]), "+f"(c[1]), "+f"(c[2]), "+f"(c[3])
        : "r"(a[0]), "r"(a[1]), "r"(a[2]), "r"(a[3]), "r"(b0), "r"(b1));
}
__device__ __forceinline__ void mma16816h(float c[4], const uint32_t a[4], uint32_t b0, uint32_t b1) {
    asm volatile("mma.sync.aligned.m16n8k16.row.col.f32.f16.f16.f32 "
        "{%0,%1,%2,%3},{%4,%5,%6,%7},{%8,%9},{%0,%1,%2,%3};"
        : "+f"(c[0]), "+f"(c[1]), "+f"(c[2]), "+f"(c[3])
        : "r"(a[0]), "r"(a[1]), "r"(a[2]), "r"(a[3]), "r"(b0), "r"(b1));
}
__device__ __forceinline__ void redv4(float* p, float a, float b, float c, float d) {
    asm volatile("red.global.add.v4.f32 [%0], {%1, %2, %3, %4};"
        :: "l"(p), "f"(a), "f"(b), "f"(c), "f"(d) : "memory");
}
__device__ __forceinline__ void pf_l2(const void* p) {
    asm volatile("prefetch.global.L2 [%0];" :: "l"(p));
}
__device__ __forceinline__ void cpa16(uint32_t dst, const void* src, int pred) {
    asm volatile("{ .reg .pred p; setp.ne.b32 p, %2, 0;\n\t"
        "@p cp.async.cg.shared.global [%0], [%1], 16; }"
        :: "r"(dst), "l"(src), "r"(pred));
}
#define CP_COMMIT() asm volatile("cp.async.commit_group;" ::: "memory")
#define CP_WAIT0()  asm volatile("cp.async.wait_group 0;" ::: "memory")

// ---- GEMM core: 128x128 tile, 16 warps, split-bf16 (k_node) ----
__device__ __forceinline__ void gemm_compute(uint32_t sAu, uint32_t sBu, float C[8][4]) {
    int tid = threadIdx.x, lane = tid & 31, wid = tid >> 5;
    int rm = (wid & 7) * 16, cn = (wid >> 3) * 64;
#pragma unroll
    for (int nf = 0; nf < 8; nf++)
#pragma unroll
        for (int q = 0; q < 4; q++) C[nf][q] = 0.f;

    int xr = lane & 7;
    int arow = xr + ((lane >> 3) & 1) * 8;
    int ahs = lane >> 4;
    int bhs = (lane >> 3) & 1;
    int bnr = xr + (lane >> 4) * 8;
    uint32_t aB = sAu + (uint32_t)(rm + arow) * 256;
    uint32_t bB[4];
#pragma unroll
    for (int g = 0; g < 4; g++) bB[g] = sBu + (uint32_t)(cn + g * 16 + bnr) * 256;

#pragma unroll
    for (int ks = 0; ks < 8; ks++) {
        uint32_t oA = (uint32_t)(((ks * 2 + ahs) ^ xr) << 4);
        uint32_t oB = (uint32_t)(((ks * 2 + bhs) ^ xr) << 4);
        uint32_t aH[4], aL[4];
        ldsm4(aH, aB + oA);
        ldsm4(aL, aB + 32768 + oA);
        uint32_t bH[4][4], bL[4][4];
#pragma unroll
        for (int g = 0; g < 4; g++) {
            ldsm4(bH[g], bB[g] + oB);
            ldsm4(bL[g], bB[g] + 32768 + oB);
        }
#pragma unroll
        for (int g = 0; g < 4; g++) {
            mma16816(C[2*g],   aH, bH[g][0], bH[g][1]);
            mma16816(C[2*g+1], aH, bH[g][2], bH[g][3]);
            mma16816(C[2*g],   aH, bL[g][0], bL[g][1]);
            mma16816(C[2*g+1], aH, bL[g][2], bL[g][3]);
            mma16816(C[2*g],   aL, bH[g][0], bH[g][1]);
            mma16816(C[2*g+1], aL, bH[g][2], bH[g][3]);
        }
    }
}

// ---- GEMM core: 128x128 tile, 16 warps, fp16 single-pass (k_edgeout) ----
__device__ __forceinline__ void gemm_f16(uint32_t sAu, uint32_t sBu, float C[8][4]) {
    int tid = threadIdx.x, lane = tid & 31, wid = tid >> 5;
    int rm = (wid & 7) * 16, cn = (wid >> 3) * 64;
#pragma unroll
    for (int nf = 0; nf < 8; nf++)
#pragma unroll
        for (int q = 0; q < 4; q++) C[nf][q] = 0.f;

    int xr = lane & 7;
    int arow = xr + ((lane >> 3) & 1) * 8;
    int ahs = lane >> 4;
    int bhs = (lane >> 3) & 1;
    int bnr = xr + (lane >> 4) * 8;
    uint32_t aB = sAu + (uint32_t)(rm + arow) * 256;
    uint32_t bB[4];
#pragma unroll
    for (int g = 0; g < 4; g++) bB[g] = sBu + (uint32_t)(cn + g * 16 + bnr) * 256;

#pragma unroll
    for (int ks = 0; ks < 8; ks++) {
        uint32_t oA = (uint32_t)(((ks * 2 + ahs) ^ xr) << 4);
        uint32_t oB = (uint32_t)(((ks * 2 + bhs) ^ xr) << 4);
        uint32_t aH[4];
        ldsm4(aH, aB + oA);
        uint32_t bH[4][4];
#pragma unroll
        for (int g = 0; g < 4; g++) ldsm4(bH[g], bB[g] + oB);
#pragma unroll
        for (int g = 0; g < 4; g++) {
            mma16816h(C[2*g],   aH, bH[g][0], bH[g][1]);
            mma16816h(C[2*g+1], aH, bH[g][2], bH[g][3]);
        }
    }
}

// ---- GEMM core: 64x128 tile, 8 warps, fp16 single-pass (k_edge) ----
__device__ __forceinline__ void gemm64_f16(uint32_t sAu, uint32_t sBu, float C[8][4]) {
    int tid = threadIdx.x, lane = tid & 31, wid = tid >> 5;
    int rm = (wid & 3) * 16, cn = (wid >> 2) * 64;
#pragma unroll
    for (int nf = 0; nf < 8; nf++)
#pragma unroll
        for (int q = 0; q < 4; q++) C[nf][q] = 0.f;

    int xr = lane & 7;
    int arow = xr + ((lane >> 3) & 1) * 8;
    int ahs = lane >> 4;
    int bhs = (lane >> 3) & 1;
    int bnr = xr + (lane >> 4) * 8;
    uint32_t aB = sAu + (uint32_t)(rm + arow) * 256;
    uint32_t bB[4];
#pragma unroll
    for (int g = 0; g < 4; g++) bB[g] = sBu + (uint32_t)(cn + g * 16 + bnr) * 256;

#pragma unroll
    for (int ks = 0; ks < 8; ks++) {
        uint32_t oA = (uint32_t)(((ks * 2 + ahs) ^ xr) << 4);
        uint32_t oB = (uint32_t)(((ks * 2 + bhs) ^ xr) << 4);
        uint32_t aH[4];
        ldsm4(aH, aB + oA);
        uint32_t bH[4][4];
#pragma unroll
        for (int g = 0; g < 4; g++) ldsm4(bH[g], bB[g] + oB);
#pragma unroll
        for (int g = 0; g < 4; g++) {
            mma16816h(C[2*g],   aH, bH[g][0], bH[g][1]);
            mma16816h(C[2*g+1], aH, bH[g][2], bH[g][3]);
        }
    }
}

__device__ __forceinline__ void storeC64(float* Cs, float C[8][4]) {
    int tid = threadIdx.x, lane = tid & 31, wid = tid >> 5;
    int rm = (wid & 3) * 16, cn = (wid >> 2) * 64;
    int r = lane >> 2, c2 = 2 * (lane & 3);
#pragma unroll
    for (int nf = 0; nf < 8; nf++) {
        int col = cn + nf * 8 + c2;
        *(float2*)(Cs + (rm + r) * CSTRIDE + col)     = make_float2(C[nf][0], C[nf][1]);
        *(float2*)(Cs + (rm + r + 8) * CSTRIDE + col) = make_float2(C[nf][2], C[nf][3]);
    }
}

// ---- 512-thr pipeline pieces ----
__device__ __forceinline__ void stage_A(uint32_t sb, const float* src, int r0, int limit) {
    int tid = threadIdx.x;
    uint32_t dst = sb + SM_STAGE;
#pragma unroll
    for (int it = 0; it < 8; it++) {
        int c = it * NT + tid;
        int row = c >> 5, part = c & 31;
        cpa16(dst + c * 16, src + (size_t)(r0 + row) * H + part * 4, (r0 + row) < limit);
    }
    CP_COMMIT();
}

__device__ __forceinline__ void stage_A_h(uint32_t sb, const __half* src, int r0, int limit) {
    int tid = threadIdx.x;
    uint32_t dst = sb + SM_STAGE;
#pragma unroll
    for (int it = 0; it < 4; it++) {
        int c = it * NT + tid;
        int row = c >> 4, part = c & 15;
        cpa16(dst + c * 16, src + (size_t)(r0 + row) * H + part * 8, (r0 + row) < limit);
    }
    CP_COMMIT();
}

__device__ __forceinline__ void convert_plain(char* sm) {
    const float* stg = (const float*)(sm + SM_STAGE);
    char* sA = sm + SM_A;
    int tid = threadIdx.x;
#pragma unroll
    for (int it = 0; it < 4; it++) {
        int s = it * NT + tid;
        int row = s >> 4, kseg = s & 15;
        const float4* p = (const float4*)(stg + row * 128 + kseg * 8);
        float4 f0 = p[0], f1 = p[1];
        float v[8] = {f0.x, f0.y, f0.z, f0.w, f1.x, f1.y, f1.z, f1.w};
        uint32_t off = (uint32_t)row * 256 + (uint32_t)((kseg ^ (row & 7)) << 4);
        storeA8(sA, sA + 32768, off, v);
    }
}

// fp16 stage -> BN+relu -> fp16 A tile (single image)
__device__ __forceinline__ void convert_bn_h(char* sm) {
    const __half* stg = (const __half*)(sm + SM_STAGE);
    const float4* sc4 = (const float4*)(sm + SM_SC);
    const float4* sh4 = (const float4*)(sm + SM_SH);
    char* sA = sm + SM_A;
    int tid = threadIdx.x;
#pragma unroll
    for (int it = 0; it < 4; it++) {
        int s = it * NT + tid;
        int row = s >> 4, kseg = s & 15;
        const __half2* p = (const __half2*)(stg + row * 128 + kseg * 8);
        float2 a0 = __half22float2(p[0]);
        float2 a1 = __half22float2(p[1]);
        float2 a2 = __half22float2(p[2]);
        float2 a3 = __half22float2(p[3]);
        float4 s0 = sc4[kseg * 2], s1 = sc4[kseg * 2 + 1];
        float4 t0 = sh4[kseg * 2], t1 = sh4[kseg * 2 + 1];
        float v[8];
        v[0] = fmaxf(fmaf(a0.x, s0.x, t0.x), 0.f);
        v[1] = fmaxf(fmaf(a0.y, s0.y, t0.y), 0.f);
        v[2] = fmaxf(fmaf(a1.x, s0.z, t0.z), 0.f);
        v[3] = fmaxf(fmaf(a1.y, s0.w, t0.w), 0.f);
        v[4] = fmaxf(fmaf(a2.x, s1.x, t1.x), 0.f);
        v[5] = fmaxf(fmaf(a2.y, s1.y, t1.y), 0.f);
        v[6] = fmaxf(fmaf(a3.x, s1.z, t1.z), 0.f);
        v[7] = fmaxf(fmaf(a3.y, s1.w, t1.w), 0.f);
        uint32_t off = (uint32_t)row * 256 + (uint32_t)((kseg ^ (row & 7)) << 4);
        storeA8h(sA, off, v);
    }
}

__device__ __forceinline__ void copy_B(int widx, char* sB) {
    const uint4* g = (const uint4*)(g_Bimg + (size_t)widx * 65536);
    uint4* d = (uint4*)sB;
    int tid = threadIdx.x;
#pragma unroll
    for (int it = 0; it < 8; it++) d[it * NT + tid] = g[it * NT + tid];
}

// fp16 B image copy (32KB): 512 threads
__device__ __forceinline__ void copy_Bh(int hidx, char* sB) {
    const uint4* g = (const uint4*)(g_Bimg_h + (size_t)hidx * 32768);
    uint4* d = (uint4*)sB;
    int tid = threadIdx.x;
#pragma unroll
    for (int it = 0; it < 4; it++) d[it * NT + tid] = g[it * NT + tid];
}

// ---- k_edge pieces (256 thr, M=64, fp16) ----
__device__ __forceinline__ void copy_Bh256(int hidx, char* sB) {
    const uint4* g = (const uint4*)(g_Bimg_h + (size_t)hidx * 32768);
    uint4* d = (uint4*)sB;
    int tid = threadIdx.x;
#pragma unroll
    for (int it = 0; it < 8; it++) d[it * 256 + tid] = g[it * 256 + tid];
}

__device__ __forceinline__ void loadA64_f16(const float* src, int r0, int limit, char* sm) {
    char* sA = sm + E_C;
    int tid = threadIdx.x;
#pragma unroll
    for (int it = 0; it < 4; it++) {
        int s = it * 256 + tid;
        int row = s >> 4, kseg = s & 15;
        float v[8] = {0.f, 0.f, 0.f, 0.f, 0.f, 0.f, 0.f, 0.f};
        if (r0 + row < limit) {
            const float* p = src + (size_t)(r0 + row) * H + kseg * 8;
            float4 f0 = *(const float4*)p;
            float4 f1 = *(const float4*)(p + 4);
            v[0] = f0.x; v[1] = f0.y; v[2] = f0.z; v[3] = f0.w;
            v[4] = f1.x; v[5] = f1.y; v[6] = f1.z; v[7] = f1.w;
        }
        uint32_t off = (uint32_t)row * 256 + (uint32_t)((kseg ^ (row & 7)) << 4);
        storeA8h(sA, off, v);
    }
}

__device__ __forceinline__ float2 h2f(uint32_t u) {
    __half2 h = *reinterpret_cast<__half2*>(&u);
    return __half22float2(h);
}

// ---------------------------------------------------------------------------
__global__ void k_init(const float* __restrict__ time_emb,
                       const float* __restrict__ Wt, const float* __restrict__ bt,
                       const float* __restrict__ Wo, const float* __restrict__ bo) {
    int j = threadIdx.x;
    for (int i = j; i < 4 * H; i += H) g_stats[i] = 0.0f;
    __shared__ float tv[H];
    float acc = bt[j];
    for (int k = 0; k < H; k++) acc += time_emb[k] * Wt[k * H + j];
    tv[j] = acc;
    __syncthreads();
    float c = bo[j];
    for (int k = 0; k < H; k++) c += tv[k] * Wo[k * H + j];
    g_cvec[j] = c;
}

// ---------------------------------------------------------------------------
__global__ void k_prep(const float* __restrict__ WU, const float* __restrict__ WV,
                       const float* __restrict__ WA, const float* __restrict__ WB,
                       const float* __restrict__ WC, const float* __restrict__ Wo) {
    const float* Ws[6] = {WU, WV, WA, WB, WC, Wo};
    const float* W = Ws[blockIdx.x];
    unsigned char* img = g_Bimg + (size_t)blockIdx.x * 65536;
    unsigned char* imgh = (blockIdx.x >= 4) ? g_Bimg_h + (size_t)(blockIdx.x - 4) * 32768 : nullptr;
    int tid = threadIdx.x;
    for (int it = 0; it < 64; it++) {
        int idx = it * 256 + tid;
        int k = idx >> 7, n = idx & 127;
        float v = W[k * H + n];
        __nv_bfloat16 hi = __float2bfloat16_rn(v);
        __nv_bfloat16 lo = __float2bfloat16_rn(v - __bfloat162float(hi));
        uint32_t off = (uint32_t)n * 256 + (uint32_t)((((k >> 3) ^ (n & 7))) << 4) + (k & 7) * 2;
        *(__nv_bfloat16*)(img + off) = hi;
        *(__nv_bfloat16*)(img + 32768 + off) = lo;
        if (imgh) *(__half*)(imgh + off) = __float2half_rn(v);
    }
}

// ---------------------------------------------------------------------------
// k_node: persistent split-bf16 (proven); Uh->agg fp32, rest fp16 packs
// ---------------------------------------------------------------------------
__global__ __launch_bounds__(NT, 1) void k_node(
        const float* __restrict__ h,
        const float* __restrict__ bU, const float* __restrict__ bV,
        const float* __restrict__ bA, const float* __restrict__ bB,
        int V, int nTiles) {
    extern __shared__ char sm[];
    uint32_t sb = smem_u32(sm);
    int tid = threadIdx.x, lane = tid & 31, wid = tid >> 5;
    int rm = (wid & 7) * 16, cn = (wid >> 3) * 64;
    int r_in = lane >> 2, c2 = 2 * (lane & 3);
    int widx = blockIdx.y;

    copy_B(widx, sm + SM_B);
    const float* bias;
    switch (widx) {
        case 0:  bias = bU; break;
        case 1:  bias = bV; break;
        case 2:  bias = bA; break;
        default: bias = bB; break;
    }
    float2 bv[8];
#pragma unroll
    for (int nf = 0; nf < 8; nf++) bv[nf] = *(const float2*)(bias + cn + nf * 8 + c2);

    int t = blockIdx.x;
    if (t >= nTiles) return;
    stage_A(sb, h, t * 128, V);
    CP_WAIT0(); __syncthreads();
    convert_plain(sm);
    __syncthreads();

    while (t < nTiles) {
        int nxt = t + gridDim.x;
        if (nxt < nTiles) stage_A(sb, h, nxt * 128, V);

        float C[8][4];
        gemm_compute(sb + SM_A, sb + SM_B, C);

        int r0 = t * 128;
#pragma unroll
        for (int nf = 0; nf < 8; nf++) {
#pragma unroll
            for (int hf = 0; hf < 2; hf++) {
                int row = r0 + rm + hf * 8 + r_in;
                if (row < V) {
                    int col = cn + nf * 8 + c2;
                    float ox = C[nf][2 * hf] + bv[nf].x;
                    float oy = C[nf][2 * hf + 1] + bv[nf].y;
                    if (widx == 0) {
                        *(float2*)(g_agg + (size_t)row * 128 + col) = make_float2(ox, oy);
                    } else {
                        __half2 hv = __floats2half2_rn(ox, oy);
                        __half* dst;
                        if (widx == 1)      dst = g_colpack_h + (size_t)row * 256 + col;
                        else if (widx == 2) dst = g_colpack_h + (size_t)row * 256 + 128 + col;
                        else                dst = g_Bh_h + (size_t)row * 128 + col;
                        *(__half2*)dst = hv;
                    }
                }
            }
        }
        CP_WAIT0();
        __syncthreads();
        if (nxt < nTiles) convert_plain(sm);
        __syncthreads();
        t = nxt;
    }
}

// ---------------------------------------------------------------------------
// k_edge: 2 CTAs/SM, M=64, fp16 MMA + fp16 gathers + fp32 agg atomics
// ---------------------------------------------------------------------------
__global__ __launch_bounds__(256, 2) void k_edge(
        const float* __restrict__ e, const float* __restrict__ bC,
        const int* __restrict__ eidx, int E, int nTiles) {
    extern __shared__ char sm[];
    uint32_t sb = smem_u32(sm);
    int tid = threadIdx.x, lane = tid & 31, w = tid >> 5;

    copy_Bh256(0, sm + E_B);   // WC fp16
    float4 bc = *(const float4*)(bC + lane * 4);
    float ss[4] = {0.f, 0.f, 0.f, 0.f}, sq[4] = {0.f, 0.f, 0.f, 0.f};

    int* rI = (int*)(sm + E_IDX);
    int* cI = rI + 64;

    for (int t = blockIdx.x; t < nTiles; t += gridDim.x) {
        int e0 = t * 64;
        __syncthreads();

        if (tid < 64) {
            int ei = e0 + tid;
            rI[tid] = (ei < E) ? eidx[ei] : 0;
        } else if (tid < 128) {
            int q = tid - 64, ei = e0 + q;
            cI[q] = (ei < E) ? eidx[(size_t)E + ei] : 0;
        }
        loadA64_f16(e, e0, E, sm);
        __syncthreads();

#pragma unroll
        for (int i = tid; i < 640; i += 256) {
            int m = i & 63, sel = i >> 6;  // 0..9
            const char* ptr;
            if (sel < 4)      ptr = (const char*)g_colpack_h + (size_t)cI[m] * 512 + sel * 128;
            else if (sel < 6) ptr = (const char*)g_Bh_h + (size_t)rI[m] * 256 + (sel - 4) * 128;
            else              ptr = (const char*)g_agg + (size_t)rI[m] * 512 + (sel - 6) * 128;
            pf_l2(ptr);
        }

        float C[8][4];
        gemm64_f16(sb + E_C, sb + E_B, C);
        __syncthreads();
        storeC64((float*)(sm + E_C), C);
        __syncthreads();

        const float* Cs = (const float*)(sm + E_C);
        int m0 = w * 8;

        float4 cc; uint2 vnu, ahu, bhu;
        float* agp_cur;
        {
            int m = m0;
            int rv = rI[m], cv = cI[m];
            const __half* cp = g_colpack_h + (size_t)cv * 256;
            agp_cur = g_agg + (size_t)rv * 128;
            cc  = *(const float4*)(Cs + m * CSTRIDE + lane * 4);
            vnu = *(const uint2*)(cp + lane * 4);
            ahu = *(const uint2*)(cp + 128 + lane * 4);
            bhu = *(const uint2*)(g_Bh_h + (size_t)rv * 128 + lane * 4);
        }
#pragma unroll
        for (int k = 0; k < 8; k++) {
            int m = m0 + k;
            int ei = e0 + m;
            float4 ccn; uint2 vnn, ahn, bhn;
            float* agp_nxt = agp_cur;
            if (k < 7) {
                int mn = m + 1;
                int rv = rI[mn], cv = cI[mn];
                const __half* cp = g_colpack_h + (size_t)cv * 256;
                agp_nxt = g_agg + (size_t)rv * 128;
                ccn = *(const float4*)(Cs + mn * CSTRIDE + lane * 4);
                vnn = *(const uint2*)(cp + lane * 4);
                ahn = *(const uint2*)(cp + 128 + lane * 4);
                bhn = *(const uint2*)(g_Bh_h + (size_t)rv * 128 + lane * 4);
            }
            if (ei < E) {
                float2 vn0 = h2f(vnu.x), vn1 = h2f(vnu.y);
                float2 ah0 = h2f(ahu.x), ah1 = h2f(ahu.y);
                float2 bh0 = h2f(bhu.x), bh1 = h2f(bhu.y);
                float4 x;
                x.x = cc.x + bc.x + ah0.x + bh0.x;
                x.y = cc.y + bc.y + ah0.y + bh0.y;
                x.z = cc.z + bc.z + ah1.x + bh1.x;
                x.w = cc.w + bc.w + ah1.y + bh1.y;
                uint2 u;
                u.x = hpack(x.x, x.y);
                u.y = hpack(x.z, x.w);
                *(uint2*)(g_epre + (size_t)ei * H + lane * 4) = u;
                float ga = vn0.x / (1.f + __expf(-x.x));
                float gb = vn0.y / (1.f + __expf(-x.y));
                float gc = vn1.x / (1.f + __expf(-x.z));
                float gd = vn1.y / (1.f + __expf(-x.w));
                redv4(agp_cur + lane * 4, ga, gb, gc, gd);
                ss[0] += x.x; ss[1] += x.y; ss[2] += x.z; ss[3] += x.w;
                sq[0] += x.x * x.x; sq[1] += x.y * x.y;
                sq[2] += x.z * x.z; sq[3] += x.w * x.w;
            }
            cc = ccn; vnu = vnn; ahu = ahn; bhu = bhn; agp_cur = agp_nxt;
        }
    }

    __syncthreads();
    float* sr = (float*)(sm + E_C);
    float* qr = sr + 1024;
    *(float4*)(sr + w * 128 + lane * 4) = make_float4(ss[0], ss[1], ss[2], ss[3]);
    *(float4*)(qr + w * 128 + lane * 4) = make_float4(sq[0], sq[1], sq[2], sq[3]);
    __syncthreads();
    if (tid < 128) {
        float a = 0.f, b = 0.f;
#pragma unroll
        for (int ww = 0; ww < 8; ww++) { a += sr[ww * 128 + tid]; b += qr[ww * 128 + tid]; }
        atomicAdd(&g_stats[2 * H + tid], a);
        atomicAdd(&g_stats[3 * H + tid], b);
    }
}

// ---------------------------------------------------------------------------
// k_edgeout: 512 thr persistent cp.async pipeline, fp16 MMA, fp16 epre
// ---------------------------------------------------------------------------
__global__ __launch_bounds__(NT, 1) void k_edgeout(
        const float* __restrict__ e, float* __restrict__ out, int E, int nTiles) {
    extern __shared__ char sm[];
    uint32_t sb = smem_u32(sm);
    int tid = threadIdx.x, lane = tid & 31, wid = tid >> 5;
    int rm = (wid & 7) * 16, cn = (wid >> 3) * 64;
    int r_in = lane >> 2, c2 = 2 * (lane & 3);

    copy_Bh(1, sm + SM_B);   // Wo fp16
    if (tid < 128) {
        ((float*)(sm + SM_SC))[tid] = g_scale_e[tid];
        ((float*)(sm + SM_SH))[tid] = g_shift_e[tid];
    }
    float2 cv2[8];
#pragma unroll
    for (int nf = 0; nf < 8; nf++) cv2[nf] = *(const float2*)(g_cvec + cn + nf * 8 + c2);

    int t = blockIdx.x;
    if (t >= nTiles) return;

    stage_A_h(sb, g_epre, t * 128, E);
    {
        int row = tid >> 2, part = (tid & 3) * 32;
        if (t * 128 + row < E) pf_l2(e + (size_t)(t * 128 + row) * H + part);
    }
    CP_WAIT0(); __syncthreads();
    convert_bn_h(sm);
    __syncthreads();

    while (t < nTiles) {
        int nxt = t + gridDim.x;
        if (nxt < nTiles) {
            stage_A_h(sb, g_epre, nxt * 128, E);
            int row = tid >> 2, part = (tid & 3) * 32;
            if (nxt * 128 + row < E) pf_l2(e + (size_t)(nxt * 128 + row) * H + part);
        }

        float C[8][4];
        gemm_f16(sb + SM_A, sb + SM_B, C);

        int e0 = t * 128;
#pragma unroll
        for (int nf = 0; nf < 8; nf++) {
#pragma unroll
            for (int hf = 0; hf < 2; hf++) {
                int ei = e0 + rm + hf * 8 + r_in;
                if (ei < E) {
                    int col = cn + nf * 8 + c2;
                    float2 ev = *(const float2*)(e + (size_t)ei * H + col);
                    float2 o = make_float2(ev.x + C[nf][2 * hf] + cv2[nf].x,
                                           ev.y + C[nf][2 * hf + 1] + cv2[nf].y);
                    *(float2*)(out + (size_t)ei * H + col) = o;
                }
            }
        }
        CP_WAIT0();
        __syncthreads();
        if (nxt < nTiles) convert_bn_h(sm);
        __syncthreads();
        t = nxt;
    }
}

// ---------------------------------------------------------------------------
__global__ void k_nstats(int rows) {
    int tid = threadIdx.x;
    int cg = tid & 31, wr = tid >> 5;
    float4 s = make_float4(0.f, 0.f, 0.f, 0.f);
    float4 qq = make_float4(0.f, 0.f, 0.f, 0.f);
    const float4* s4 = (const float4*)g_agg;
    for (int r = blockIdx.x * 8 + wr; r < rows; r += gridDim.x * 8) {
        float4 x = s4[(size_t)r * 32 + cg];
        s.x += x.x; s.y += x.y; s.z += x.z; s.w += x.w;
        qq.x += x.x * x.x; qq.y += x.y * x.y; qq.z += x.z * x.z; qq.w += x.w * x.w;
    }
    __shared__ float sh1[8][128], sh2[8][128];
    *(float4*)&sh1[wr][cg * 4] = s;
    *(float4*)&sh2[wr][cg * 4] = qq;
    __syncthreads();
    if (tid < 128) {
        float a = 0.f, b = 0.f;
#pragma unroll
        for (int ww = 0; ww < 8; ww++) { a += sh1[ww][tid]; b += sh2[ww][tid]; }
        atomicAdd(&g_stats[tid], a);
        atomicAdd(&g_stats[H + tid], b);
    }
}

// ---------------------------------------------------------------------------
__global__ void k_finalize(const float* __restrict__ gh, const float* __restrict__ bh,
                           const float* __restrict__ ge, const float* __restrict__ be,
                           int V, int E) {
    int j = threadIdx.x;
    float invV = 1.0f / (float)V, invE = 1.0f / (float)E;
    float mh = g_stats[j] * invV;
    float vh = g_stats[H + j] * invV - mh * mh;
    float sc = gh[j] * rsqrtf(vh + 1e-5f);
    g_scale_h[j] = sc;
    g_shift_h[j] = bh[j] - mh * sc;
    float me = g_stats[2 * H + j] * invE;
    float ve = g_stats[3 * H + j] * invE - me * me;
    float se = ge[j] * rsqrtf(ve + 1e-5f);
    g_scale_e[j] = se;
    g_shift_e[j] = be[j] - me * se;
}

// ---------------------------------------------------------------------------
__global__ void k_nodeout(const float* __restrict__ h, float* __restrict__ out, int V) {
    int idx = blockIdx.x * blockDim.x + threadIdx.x;
    int total = V * (H / 4);
    if (idx >= total) return;
    int j = (idx & 31) * 4;
    float4 a  = *(const float4*)&g_agg[(size_t)idx * 4];
    float4 sc = *(const float4*)&g_scale_h[j];
    float4 sh = *(const float4*)&g_shift_h[j];
    float4 hv = *(const float4*)&h[(size_t)idx * 4];
    float4 r;
    r.x = hv.x + fmaxf(fmaf(a.x, sc.x, sh.x), 0.f);
    r.y = hv.y + fmaxf(fmaf(a.y, sc.y, sh.y), 0.f);
    r.z = hv.z + fmaxf(fmaf(a.z, sc.z, sh.z), 0.f);
    r.w = hv.w + fmaxf(fmaf(a.w, sc.w, sh.w), 0.f);
    *(float4*)&out[(size_t)idx * 4] = r;
}

// ---------------------------------------------------------------------------
extern "C" void kernel_launch(void* const* d_in, const int* in_sizes, int n_in,
                              void* d_out, int out_size) {
    const float* h        = (const float*)d_in[0];
    const float* e        = (const float*)d_in[1];
    const float* time_emb = (const float*)d_in[2];
    const int*   eidx     = (const int*)d_in[3];
    const float* WU = (const float*)d_in[4];  const float* bU = (const float*)d_in[5];
    const float* WV = (const float*)d_in[6];  const float* bV = (const float*)d_in[7];
    const float* WA = (const float*)d_in[8];  const float* bA = (const float*)d_in[9];
    const float* WB = (const float*)d_in[10]; const float* bB = (const float*)d_in[11];
    const float* WC = (const float*)d_in[12]; const float* bC = (const float*)d_in[13];
    const float* Wt = (const float*)d_in[14]; const float* bt = (const float*)d_in[15];
    const float* Wo = (const float*)d_in[16]; const float* bo = (const float*)d_in[17];
    const float* gh = (const float*)d_in[18]; const float* bh = (const float*)d_in[19];
    const float* ge = (const float*)d_in[20]; const float* be = (const float*)d_in[21];

    int V = in_sizes[0] / H;
    int E = in_sizes[3] / 2;

    float* xout = (float*)d_out;
    float* eout = xout + (size_t)V * H;

    cudaFuncSetAttribute(k_node,    cudaFuncAttributeMaxDynamicSharedMemorySize, SMEM_BYTES);
    cudaFuncSetAttribute(k_edge,    cudaFuncAttributeMaxDynamicSharedMemorySize, E_SMEM);
    cudaFuncSetAttribute(k_edgeout, cudaFuncAttributeMaxDynamicSharedMemorySize, SMEM_BYTES);

    int vTiles   = (V + 127) / 128;
    int eTiles   = (E + 127) / 128;
    int eTiles64 = (E + 63) / 64;
    int gxNode = vTiles < 37 ? vTiles : 37;
    int gxE64 = eTiles64 < 296 ? eTiles64 : 296;
    int gxE = eTiles < 148 ? eTiles : 148;

    k_init<<<1, 128>>>(time_emb, Wt, bt, Wo, bo);
    k_prep<<<6, 256>>>(WU, WV, WA, WB, WC, Wo);
    k_node<<<dim3(gxNode, 4), NT, SMEM_BYTES>>>(h, bU, bV, bA, bB, V, vTiles);
    k_edge<<<gxE64, 256, E_SMEM>>>(e, bC, eidx, E, eTiles64);
    k_nstats<<<512, 256>>>(V);
    k_finalize<<<1, 128>>>(gh, bh, ge, be, V, E);
    k_nodeout<<<(V * (H / 4) + 255) / 256, 256>>>(h, xout, V);
    k_edgeout<<<gxE, NT, SMEM_BYTES>>>(e, eout, E, eTiles);
}

// round 14
// speedup vs baseline: 1.3046x; 1.0238x over previous
#include <cuda_runtime.h>
#include <cuda_bf16.h>
#include <cuda_fp16.h>
#include <cstdint>

// ---------------------------------------------------------------------------
// DAGCondGNNEncoder (sm_103 HMMA path).
// R14: cp.async staging pipeline inside 2-CTA k_edge; fp16 single-pass MMA
//      for k_node's Vn/Ah/Bh (stored fp16 anyway). Uh keeps split-bf16.
//      fp16 e_pre + fp16 gathers + fp16 edge GEMMs (R11-R13 proven).
// ---------------------------------------------------------------------------

#define H 128
#define VMAX 50000
#define EMAX 625000
#define NT 512

// ---- device scratch ----
__device__ __align__(16) __half g_colpack_h[(size_t)VMAX * 256];  // [Vn|Ah] fp16
__device__ __align__(16) __half g_Bh_h[(size_t)VMAX * 128];       // Bh fp16
__device__ __align__(16) float  g_agg[(size_t)VMAX * 128];        // Uh + scatter
__device__ __align__(16) __half g_epre[(size_t)EMAX * H];         // fp16 e_pre
__device__ __align__(16) float g_stats[4 * H];
__device__ __align__(16) float g_cvec[H];
__device__ __align__(16) float g_scale_h[H];
__device__ __align__(16) float g_shift_h[H];
__device__ __align__(16) float g_scale_e[H];
__device__ __align__(16) float g_shift_e[H];
__device__ __align__(16) unsigned char g_Bimg[6 * 65536];   // split-bf16 hi/lo
__device__ __align__(16) unsigned char g_Bimg_h[5 * 32768]; // fp16: WV,WA,WB,WC,Wo

// ---- smem layout: 512-thr kernels (k_node / k_edgeout) ----
#define SM_SC    2048
#define SM_SH    2560
#define SM_A     4096
#define CSTRIDE  132
#define SM_STAGE 71680
#define SM_B     137216
#define SMEM_BYTES 202752

// ---- smem layout: k_edge (2 CTAs/SM, 256 thr, M=64, fp16, staged) ----
#define E_IDX   0            // idx double buffer: p*512 -> rI[64]|cI[64]
#define E_C     2048         // A fp16 16KB / C fp32 33792 overlay
#define E_STG   36864        // raw fp32 stage 32KB
#define E_B     69632        // B fp16 32KB
#define E_SMEM  102400

// ---- helpers ----
__device__ __forceinline__ uint32_t smem_u32(const void* p) {
    uint32_t a;
    asm("{ .reg .u64 t; cvta.to.shared.u64 t, %1; cvt.u32.u64 %0, t; }" : "=r"(a) : "l"(p));
    return a;
}
__device__ __forceinline__ uint32_t bpack(float a, float b) {
    __nv_bfloat162 t = __floats2bfloat162_rn(a, b);
    return *reinterpret_cast<uint32_t*>(&t);
}
__device__ __forceinline__ float bres(float a) {
    __nv_bfloat16 hh = __float2bfloat16_rn(a);
    return a - __bfloat162float(hh);
}
__device__ __forceinline__ uint32_t hpack(float a, float b) {
    __half2 t = __floats2half2_rn(a, b);
    return *reinterpret_cast<uint32_t*>(&t);
}
__device__ __forceinline__ void storeA8(char* hiP, char* loP, uint32_t off, const float* v) {
    uint4 hv, lv;
    hv.x = bpack(v[0], v[1]); hv.y = bpack(v[2], v[3]);
    hv.z = bpack(v[4], v[5]); hv.w = bpack(v[6], v[7]);
    lv.x = bpack(bres(v[0]), bres(v[1])); lv.y = bpack(bres(v[2]), bres(v[3]));
    lv.z = bpack(bres(v[4]), bres(v[5])); lv.w = bpack(bres(v[6]), bres(v[7]));
    *(uint4*)(hiP + off) = hv;
    *(uint4*)(loP + off) = lv;
}
__device__ __forceinline__ void storeA8h(char* dst, uint32_t off, const float* v) {
    uint4 hv;
    hv.x = hpack(v[0], v[1]); hv.y = hpack(v[2], v[3]);
    hv.z = hpack(v[4], v[5]); hv.w = hpack(v[6], v[7]);
    *(uint4*)(dst + off) = hv;
}
__device__ __forceinline__ void ldsm4(uint32_t r[4], uint32_t addr) {
    asm volatile("ldmatrix.sync.aligned.m8n8.x4.shared.b16 {%0,%1,%2,%3}, [%4];"
        : "=r"(r[0]), "=r"(r[1]), "=r"(r[2]), "=r"(r[3]) : "r"(addr));
}
__device__ __forceinline__ void mma16816(float c[4], const uint32_t a[4], uint32_t b0, uint32_t b1) {
    asm volatile("mma.sync.aligned.m16n8k16.row.col.f32.bf16.bf16.f32 "
        "{%0,%1,%2,%3},{%4,%5,%6,%7},{%8,%9},{%0,%1,%2,%3};"
        : "+f"(c[0]), "+f"(c[1]), "+f"(c[2]), "+f"(c[3])
        : "r"(a[0]), "r"(a[1]), "r"(a[2]), "r"(a[3]), "r"(b0), "r"(b1));
}
__device__ __forceinline__ void mma16816h(float c[4], const uint32_t a[4], uint32_t b0, uint32_t b1) {
    asm volatile("mma.sync.aligned.m16n8k16.row.col.f32.f16.f16.f32 "
        "{%0,%1,%2,%3},{%4,%5,%6,%7},{%8,%9},{%0,%1,%2,%3};"
        : "+f"(c[0]), "+f"(c[1]), "+f"(c[2]), "+f"(c[3])
        : "r"(a[0]), "r"(a[1]), "r"(a[2]), "r"(a[3]), "r"(b0), "r"(b1));
}
__device__ __forceinline__ void redv4(float* p, float a, float b, float c, float d) {
    asm volatile("red.global.add.v4.f32 [%0], {%1, %2, %3, %4};"
        :: "l"(p), "f"(a), "f"(b), "f"(c), "f"(d) : "memory");
}
__device__ __forceinline__ void pf_l2(const void* p) {
    asm volatile("prefetch.global.L2 [%0];" :: "l"(p));
}
__device__ __forceinline__ void cpa16(uint32_t dst, const void* src, int pred) {
    asm volatile("{ .reg .pred p; setp.ne.b32 p, %2, 0;\n\t"
        "@p cp.async.cg.shared.global [%0], [%1], 16; }"
        :: "r"(dst), "l"(src), "r"(pred));
}
#define CP_COMMIT() asm volatile("cp.async.commit_group;" ::: "memory")
#define CP_WAIT0()  asm volatile("cp.async.wait_group 0;" ::: "memory")

// ---- GEMM core: 128x128 tile, 16 warps, split-bf16 (k_node Uh) ----
__device__ __forceinline__ void gemm_compute(uint32_t sAu, uint32_t sBu, float C[8][4]) {
    int tid = threadIdx.x, lane = tid & 31, wid = tid >> 5;
    int rm = (wid & 7) * 16, cn = (wid >> 3) * 64;
#pragma unroll
    for (int nf = 0; nf < 8; nf++)
#pragma unroll
        for (int q = 0; q < 4; q++) C[nf][q] = 0.f;

    int xr = lane & 7;
    int arow = xr + ((lane >> 3) & 1) * 8;
    int ahs = lane >> 4;
    int bhs = (lane >> 3) & 1;
    int bnr = xr + (lane >> 4) * 8;
    uint32_t aB = sAu + (uint32_t)(rm + arow) * 256;
    uint32_t bB[4];
#pragma unroll
    for (int g = 0; g < 4; g++) bB[g] = sBu + (uint32_t)(cn + g * 16 + bnr) * 256;

#pragma unroll
    for (int ks = 0; ks < 8; ks++) {
        uint32_t oA = (uint32_t)(((ks * 2 + ahs) ^ xr) << 4);
        uint32_t oB = (uint32_t)(((ks * 2 + bhs) ^ xr) << 4);
        uint32_t aH[4], aL[4];
        ldsm4(aH, aB + oA);
        ldsm4(aL, aB + 32768 + oA);
        uint32_t bH[4][4], bL[4][4];
#pragma unroll
        for (int g = 0; g < 4; g++) {
            ldsm4(bH[g], bB[g] + oB);
            ldsm4(bL[g], bB[g] + 32768 + oB);
        }
#pragma unroll
        for (int g = 0; g < 4; g++) {
            mma16816(C[2*g],   aH, bH[g][0], bH[g][1]);
            mma16816(C[2*g+1], aH, bH[g][2], bH[g][3]);
            mma16816(C[2*g],   aH, bL[g][0], bL[g][1]);
            mma16816(C[2*g+1], aH, bL[g][2], bL[g][3]);
            mma16816(C[2*g],   aL, bH[g][0], bH[g][1]);
            mma16816(C[2*g+1], aL, bH[g][2], bH[g][3]);
        }
    }
}

// ---- GEMM core: 128x128 tile, 16 warps, fp16 single-pass ----
__device__ __forceinline__ void gemm_f16(uint32_t sAu, uint32_t sBu, float C[8][4]) {
    int tid = threadIdx.x, lane = tid & 31, wid = tid >> 5;
    int rm = (wid & 7) * 16, cn = (wid >> 3) * 64;
#pragma unroll
    for (int nf = 0; nf < 8; nf++)
#pragma unroll
        for (int q = 0; q < 4; q++) C[nf][q] = 0.f;

    int xr = lane & 7;
    int arow = xr + ((lane >> 3) & 1) * 8;
    int ahs = lane >> 4;
    int bhs = (lane >> 3) & 1;
    int bnr = xr + (lane >> 4) * 8;
    uint32_t aB = sAu + (uint32_t)(rm + arow) * 256;
    uint32_t bB[4];
#pragma unroll
    for (int g = 0; g < 4; g++) bB[g] = sBu + (uint32_t)(cn + g * 16 + bnr) * 256;

#pragma unroll
    for (int ks = 0; ks < 8; ks++) {
        uint32_t oA = (uint32_t)(((ks * 2 + ahs) ^ xr) << 4);
        uint32_t oB = (uint32_t)(((ks * 2 + bhs) ^ xr) << 4);
        uint32_t aH[4];
        ldsm4(aH, aB + oA);
        uint32_t bH[4][4];
#pragma unroll
        for (int g = 0; g < 4; g++) ldsm4(bH[g], bB[g] + oB);
#pragma unroll
        for (int g = 0; g < 4; g++) {
            mma16816h(C[2*g],   aH, bH[g][0], bH[g][1]);
            mma16816h(C[2*g+1], aH, bH[g][2], bH[g][3]);
        }
    }
}

// ---- GEMM core: 64x128 tile, 8 warps, fp16 single-pass (k_edge) ----
__device__ __forceinline__ void gemm64_f16(uint32_t sAu, uint32_t sBu, float C[8][4]) {
    int tid = threadIdx.x, lane = tid & 31, wid = tid >> 5;
    int rm = (wid & 3) * 16, cn = (wid >> 2) * 64;
#pragma unroll
    for (int nf = 0; nf < 8; nf++)
#pragma unroll
        for (int q = 0; q < 4; q++) C[nf][q] = 0.f;

    int xr = lane & 7;
    int arow = xr + ((lane >> 3) & 1) * 8;
    int ahs = lane >> 4;
    int bhs = (lane >> 3) & 1;
    int bnr = xr + (lane >> 4) * 8;
    uint32_t aB = sAu + (uint32_t)(rm + arow) * 256;
    uint32_t bB[4];
#pragma unroll
    for (int g = 0; g < 4; g++) bB[g] = sBu + (uint32_t)(cn + g * 16 + bnr) * 256;

#pragma unroll
    for (int ks = 0; ks < 8; ks++) {
        uint32_t oA = (uint32_t)(((ks * 2 + ahs) ^ xr) << 4);
        uint32_t oB = (uint32_t)(((ks * 2 + bhs) ^ xr) << 4);
        uint32_t aH[4];
        ldsm4(aH, aB + oA);
        uint32_t bH[4][4];
#pragma unroll
        for (int g = 0; g < 4; g++) ldsm4(bH[g], bB[g] + oB);
#pragma unroll
        for (int g = 0; g < 4; g++) {
            mma16816h(C[2*g],   aH, bH[g][0], bH[g][1]);
            mma16816h(C[2*g+1], aH, bH[g][2], bH[g][3]);
        }
    }
}

__device__ __forceinline__ void storeC64(float* Cs, float C[8][4]) {
    int tid = threadIdx.x, lane = tid & 31, wid = tid >> 5;
    int rm = (wid & 3) * 16, cn = (wid >> 2) * 64;
    int r = lane >> 2, c2 = 2 * (lane & 3);
#pragma unroll
    for (int nf = 0; nf < 8; nf++) {
        int col = cn + nf * 8 + c2;
        *(float2*)(Cs + (rm + r) * CSTRIDE + col)     = make_float2(C[nf][0], C[nf][1]);
        *(float2*)(Cs + (rm + r + 8) * CSTRIDE + col) = make_float2(C[nf][2], C[nf][3]);
    }
}

// ---- 512-thr pipeline pieces ----
__device__ __forceinline__ void stage_A(uint32_t sb, const float* src, int r0, int limit) {
    int tid = threadIdx.x;
    uint32_t dst = sb + SM_STAGE;
#pragma unroll
    for (int it = 0; it < 8; it++) {
        int c = it * NT + tid;
        int row = c >> 5, part = c & 31;
        cpa16(dst + c * 16, src + (size_t)(r0 + row) * H + part * 4, (r0 + row) < limit);
    }
    CP_COMMIT();
}

__device__ __forceinline__ void stage_A_h(uint32_t sb, const __half* src, int r0, int limit) {
    int tid = threadIdx.x;
    uint32_t dst = sb + SM_STAGE;
#pragma unroll
    for (int it = 0; it < 4; it++) {
        int c = it * NT + tid;
        int row = c >> 4, part = c & 15;
        cpa16(dst + c * 16, src + (size_t)(r0 + row) * H + part * 8, (r0 + row) < limit);
    }
    CP_COMMIT();
}

__device__ __forceinline__ void convert_plain(char* sm) {
    const float* stg = (const float*)(sm + SM_STAGE);
    char* sA = sm + SM_A;
    int tid = threadIdx.x;
#pragma unroll
    for (int it = 0; it < 4; it++) {
        int s = it * NT + tid;
        int row = s >> 4, kseg = s & 15;
        const float4* p = (const float4*)(stg + row * 128 + kseg * 8);
        float4 f0 = p[0], f1 = p[1];
        float v[8] = {f0.x, f0.y, f0.z, f0.w, f1.x, f1.y, f1.z, f1.w};
        uint32_t off = (uint32_t)row * 256 + (uint32_t)((kseg ^ (row & 7)) << 4);
        storeA8(sA, sA + 32768, off, v);
    }
}

// fp32 stage -> fp16 A tile (k_node widx 1-3)
__device__ __forceinline__ void convert_plain_h(char* sm) {
    const float* stg = (const float*)(sm + SM_STAGE);
    char* sA = sm + SM_A;
    int tid = threadIdx.x;
#pragma unroll
    for (int it = 0; it < 4; it++) {
        int s = it * NT + tid;
        int row = s >> 4, kseg = s & 15;
        const float4* p = (const float4*)(stg + row * 128 + kseg * 8);
        float4 f0 = p[0], f1 = p[1];
        float v[8] = {f0.x, f0.y, f0.z, f0.w, f1.x, f1.y, f1.z, f1.w};
        uint32_t off = (uint32_t)row * 256 + (uint32_t)((kseg ^ (row & 7)) << 4);
        storeA8h(sA, off, v);
    }
}

// fp16 stage -> BN+relu -> fp16 A tile (k_edgeout)
__device__ __forceinline__ void convert_bn_h(char* sm) {
    const __half* stg = (const __half*)(sm + SM_STAGE);
    const float4* sc4 = (const float4*)(sm + SM_SC);
    const float4* sh4 = (const float4*)(sm + SM_SH);
    char* sA = sm + SM_A;
    int tid = threadIdx.x;
#pragma unroll
    for (int it = 0; it < 4; it++) {
        int s = it * NT + tid;
        int row = s >> 4, kseg = s & 15;
        const __half2* p = (const __half2*)(stg + row * 128 + kseg * 8);
        float2 a0 = __half22float2(p[0]);
        float2 a1 = __half22float2(p[1]);
        float2 a2 = __half22float2(p[2]);
        float2 a3 = __half22float2(p[3]);
        float4 s0 = sc4[kseg * 2], s1 = sc4[kseg * 2 + 1];
        float4 t0 = sh4[kseg * 2], t1 = sh4[kseg * 2 + 1];
        float v[8];
        v[0] = fmaxf(fmaf(a0.x, s0.x, t0.x), 0.f);
        v[1] = fmaxf(fmaf(a0.y, s0.y, t0.y), 0.f);
        v[2] = fmaxf(fmaf(a1.x, s0.z, t0.z), 0.f);
        v[3] = fmaxf(fmaf(a1.y, s0.w, t0.w), 0.f);
        v[4] = fmaxf(fmaf(a2.x, s1.x, t1.x), 0.f);
        v[5] = fmaxf(fmaf(a2.y, s1.y, t1.y), 0.f);
        v[6] = fmaxf(fmaf(a3.x, s1.z, t1.z), 0.f);
        v[7] = fmaxf(fmaf(a3.y, s1.w, t1.w), 0.f);
        uint32_t off = (uint32_t)row * 256 + (uint32_t)((kseg ^ (row & 7)) << 4);
        storeA8h(sA, off, v);
    }
}

__device__ __forceinline__ void copy_B(int widx, char* sB) {
    const uint4* g = (const uint4*)(g_Bimg + (size_t)widx * 65536);
    uint4* d = (uint4*)sB;
    int tid = threadIdx.x;
#pragma unroll
    for (int it = 0; it < 8; it++) d[it * NT + tid] = g[it * NT + tid];
}

__device__ __forceinline__ void copy_Bh(int hidx, char* sB) {
    const uint4* g = (const uint4*)(g_Bimg_h + (size_t)hidx * 32768);
    uint4* d = (uint4*)sB;
    int tid = threadIdx.x;
#pragma unroll
    for (int it = 0; it < 4; it++) d[it * NT + tid] = g[it * NT + tid];
}

// ---- k_edge pieces (256 thr, M=64, fp16, staged) ----
__device__ __forceinline__ void copy_Bh256(int hidx, char* sB) {
    const uint4* g = (const uint4*)(g_Bimg_h + (size_t)hidx * 32768);
    uint4* d = (uint4*)sB;
    int tid = threadIdx.x;
#pragma unroll
    for (int it = 0; it < 8; it++) d[it * 256 + tid] = g[it * 256 + tid];
}

// stage 64 rows of fp32 e (32KB) via cp.async
__device__ __forceinline__ void stage_A64(uint32_t sb, const float* src, int r0, int limit) {
    int tid = threadIdx.x;
    uint32_t dst = sb + E_STG;
#pragma unroll
    for (int it = 0; it < 8; it++) {
        int c = it * 256 + tid;
        int row = c >> 5, part = c & 31;
        cpa16(dst + c * 16, src + (size_t)(r0 + row) * H + part * 4, (r0 + row) < limit);
    }
    CP_COMMIT();
}

// fp32 stage -> fp16 A (64 rows)
__device__ __forceinline__ void convert64_h(char* sm) {
    const float* stg = (const float*)(sm + E_STG);
    char* sA = sm + E_C;
    int tid = threadIdx.x;
#pragma unroll
    for (int it = 0; it < 4; it++) {
        int s = it * 256 + tid;
        int row = s >> 4, kseg = s & 15;
        const float4* p = (const float4*)(stg + row * 128 + kseg * 8);
        float4 f0 = p[0], f1 = p[1];
        float v[8] = {f0.x, f0.y, f0.z, f0.w, f1.x, f1.y, f1.z, f1.w};
        uint32_t off = (uint32_t)row * 256 + (uint32_t)((kseg ^ (row & 7)) << 4);
        storeA8h(sA, off, v);
    }
}

__device__ __forceinline__ void load_idx64(char* sm, const int* eidx, int t, int E, int p) {
    int tid = threadIdx.x;
    int e0 = t * 64;
    int* rI = (int*)(sm + E_IDX + p * 512);
    if (tid < 64) {
        int ei = e0 + tid;
        rI[tid] = (ei < E) ? eidx[ei] : 0;
    } else if (tid < 128) {
        int q = tid - 64, ei = e0 + q;
        rI[64 + q] = (ei < E) ? eidx[(size_t)E + ei] : 0;
    }
}

__device__ __forceinline__ float2 h2f(uint32_t u) {
    __half2 h = *reinterpret_cast<__half2*>(&u);
    return __half22float2(h);
}

// ---------------------------------------------------------------------------
__global__ void k_init(const float* __restrict__ time_emb,
                       const float* __restrict__ Wt, const float* __restrict__ bt,
                       const float* __restrict__ Wo, const float* __restrict__ bo) {
    int j = threadIdx.x;
    for (int i = j; i < 4 * H; i += H) g_stats[i] = 0.0f;
    __shared__ float tv[H];
    float acc = bt[j];
    for (int k = 0; k < H; k++) acc += time_emb[k] * Wt[k * H + j];
    tv[j] = acc;
    __syncthreads();
    float c = bo[j];
    for (int k = 0; k < H; k++) c += tv[k] * Wo[k * H + j];
    g_cvec[j] = c;
}

// ---------------------------------------------------------------------------
__global__ void k_prep(const float* __restrict__ WU, const float* __restrict__ WV,
                       const float* __restrict__ WA, const float* __restrict__ WB,
                       const float* __restrict__ WC, const float* __restrict__ Wo) {
    const float* Ws[6] = {WU, WV, WA, WB, WC, Wo};
    const float* W = Ws[blockIdx.x];
    unsigned char* img = g_Bimg + (size_t)blockIdx.x * 65536;
    unsigned char* imgh = (blockIdx.x >= 1) ? g_Bimg_h + (size_t)(blockIdx.x - 1) * 32768 : nullptr;
    int tid = threadIdx.x;
    for (int it = 0; it < 64; it++) {
        int idx = it * 256 + tid;
        int k = idx >> 7, n = idx & 127;
        float v = W[k * H + n];
        __nv_bfloat16 hi = __float2bfloat16_rn(v);
        __nv_bfloat16 lo = __float2bfloat16_rn(v - __bfloat162float(hi));
        uint32_t off = (uint32_t)n * 256 + (uint32_t)((((k >> 3) ^ (n & 7))) << 4) + (k & 7) * 2;
        *(__nv_bfloat16*)(img + off) = hi;
        *(__nv_bfloat16*)(img + 32768 + off) = lo;
        if (imgh) *(__half*)(imgh + off) = __float2half_rn(v);
    }
}

// ---------------------------------------------------------------------------
// k_node: persistent. widx 0 (Uh) split-bf16; widx 1-3 fp16 single-pass.
// ---------------------------------------------------------------------------
__global__ __launch_bounds__(NT, 1) void k_node(
        const float* __restrict__ h,
        const float* __restrict__ bU, const float* __restrict__ bV,
        const float* __restrict__ bA, const float* __restrict__ bB,
        int V, int nTiles) {
    extern __shared__ char sm[];
    uint32_t sb = smem_u32(sm);
    int tid = threadIdx.x, lane = tid & 31, wid = tid >> 5;
    int rm = (wid & 7) * 16, cn = (wid >> 3) * 64;
    int r_in = lane >> 2, c2 = 2 * (lane & 3);
    int widx = blockIdx.y;

    if (widx == 0) copy_B(0, sm + SM_B);
    else           copy_Bh(widx - 1, sm + SM_B);
    const float* bias;
    switch (widx) {
        case 0:  bias = bU; break;
        case 1:  bias = bV; break;
        case 2:  bias = bA; break;
        default: bias = bB; break;
    }
    float2 bv[8];
#pragma unroll
    for (int nf = 0; nf < 8; nf++) bv[nf] = *(const float2*)(bias + cn + nf * 8 + c2);

    int t = blockIdx.x;
    if (t >= nTiles) return;
    stage_A(sb, h, t * 128, V);
    CP_WAIT0(); __syncthreads();
    if (widx == 0) convert_plain(sm); else convert_plain_h(sm);
    __syncthreads();

    while (t < nTiles) {
        int nxt = t + gridDim.x;
        if (nxt < nTiles) stage_A(sb, h, nxt * 128, V);

        float C[8][4];
        if (widx == 0) gemm_compute(sb + SM_A, sb + SM_B, C);
        else           gemm_f16(sb + SM_A, sb + SM_B, C);

        int r0 = t * 128;
#pragma unroll
        for (int nf = 0; nf < 8; nf++) {
#pragma unroll
            for (int hf = 0; hf < 2; hf++) {
                int row = r0 + rm + hf * 8 + r_in;
                if (row < V) {
                    int col = cn + nf * 8 + c2;
                    float ox = C[nf][2 * hf] + bv[nf].x;
                    float oy = C[nf][2 * hf + 1] + bv[nf].y;
                    if (widx == 0) {
                        *(float2*)(g_agg + (size_t)row * 128 + col) = make_float2(ox, oy);
                    } else {
                        __half2 hv = __floats2half2_rn(ox, oy);
                        __half* dst;
                        if (widx == 1)      dst = g_colpack_h + (size_t)row * 256 + col;
                        else if (widx == 2) dst = g_colpack_h + (size_t)row * 256 + 128 + col;
                        else                dst = g_Bh_h + (size_t)row * 128 + col;
                        *(__half2*)dst = hv;
                    }
                }
            }
        }
        CP_WAIT0();
        __syncthreads();
        if (nxt < nTiles) { if (widx == 0) convert_plain(sm); else convert_plain_h(sm); }
        __syncthreads();
        t = nxt;
    }
}

// ---------------------------------------------------------------------------
// k_edge: 2 CTAs/SM, M=64, fp16 MMA, cp.async staged e, fp16 gathers
// ---------------------------------------------------------------------------
__global__ __launch_bounds__(256, 2) void k_edge(
        const float* __restrict__ e, const float* __restrict__ bC,
        const int* __restrict__ eidx, int E, int nTiles) {
    extern __shared__ char sm[];
    uint32_t sb = smem_u32(sm);
    int tid = threadIdx.x, lane = tid & 31, w = tid >> 5;

    copy_Bh256(3, sm + E_B);   // WC fp16
    float4 bc = *(const float4*)(bC + lane * 4);
    float ss[4] = {0.f, 0.f, 0.f, 0.f}, sq[4] = {0.f, 0.f, 0.f, 0.f};

    int p = 0;
    int t0 = blockIdx.x;
    if (t0 < nTiles) {
        load_idx64(sm, eidx, t0, E, 0);
        stage_A64(sb, e, t0 * 64, E);
    }
    __syncthreads();  // B + idx visible

    for (int t = t0; t < nTiles; t += gridDim.x, p ^= 1) {
        int e0 = t * 64;
        const int* rI = (const int*)(sm + E_IDX + p * 512);
        const int* cI = rI + 64;

        CP_WAIT0();
        __syncthreads();          // stage ready; prev epilogue done (C region free)
        convert64_h(sm);          // stage -> fp16 A

        // prefetch this tile's gather rows while A convert finishes / GEMM runs
#pragma unroll
        for (int i = tid; i < 640; i += 256) {
            int m = i & 63, sel = i >> 6;  // 0..9
            const char* ptr;
            if (sel < 4)      ptr = (const char*)g_colpack_h + (size_t)cI[m] * 512 + sel * 128;
            else if (sel < 6) ptr = (const char*)g_Bh_h + (size_t)rI[m] * 256 + (sel - 4) * 128;
            else              ptr = (const char*)g_agg + (size_t)rI[m] * 512 + (sel - 6) * 128;
            pf_l2(ptr);
        }
        __syncthreads();          // A ready

        int nxt = t + gridDim.x;
        if (nxt < nTiles) {
            stage_A64(sb, e, nxt * 64, E);
            load_idx64(sm, eidx, nxt, E, p ^ 1);
        }

        float C[8][4];
        gemm64_f16(sb + E_C, sb + E_B, C);
        __syncthreads();
        storeC64((float*)(sm + E_C), C);
        __syncthreads();

        const float* Cs = (const float*)(sm + E_C);
        int m0 = w * 8;

        float4 cc; uint2 vnu, ahu, bhu;
        float* agp_cur;
        {
            int m = m0;
            int rv = rI[m], cv = cI[m];
            const __half* cp = g_colpack_h + (size_t)cv * 256;
            agp_cur = g_agg + (size_t)rv * 128;
            cc  = *(const float4*)(Cs + m * CSTRIDE + lane * 4);
            vnu = *(const uint2*)(cp + lane * 4);
            ahu = *(const uint2*)(cp + 128 + lane * 4);
            bhu = *(const uint2*)(g_Bh_h + (size_t)rv * 128 + lane * 4);
        }
#pragma unroll
        for (int k = 0; k < 8; k++) {
            int m = m0 + k;
            int ei = e0 + m;
            float4 ccn; uint2 vnn, ahn, bhn;
            float* agp_nxt = agp_cur;
            if (k < 7) {
                int mn = m + 1;
                int rv = rI[mn], cv = cI[mn];
                const __half* cp = g_colpack_h + (size_t)cv * 256;
                agp_nxt = g_agg + (size_t)rv * 128;
                ccn = *(const float4*)(Cs + mn * CSTRIDE + lane * 4);
                vnn = *(const uint2*)(cp + lane * 4);
                ahn = *(const uint2*)(cp + 128 + lane * 4);
                bhn = *(const uint2*)(g_Bh_h + (size_t)rv * 128 + lane * 4);
            }
            if (ei < E) {
                float2 vn0 = h2f(vnu.x), vn1 = h2f(vnu.y);
                float2 ah0 = h2f(ahu.x), ah1 = h2f(ahu.y);
                float2 bh0 = h2f(bhu.x), bh1 = h2f(bhu.y);
                float4 x;
                x.x = cc.x + bc.x + ah0.x + bh0.x;
                x.y = cc.y + bc.y + ah0.y + bh0.y;
                x.z = cc.z + bc.z + ah1.x + bh1.x;
                x.w = cc.w + bc.w + ah1.y + bh1.y;
                uint2 u;
                u.x = hpack(x.x, x.y);
                u.y = hpack(x.z, x.w);
                *(uint2*)(g_epre + (size_t)ei * H + lane * 4) = u;
                float ga = vn0.x / (1.f + __expf(-x.x));
                float gb = vn0.y / (1.f + __expf(-x.y));
                float gc = vn1.x / (1.f + __expf(-x.z));
                float gd = vn1.y / (1.f + __expf(-x.w));
                redv4(agp_cur + lane * 4, ga, gb, gc, gd);
                ss[0] += x.x; ss[1] += x.y; ss[2] += x.z; ss[3] += x.w;
                sq[0] += x.x * x.x; sq[1] += x.y * x.y;
                sq[2] += x.z * x.z; sq[3] += x.w * x.w;
            }
            cc = ccn; vnu = vnn; ahu = ahn; bhu = bhn; agp_cur = agp_nxt;
        }
    }

    __syncthreads();
    float* sr = (float*)(sm + E_C);
    float* qr = sr + 1024;
    *(float4*)(sr + w * 128 + lane * 4) = make_float4(ss[0], ss[1], ss[2], ss[3]);
    *(float4*)(qr + w * 128 + lane * 4) = make_float4(sq[0], sq[1], sq[2], sq[3]);
    __syncthreads();
    if (tid < 128) {
        float a = 0.f, b = 0.f;
#pragma unroll
        for (int ww = 0; ww < 8; ww++) { a += sr[ww * 128 + tid]; b += qr[ww * 128 + tid]; }
        atomicAdd(&g_stats[2 * H + tid], a);
        atomicAdd(&g_stats[3 * H + tid], b);
    }
}

// ---------------------------------------------------------------------------
// k_edgeout: 512 thr persistent cp.async pipeline, fp16 MMA, fp16 epre
// ---------------------------------------------------------------------------
__global__ __launch_bounds__(NT, 1) void k_edgeout(
        const float* __restrict__ e, float* __restrict__ out, int E, int nTiles) {
    extern __shared__ char sm[];
    uint32_t sb = smem_u32(sm);
    int tid = threadIdx.x, lane = tid & 31, wid = tid >> 5;
    int rm = (wid & 7) * 16, cn = (wid >> 3) * 64;
    int r_in = lane >> 2, c2 = 2 * (lane & 3);

    copy_Bh(4, sm + SM_B);   // Wo fp16
    if (tid < 128) {
        ((float*)(sm + SM_SC))[tid] = g_scale_e[tid];
        ((float*)(sm + SM_SH))[tid] = g_shift_e[tid];
    }
    float2 cv2[8];
#pragma unroll
    for (int nf = 0; nf < 8; nf++) cv2[nf] = *(const float2*)(g_cvec + cn + nf * 8 + c2);

    int t = blockIdx.x;
    if (t >= nTiles) return;

    stage_A_h(sb, g_epre, t * 128, E);
    {
        int row = tid >> 2, part = (tid & 3) * 32;
        if (t * 128 + row < E) pf_l2(e + (size_t)(t * 128 + row) * H + part);
    }
    CP_WAIT0(); __syncthreads();
    convert_bn_h(sm);
    __syncthreads();

    while (t < nTiles) {
        int nxt = t + gridDim.x;
        if (nxt < nTiles) {
            stage_A_h(sb, g_epre, nxt * 128, E);
            int row = tid >> 2, part = (tid & 3) * 32;
            if (nxt * 128 + row < E) pf_l2(e + (size_t)(nxt * 128 + row) * H + part);
        }

        float C[8][4];
        gemm_f16(sb + SM_A, sb + SM_B, C);

        int e0 = t * 128;
#pragma unroll
        for (int nf = 0; nf < 8; nf++) {
#pragma unroll
            for (int hf = 0; hf < 2; hf++) {
                int ei = e0 + rm + hf * 8 + r_in;
                if (ei < E) {
                    int col = cn + nf * 8 + c2;
                    float2 ev = *(const float2*)(e + (size_t)ei * H + col);
                    float2 o = make_float2(ev.x + C[nf][2 * hf] + cv2[nf].x,
                                           ev.y + C[nf][2 * hf + 1] + cv2[nf].y);
                    *(float2*)(out + (size_t)ei * H + col) = o;
                }
            }
        }
        CP_WAIT0();
        __syncthreads();
        if (nxt < nTiles) convert_bn_h(sm);
        __syncthreads();
        t = nxt;
    }
}

// ---------------------------------------------------------------------------
__global__ void k_nstats(int rows) {
    int tid = threadIdx.x;
    int cg = tid & 31, wr = tid >> 5;
    float4 s = make_float4(0.f, 0.f, 0.f, 0.f);
    float4 qq = make_float4(0.f, 0.f, 0.f, 0.f);
    const float4* s4 = (const float4*)g_agg;
    for (int r = blockIdx.x * 8 + wr; r < rows; r += gridDim.x * 8) {
        float4 x = s4[(size_t)r * 32 + cg];
        s.x += x.x; s.y += x.y; s.z += x.z; s.w += x.w;
        qq.x += x.x * x.x; qq.y += x.y * x.y; qq.z += x.z * x.z; qq.w += x.w * x.w;
    }
    __shared__ float sh1[8][128], sh2[8][128];
    *(float4*)&sh1[wr][cg * 4] = s;
    *(float4*)&sh2[wr][cg * 4] = qq;
    __syncthreads();
    if (tid < 128) {
        float a = 0.f, b = 0.f;
#pragma unroll
        for (int ww = 0; ww < 8; ww++) { a += sh1[ww][tid]; b += sh2[ww][tid]; }
        atomicAdd(&g_stats[tid], a);
        atomicAdd(&g_stats[H + tid], b);
    }
}

// ---------------------------------------------------------------------------
__global__ void k_finalize(const float* __restrict__ gh, const float* __restrict__ bh,
                           const float* __restrict__ ge, const float* __restrict__ be,
                           int V, int E) {
    int j = threadIdx.x;
    float invV = 1.0f / (float)V, invE = 1.0f / (float)E;
    float mh = g_stats[j] * invV;
    float vh = g_stats[H + j] * invV - mh * mh;
    float sc = gh[j] * rsqrtf(vh + 1e-5f);
    g_scale_h[j] = sc;
    g_shift_h[j] = bh[j] - mh * sc;
    float me = g_stats[2 * H + j] * invE;
    float ve = g_stats[3 * H + j] * invE - me * me;
    float se = ge[j] * rsqrtf(ve + 1e-5f);
    g_scale_e[j] = se;
    g_shift_e[j] = be[j] - me * se;
}

// ---------------------------------------------------------------------------
__global__ void k_nodeout(const float* __restrict__ h, float* __restrict__ out, int V) {
    int idx = blockIdx.x * blockDim.x + threadIdx.x;
    int total = V * (H / 4);
    if (idx >= total) return;
    int j = (idx & 31) * 4;
    float4 a  = *(const float4*)&g_agg[(size_t)idx * 4];
    float4 sc = *(const float4*)&g_scale_h[j];
    float4 sh = *(const float4*)&g_shift_h[j];
    float4 hv = *(const float4*)&h[(size_t)idx * 4];
    float4 r;
    r.x = hv.x + fmaxf(fmaf(a.x, sc.x, sh.x), 0.f);
    r.y = hv.y + fmaxf(fmaf(a.y, sc.y, sh.y), 0.f);
    r.z = hv.z + fmaxf(fmaf(a.z, sc.z, sh.z), 0.f);
    r.w = hv.w + fmaxf(fmaf(a.w, sc.w, sh.w), 0.f);
    *(float4*)&out[(size_t)idx * 4] = r;
}

// ---------------------------------------------------------------------------
extern "C" void kernel_launch(void* const* d_in, const int* in_sizes, int n_in,
                              void* d_out, int out_size) {
    const float* h        = (const float*)d_in[0];
    const float* e        = (const float*)d_in[1];
    const float* time_emb = (const float*)d_in[2];
    const int*   eidx     = (const int*)d_in[3];
    const float* WU = (const float*)d_in[4];  const float* bU = (const float*)d_in[5];
    const float* WV = (const float*)d_in[6];  const float* bV = (const float*)d_in[7];
    const float* WA = (const float*)d_in[8];  const float* bA = (const float*)d_in[9];
    const float* WB = (const float*)d_in[10]; const float* bB = (const float*)d_in[11];
    const float* WC = (const float*)d_in[12]; const float* bC = (const float*)d_in[13];
    const float* Wt = (const float*)d_in[14]; const float* bt = (const float*)d_in[15];
    const float* Wo = (const float*)d_in[16]; const float* bo = (const float*)d_in[17];
    const float* gh = (const float*)d_in[18]; const float* bh = (const float*)d_in[19];
    const float* ge = (const float*)d_in[20]; const float* be = (const float*)d_in[21];

    int V = in_sizes[0] / H;
    int E = in_sizes[3] / 2;

    float* xout = (float*)d_out;
    float* eout = xout + (size_t)V * H;

    cudaFuncSetAttribute(k_node,    cudaFuncAttributeMaxDynamicSharedMemorySize, SMEM_BYTES);
    cudaFuncSetAttribute(k_edge,    cudaFuncAttributeMaxDynamicSharedMemorySize, E_SMEM);
    cudaFuncSetAttribute(k_edgeout, cudaFuncAttributeMaxDynamicSharedMemorySize, SMEM_BYTES);

    int vTiles   = (V + 127) / 128;
    int eTiles   = (E + 127) / 128;
    int eTiles64 = (E + 63) / 64;
    int gxNode = vTiles < 37 ? vTiles : 37;
    int gxE64 = eTiles64 < 296 ? eTiles64 : 296;
    int gxE = eTiles < 148 ? eTiles : 148;

    k_init<<<1, 128>>>(time_emb, Wt, bt, Wo, bo);
    k_prep<<<6, 256>>>(WU, WV, WA, WB, WC, Wo);
    k_node<<<dim3(gxNode, 4), NT, SMEM_BYTES>>>(h, bU, bV, bA, bB, V, vTiles);
    k_edge<<<gxE64, 256, E_SMEM>>>(e, bC, eidx, E, eTiles64);
    k_nstats<<<512, 256>>>(V);
    k_finalize<<<1, 128>>>(gh, bh, ge, be, V, E);
    k_nodeout<<<(V * (H / 4) + 255) / 256, 256>>>(h, xout, V);
    k_edgeout<<<gxE, NT, SMEM_BYTES>>>(e, eout, E, eTiles);
}

// round 15
// speedup vs baseline: 1.3490x; 1.0340x over previous
#include <cuda_runtime.h>
#include <cuda_bf16.h>
#include <cuda_fp16.h>
#include <cstdint>

// ---------------------------------------------------------------------------
// DAGCondGNNEncoder (sm_103 HMMA path).
// R15: k_edgeout rebuilt as 2-CTA/SM M=64 fp16 pipeline with direct fragment
//      epilogue (no SMEM C). k_edge/k_node unchanged from R14.
// ---------------------------------------------------------------------------

#define H 128
#define VMAX 50000
#define EMAX 625000
#define NT 512

// ---- device scratch ----
__device__ __align__(16) __half g_colpack_h[(size_t)VMAX * 256];  // [Vn|Ah] fp16
__device__ __align__(16) __half g_Bh_h[(size_t)VMAX * 128];       // Bh fp16
__device__ __align__(16) float  g_agg[(size_t)VMAX * 128];        // Uh + scatter
__device__ __align__(16) __half g_epre[(size_t)EMAX * H];         // fp16 e_pre
__device__ __align__(16) float g_stats[4 * H];
__device__ __align__(16) float g_cvec[H];
__device__ __align__(16) float g_scale_h[H];
__device__ __align__(16) float g_shift_h[H];
__device__ __align__(16) float g_scale_e[H];
__device__ __align__(16) float g_shift_e[H];
__device__ __align__(16) unsigned char g_Bimg[6 * 65536];   // split-bf16 hi/lo
__device__ __align__(16) unsigned char g_Bimg_h[5 * 32768]; // fp16: WV,WA,WB,WC,Wo

// ---- smem layout: k_node (512 thr) ----
#define SM_A     4096
#define CSTRIDE  132
#define SM_STAGE 71680
#define SM_B     137216
#define SMEM_BYTES 202752

// ---- smem layout: k_edge (2 CTAs/SM, 256 thr, M=64, fp16, staged) ----
#define E_IDX   0
#define E_C     2048         // A fp16 16KB / C fp32 33792 overlay
#define E_STG   36864        // raw fp32 stage 32KB
#define E_B     69632        // B fp16 32KB
#define E_SMEM  102400

// ---- smem layout: k_edgeout (2 CTAs/SM, 256 thr, M=64, fp16, staged) ----
#define EO_SC   0
#define EO_SH   512
#define EO_A    2048         // A fp16 16KB
#define EO_STG  18432        // epre fp16 stage 16KB
#define EO_B    34816        // B fp16 32KB
#define EO_SMEM 67584

// ---- helpers ----
__device__ __forceinline__ uint32_t smem_u32(const void* p) {
    uint32_t a;
    asm("{ .reg .u64 t; cvta.to.shared.u64 t, %1; cvt.u32.u64 %0, t; }" : "=r"(a) : "l"(p));
    return a;
}
__device__ __forceinline__ uint32_t bpack(float a, float b) {
    __nv_bfloat162 t = __floats2bfloat162_rn(a, b);
    return *reinterpret_cast<uint32_t*>(&t);
}
__device__ __forceinline__ float bres(float a) {
    __nv_bfloat16 hh = __float2bfloat16_rn(a);
    return a - __bfloat162float(hh);
}
__device__ __forceinline__ uint32_t hpack(float a, float b) {
    __half2 t = __floats2half2_rn(a, b);
    return *reinterpret_cast<uint32_t*>(&t);
}
__device__ __forceinline__ void storeA8(char* hiP, char* loP, uint32_t off, const float* v) {
    uint4 hv, lv;
    hv.x = bpack(v[0], v[1]); hv.y = bpack(v[2], v[3]);
    hv.z = bpack(v[4], v[5]); hv.w = bpack(v[6], v[7]);
    lv.x = bpack(bres(v[0]), bres(v[1])); lv.y = bpack(bres(v[2]), bres(v[3]));
    lv.z = bpack(bres(v[4]), bres(v[5])); lv.w = bpack(bres(v[6]), bres(v[7]));
    *(uint4*)(hiP + off) = hv;
    *(uint4*)(loP + off) = lv;
}
__device__ __forceinline__ void storeA8h(char* dst, uint32_t off, const float* v) {
    uint4 hv;
    hv.x = hpack(v[0], v[1]); hv.y = hpack(v[2], v[3]);
    hv.z = hpack(v[4], v[5]); hv.w = hpack(v[6], v[7]);
    *(uint4*)(dst + off) = hv;
}
__device__ __forceinline__ void ldsm4(uint32_t r[4], uint32_t addr) {
    asm volatile("ldmatrix.sync.aligned.m8n8.x4.shared.b16 {%0,%1,%2,%3}, [%4];"
        : "=r"(r[0]), "=r"(r[1]), "=r"(r[2]), "=r"(r[3]) : "r"(addr));
}
__device__ __forceinline__ void mma16816(float c[4], const uint32_t a[4], uint32_t b0, uint32_t b1) {
    asm volatile("mma.sync.aligned.m16n8k16.row.col.f32.bf16.bf16.f32 "
        "{%0,%1,%2,%3},{%4,%5,%6,%7},{%8,%9},{%0,%1,%2,%3};"
        : "+f"(c[0]), "+f"(c[1]), "+f"(c[2]), "+f"(c[3])
        : "r"(a[0]), "r"(a[1]), "r"(a[2]), "r"(a[3]), "r"(b0), "r"(b1));
}
__device__ __forceinline__ void mma16816h(float c[4], const uint32_t a[4], uint32_t b0, uint32_t b1) {
    asm volatile("mma.sync.aligned.m16n8k16.row.col.f32.f16.f16.f32 "
        "{%0,%1,%2,%3},{%4,%5,%6,%7},{%8,%9},{%0,%1,%2,%3};"
        : "+f"(c[0]), "+f"(c[1]), "+f"(c[2]), "+f"(c[3])
        : "r"(a[0]), "r"(a[1]), "r"(a[2]), "r"(a[3]), "r"(b0), "r"(b1));
}
__device__ __forceinline__ void redv4(float* p, float a, float b, float c, float d) {
    asm volatile("red.global.add.v4.f32 [%0], {%1, %2, %3, %4};"
        :: "l"(p), "f"(a), "f"(b), "f"(c), "f"(d) : "memory");
}
__device__ __forceinline__ void pf_l2(const void* p) {
    asm volatile("prefetch.global.L2 [%0];" :: "l"(p));
}
__device__ __forceinline__ void cpa16(uint32_t dst, const void* src, int pred) {
    asm volatile("{ .reg .pred p; setp.ne.b32 p, %2, 0;\n\t"
        "@p cp.async.cg.shared.global [%0], [%1], 16; }"
        :: "r"(dst), "l"(src), "r"(pred));
}
#define CP_COMMIT() asm volatile("cp.async.commit_group;" ::: "memory")
#define CP_WAIT0()  asm volatile("cp.async.wait_group 0;" ::: "memory")

// ---- GEMM core: 128x128 tile, 16 warps, split-bf16 (k_node Uh) ----
__device__ __forceinline__ void gemm_compute(uint32_t sAu, uint32_t sBu, float C[8][4]) {
    int tid = threadIdx.x, lane = tid & 31, wid = tid >> 5;
    int rm = (wid & 7) * 16, cn = (wid >> 3) * 64;
#pragma unroll
    for (int nf = 0; nf < 8; nf++)
#pragma unroll
        for (int q = 0; q < 4; q++) C[nf][q] = 0.f;

    int xr = lane & 7;
    int arow = xr + ((lane >> 3) & 1) * 8;
    int ahs = lane >> 4;
    int bhs = (lane >> 3) & 1;
    int bnr = xr + (lane >> 4) * 8;
    uint32_t aB = sAu + (uint32_t)(rm + arow) * 256;
    uint32_t bB[4];
#pragma unroll
    for (int g = 0; g < 4; g++) bB[g] = sBu + (uint32_t)(cn + g * 16 + bnr) * 256;

#pragma unroll
    for (int ks = 0; ks < 8; ks++) {
        uint32_t oA = (uint32_t)(((ks * 2 + ahs) ^ xr) << 4);
        uint32_t oB = (uint32_t)(((ks * 2 + bhs) ^ xr) << 4);
        uint32_t aH[4], aL[4];
        ldsm4(aH, aB + oA);
        ldsm4(aL, aB + 32768 + oA);
        uint32_t bH[4][4], bL[4][4];
#pragma unroll
        for (int g = 0; g < 4; g++) {
            ldsm4(bH[g], bB[g] + oB);
            ldsm4(bL[g], bB[g] + 32768 + oB);
        }
#pragma unroll
        for (int g = 0; g < 4; g++) {
            mma16816(C[2*g],   aH, bH[g][0], bH[g][1]);
            mma16816(C[2*g+1], aH, bH[g][2], bH[g][3]);
            mma16816(C[2*g],   aH, bL[g][0], bL[g][1]);
            mma16816(C[2*g+1], aH, bL[g][2], bL[g][3]);
            mma16816(C[2*g],   aL, bH[g][0], bH[g][1]);
            mma16816(C[2*g+1], aL, bH[g][2], bH[g][3]);
        }
    }
}

// ---- GEMM core: 128x128 tile, 16 warps, fp16 single-pass (k_node 1-3) ----
__device__ __forceinline__ void gemm_f16(uint32_t sAu, uint32_t sBu, float C[8][4]) {
    int tid = threadIdx.x, lane = tid & 31, wid = tid >> 5;
    int rm = (wid & 7) * 16, cn = (wid >> 3) * 64;
#pragma unroll
    for (int nf = 0; nf < 8; nf++)
#pragma unroll
        for (int q = 0; q < 4; q++) C[nf][q] = 0.f;

    int xr = lane & 7;
    int arow = xr + ((lane >> 3) & 1) * 8;
    int ahs = lane >> 4;
    int bhs = (lane >> 3) & 1;
    int bnr = xr + (lane >> 4) * 8;
    uint32_t aB = sAu + (uint32_t)(rm + arow) * 256;
    uint32_t bB[4];
#pragma unroll
    for (int g = 0; g < 4; g++) bB[g] = sBu + (uint32_t)(cn + g * 16 + bnr) * 256;

#pragma unroll
    for (int ks = 0; ks < 8; ks++) {
        uint32_t oA = (uint32_t)(((ks * 2 + ahs) ^ xr) << 4);
        uint32_t oB = (uint32_t)(((ks * 2 + bhs) ^ xr) << 4);
        uint32_t aH[4];
        ldsm4(aH, aB + oA);
        uint32_t bH[4][4];
#pragma unroll
        for (int g = 0; g < 4; g++) ldsm4(bH[g], bB[g] + oB);
#pragma unroll
        for (int g = 0; g < 4; g++) {
            mma16816h(C[2*g],   aH, bH[g][0], bH[g][1]);
            mma16816h(C[2*g+1], aH, bH[g][2], bH[g][3]);
        }
    }
}

// ---- GEMM core: 64x128 tile, 8 warps, fp16 single-pass ----
__device__ __forceinline__ void gemm64_f16(uint32_t sAu, uint32_t sBu, float C[8][4]) {
    int tid = threadIdx.x, lane = tid & 31, wid = tid >> 5;
    int rm = (wid & 3) * 16, cn = (wid >> 2) * 64;
#pragma unroll
    for (int nf = 0; nf < 8; nf++)
#pragma unroll
        for (int q = 0; q < 4; q++) C[nf][q] = 0.f;

    int xr = lane & 7;
    int arow = xr + ((lane >> 3) & 1) * 8;
    int ahs = lane >> 4;
    int bhs = (lane >> 3) & 1;
    int bnr = xr + (lane >> 4) * 8;
    uint32_t aB = sAu + (uint32_t)(rm + arow) * 256;
    uint32_t bB[4];
#pragma unroll
    for (int g = 0; g < 4; g++) bB[g] = sBu + (uint32_t)(cn + g * 16 + bnr) * 256;

#pragma unroll
    for (int ks = 0; ks < 8; ks++) {
        uint32_t oA = (uint32_t)(((ks * 2 + ahs) ^ xr) << 4);
        uint32_t oB = (uint32_t)(((ks * 2 + bhs) ^ xr) << 4);
        uint32_t aH[4];
        ldsm4(aH, aB + oA);
        uint32_t bH[4][4];
#pragma unroll
        for (int g = 0; g < 4; g++) ldsm4(bH[g], bB[g] + oB);
#pragma unroll
        for (int g = 0; g < 4; g++) {
            mma16816h(C[2*g],   aH, bH[g][0], bH[g][1]);
            mma16816h(C[2*g+1], aH, bH[g][2], bH[g][3]);
        }
    }
}

__device__ __forceinline__ void storeC64(float* Cs, float C[8][4]) {
    int tid = threadIdx.x, lane = tid & 31, wid = tid >> 5;
    int rm = (wid & 3) * 16, cn = (wid >> 2) * 64;
    int r = lane >> 2, c2 = 2 * (lane & 3);
#pragma unroll
    for (int nf = 0; nf < 8; nf++) {
        int col = cn + nf * 8 + c2;
        *(float2*)(Cs + (rm + r) * CSTRIDE + col)     = make_float2(C[nf][0], C[nf][1]);
        *(float2*)(Cs + (rm + r + 8) * CSTRIDE + col) = make_float2(C[nf][2], C[nf][3]);
    }
}

// ---- 512-thr pipeline pieces (k_node) ----
__device__ __forceinline__ void stage_A(uint32_t sb, const float* src, int r0, int limit) {
    int tid = threadIdx.x;
    uint32_t dst = sb + SM_STAGE;
#pragma unroll
    for (int it = 0; it < 8; it++) {
        int c = it * NT + tid;
        int row = c >> 5, part = c & 31;
        cpa16(dst + c * 16, src + (size_t)(r0 + row) * H + part * 4, (r0 + row) < limit);
    }
    CP_COMMIT();
}

__device__ __forceinline__ void convert_plain(char* sm) {
    const float* stg = (const float*)(sm + SM_STAGE);
    char* sA = sm + SM_A;
    int tid = threadIdx.x;
#pragma unroll
    for (int it = 0; it < 4; it++) {
        int s = it * NT + tid;
        int row = s >> 4, kseg = s & 15;
        const float4* p = (const float4*)(stg + row * 128 + kseg * 8);
        float4 f0 = p[0], f1 = p[1];
        float v[8] = {f0.x, f0.y, f0.z, f0.w, f1.x, f1.y, f1.z, f1.w};
        uint32_t off = (uint32_t)row * 256 + (uint32_t)((kseg ^ (row & 7)) << 4);
        storeA8(sA, sA + 32768, off, v);
    }
}

__device__ __forceinline__ void convert_plain_h(char* sm) {
    const float* stg = (const float*)(sm + SM_STAGE);
    char* sA = sm + SM_A;
    int tid = threadIdx.x;
#pragma unroll
    for (int it = 0; it < 4; it++) {
        int s = it * NT + tid;
        int row = s >> 4, kseg = s & 15;
        const float4* p = (const float4*)(stg + row * 128 + kseg * 8);
        float4 f0 = p[0], f1 = p[1];
        float v[8] = {f0.x, f0.y, f0.z, f0.w, f1.x, f1.y, f1.z, f1.w};
        uint32_t off = (uint32_t)row * 256 + (uint32_t)((kseg ^ (row & 7)) << 4);
        storeA8h(sA, off, v);
    }
}

__device__ __forceinline__ void copy_B(int widx, char* sB) {
    const uint4* g = (const uint4*)(g_Bimg + (size_t)widx * 65536);
    uint4* d = (uint4*)sB;
    int tid = threadIdx.x;
#pragma unroll
    for (int it = 0; it < 8; it++) d[it * NT + tid] = g[it * NT + tid];
}

__device__ __forceinline__ void copy_Bh(int hidx, char* sB) {
    const uint4* g = (const uint4*)(g_Bimg_h + (size_t)hidx * 32768);
    uint4* d = (uint4*)sB;
    int tid = threadIdx.x;
#pragma unroll
    for (int it = 0; it < 4; it++) d[it * NT + tid] = g[it * NT + tid];
}

// ---- 256-thr pieces ----
__device__ __forceinline__ void copy_Bh256(int hidx, char* sB) {
    const uint4* g = (const uint4*)(g_Bimg_h + (size_t)hidx * 32768);
    uint4* d = (uint4*)sB;
    int tid = threadIdx.x;
#pragma unroll
    for (int it = 0; it < 8; it++) d[it * 256 + tid] = g[it * 256 + tid];
}

// k_edge: stage 64 rows fp32 e (32KB)
__device__ __forceinline__ void stage_A64(uint32_t sb, const float* src, int r0, int limit) {
    int tid = threadIdx.x;
    uint32_t dst = sb + E_STG;
#pragma unroll
    for (int it = 0; it < 8; it++) {
        int c = it * 256 + tid;
        int row = c >> 5, part = c & 31;
        cpa16(dst + c * 16, src + (size_t)(r0 + row) * H + part * 4, (r0 + row) < limit);
    }
    CP_COMMIT();
}

__device__ __forceinline__ void convert64_h(char* sm) {
    const float* stg = (const float*)(sm + E_STG);
    char* sA = sm + E_C;
    int tid = threadIdx.x;
#pragma unroll
    for (int it = 0; it < 4; it++) {
        int s = it * 256 + tid;
        int row = s >> 4, kseg = s & 15;
        const float4* p = (const float4*)(stg + row * 128 + kseg * 8);
        float4 f0 = p[0], f1 = p[1];
        float v[8] = {f0.x, f0.y, f0.z, f0.w, f1.x, f1.y, f1.z, f1.w};
        uint32_t off = (uint32_t)row * 256 + (uint32_t)((kseg ^ (row & 7)) << 4);
        storeA8h(sA, off, v);
    }
}

__device__ __forceinline__ void load_idx64(char* sm, const int* eidx, int t, int E, int p) {
    int tid = threadIdx.x;
    int e0 = t * 64;
    int* rI = (int*)(sm + E_IDX + p * 512);
    if (tid < 64) {
        int ei = e0 + tid;
        rI[tid] = (ei < E) ? eidx[ei] : 0;
    } else if (tid < 128) {
        int q = tid - 64, ei = e0 + q;
        rI[64 + q] = (ei < E) ? eidx[(size_t)E + ei] : 0;
    }
}

// k_edgeout: stage 64 rows fp16 epre (16KB)
__device__ __forceinline__ void stage64_h(uint32_t sb, const __half* src, int r0, int limit) {
    int tid = threadIdx.x;
    uint32_t dst = sb + EO_STG;
#pragma unroll
    for (int it = 0; it < 4; it++) {
        int c = it * 256 + tid;
        int row = c >> 4, part = c & 15;
        cpa16(dst + c * 16, src + (size_t)(r0 + row) * H + part * 8, (r0 + row) < limit);
    }
    CP_COMMIT();
}

// fp16 stage -> BN+relu -> fp16 A (64 rows, k_edgeout)
__device__ __forceinline__ void convert_bn64(char* sm) {
    const __half* stg = (const __half*)(sm + EO_STG);
    const float4* sc4 = (const float4*)(sm + EO_SC);
    const float4* sh4 = (const float4*)(sm + EO_SH);
    char* sA = sm + EO_A;
    int tid = threadIdx.x;
#pragma unroll
    for (int it = 0; it < 4; it++) {
        int s = it * 256 + tid;
        int row = s >> 4, kseg = s & 15;
        const __half2* p = (const __half2*)(stg + row * 128 + kseg * 8);
        float2 a0 = __half22float2(p[0]);
        float2 a1 = __half22float2(p[1]);
        float2 a2 = __half22float2(p[2]);
        float2 a3 = __half22float2(p[3]);
        float4 s0 = sc4[kseg * 2], s1 = sc4[kseg * 2 + 1];
        float4 t0 = sh4[kseg * 2], t1 = sh4[kseg * 2 + 1];
        float v[8];
        v[0] = fmaxf(fmaf(a0.x, s0.x, t0.x), 0.f);
        v[1] = fmaxf(fmaf(a0.y, s0.y, t0.y), 0.f);
        v[2] = fmaxf(fmaf(a1.x, s0.z, t0.z), 0.f);
        v[3] = fmaxf(fmaf(a1.y, s0.w, t0.w), 0.f);
        v[4] = fmaxf(fmaf(a2.x, s1.x, t1.x), 0.f);
        v[5] = fmaxf(fmaf(a2.y, s1.y, t1.y), 0.f);
        v[6] = fmaxf(fmaf(a3.x, s1.z, t1.z), 0.f);
        v[7] = fmaxf(fmaf(a3.y, s1.w, t1.w), 0.f);
        uint32_t off = (uint32_t)row * 256 + (uint32_t)((kseg ^ (row & 7)) << 4);
        storeA8h(sA, off, v);
    }
}

__device__ __forceinline__ float2 h2f(uint32_t u) {
    __half2 h = *reinterpret_cast<__half2*>(&u);
    return __half22float2(h);
}

// ---------------------------------------------------------------------------
__global__ void k_init(const float* __restrict__ time_emb,
                       const float* __restrict__ Wt, const float* __restrict__ bt,
                       const float* __restrict__ Wo, const float* __restrict__ bo) {
    int j = threadIdx.x;
    for (int i = j; i < 4 * H; i += H) g_stats[i] = 0.0f;
    __shared__ float tv[H];
    float acc = bt[j];
    for (int k = 0; k < H; k++) acc += time_emb[k] * Wt[k * H + j];
    tv[j] = acc;
    __syncthreads();
    float c = bo[j];
    for (int k = 0; k < H; k++) c += tv[k] * Wo[k * H + j];
    g_cvec[j] = c;
}

// ---------------------------------------------------------------------------
__global__ void k_prep(const float* __restrict__ WU, const float* __restrict__ WV,
                       const float* __restrict__ WA, const float* __restrict__ WB,
                       const float* __restrict__ WC, const float* __restrict__ Wo) {
    const float* Ws[6] = {WU, WV, WA, WB, WC, Wo};
    const float* W = Ws[blockIdx.x];
    unsigned char* img = g_Bimg + (size_t)blockIdx.x * 65536;
    unsigned char* imgh = (blockIdx.x >= 1) ? g_Bimg_h + (size_t)(blockIdx.x - 1) * 32768 : nullptr;
    int tid = threadIdx.x;
    for (int it = 0; it < 64; it++) {
        int idx = it * 256 + tid;
        int k = idx >> 7, n = idx & 127;
        float v = W[k * H + n];
        __nv_bfloat16 hi = __float2bfloat16_rn(v);
        __nv_bfloat16 lo = __float2bfloat16_rn(v - __bfloat162float(hi));
        uint32_t off = (uint32_t)n * 256 + (uint32_t)((((k >> 3) ^ (n & 7))) << 4) + (k & 7) * 2;
        *(__nv_bfloat16*)(img + off) = hi;
        *(__nv_bfloat16*)(img + 32768 + off) = lo;
        if (imgh) *(__half*)(imgh + off) = __float2half_rn(v);
    }
}

// ---------------------------------------------------------------------------
// k_node: persistent. widx 0 (Uh) split-bf16; widx 1-3 fp16 single-pass.
// ---------------------------------------------------------------------------
__global__ __launch_bounds__(NT, 1) void k_node(
        const float* __restrict__ h,
        const float* __restrict__ bU, const float* __restrict__ bV,
        const float* __restrict__ bA, const float* __restrict__ bB,
        int V, int nTiles) {
    extern __shared__ char sm[];
    uint32_t sb = smem_u32(sm);
    int tid = threadIdx.x, lane = tid & 31, wid = tid >> 5;
    int rm = (wid & 7) * 16, cn = (wid >> 3) * 64;
    int r_in = lane >> 2, c2 = 2 * (lane & 3);
    int widx = blockIdx.y;

    if (widx == 0) copy_B(0, sm + SM_B);
    else           copy_Bh(widx - 1, sm + SM_B);
    const float* bias;
    switch (widx) {
        case 0:  bias = bU; break;
        case 1:  bias = bV; break;
        case 2:  bias = bA; break;
        default: bias = bB; break;
    }
    float2 bv[8];
#pragma unroll
    for (int nf = 0; nf < 8; nf++) bv[nf] = *(const float2*)(bias + cn + nf * 8 + c2);

    int t = blockIdx.x;
    if (t >= nTiles) return;
    stage_A(sb, h, t * 128, V);
    CP_WAIT0(); __syncthreads();
    if (widx == 0) convert_plain(sm); else convert_plain_h(sm);
    __syncthreads();

    while (t < nTiles) {
        int nxt = t + gridDim.x;
        if (nxt < nTiles) stage_A(sb, h, nxt * 128, V);

        float C[8][4];
        if (widx == 0) gemm_compute(sb + SM_A, sb + SM_B, C);
        else           gemm_f16(sb + SM_A, sb + SM_B, C);

        int r0 = t * 128;
#pragma unroll
        for (int nf = 0; nf < 8; nf++) {
#pragma unroll
            for (int hf = 0; hf < 2; hf++) {
                int row = r0 + rm + hf * 8 + r_in;
                if (row < V) {
                    int col = cn + nf * 8 + c2;
                    float ox = C[nf][2 * hf] + bv[nf].x;
                    float oy = C[nf][2 * hf + 1] + bv[nf].y;
                    if (widx == 0) {
                        *(float2*)(g_agg + (size_t)row * 128 + col) = make_float2(ox, oy);
                    } else {
                        __half2 hv = __floats2half2_rn(ox, oy);
                        __half* dst;
                        if (widx == 1)      dst = g_colpack_h + (size_t)row * 256 + col;
                        else if (widx == 2) dst = g_colpack_h + (size_t)row * 256 + 128 + col;
                        else                dst = g_Bh_h + (size_t)row * 128 + col;
                        *(__half2*)dst = hv;
                    }
                }
            }
        }
        CP_WAIT0();
        __syncthreads();
        if (nxt < nTiles) { if (widx == 0) convert_plain(sm); else convert_plain_h(sm); }
        __syncthreads();
        t = nxt;
    }
}

// ---------------------------------------------------------------------------
// k_edge: 2 CTAs/SM, M=64, fp16 MMA, cp.async staged e, fp16 gathers (R14)
// ---------------------------------------------------------------------------
__global__ __launch_bounds__(256, 2) void k_edge(
        const float* __restrict__ e, const float* __restrict__ bC,
        const int* __restrict__ eidx, int E, int nTiles) {
    extern __shared__ char sm[];
    uint32_t sb = smem_u32(sm);
    int tid = threadIdx.x, lane = tid & 31, w = tid >> 5;

    copy_Bh256(3, sm + E_B);   // WC fp16
    float4 bc = *(const float4*)(bC + lane * 4);
    float ss[4] = {0.f, 0.f, 0.f, 0.f}, sq[4] = {0.f, 0.f, 0.f, 0.f};

    int p = 0;
    int t0 = blockIdx.x;
    if (t0 < nTiles) {
        load_idx64(sm, eidx, t0, E, 0);
        stage_A64(sb, e, t0 * 64, E);
    }
    __syncthreads();

    for (int t = t0; t < nTiles; t += gridDim.x, p ^= 1) {
        int e0 = t * 64;
        const int* rI = (const int*)(sm + E_IDX + p * 512);
        const int* cI = rI + 64;

        CP_WAIT0();
        __syncthreads();
        convert64_h(sm);

#pragma unroll
        for (int i = tid; i < 640; i += 256) {
            int m = i & 63, sel = i >> 6;
            const char* ptr;
            if (sel < 4)      ptr = (const char*)g_colpack_h + (size_t)cI[m] * 512 + sel * 128;
            else if (sel < 6) ptr = (const char*)g_Bh_h + (size_t)rI[m] * 256 + (sel - 4) * 128;
            else              ptr = (const char*)g_agg + (size_t)rI[m] * 512 + (sel - 6) * 128;
            pf_l2(ptr);
        }
        __syncthreads();

        int nxt = t + gridDim.x;
        if (nxt < nTiles) {
            stage_A64(sb, e, nxt * 64, E);
            load_idx64(sm, eidx, nxt, E, p ^ 1);
        }

        float C[8][4];
        gemm64_f16(sb + E_C, sb + E_B, C);
        __syncthreads();
        storeC64((float*)(sm + E_C), C);
        __syncthreads();

        const float* Cs = (const float*)(sm + E_C);
        int m0 = w * 8;

        float4 cc; uint2 vnu, ahu, bhu;
        float* agp_cur;
        {
            int m = m0;
            int rv = rI[m], cv = cI[m];
            const __half* cp = g_colpack_h + (size_t)cv * 256;
            agp_cur = g_agg + (size_t)rv * 128;
            cc  = *(const float4*)(Cs + m * CSTRIDE + lane * 4);
            vnu = *(const uint2*)(cp + lane * 4);
            ahu = *(const uint2*)(cp + 128 + lane * 4);
            bhu = *(const uint2*)(g_Bh_h + (size_t)rv * 128 + lane * 4);
        }
#pragma unroll
        for (int k = 0; k < 8; k++) {
            int m = m0 + k;
            int ei = e0 + m;
            float4 ccn; uint2 vnn, ahn, bhn;
            float* agp_nxt = agp_cur;
            if (k < 7) {
                int mn = m + 1;
                int rv = rI[mn], cv = cI[mn];
                const __half* cp = g_colpack_h + (size_t)cv * 256;
                agp_nxt = g_agg + (size_t)rv * 128;
                ccn = *(const float4*)(Cs + mn * CSTRIDE + lane * 4);
                vnn = *(const uint2*)(cp + lane * 4);
                ahn = *(const uint2*)(cp + 128 + lane * 4);
                bhn = *(const uint2*)(g_Bh_h + (size_t)rv * 128 + lane * 4);
            }
            if (ei < E) {
                float2 vn0 = h2f(vnu.x), vn1 = h2f(vnu.y);
                float2 ah0 = h2f(ahu.x), ah1 = h2f(ahu.y);
                float2 bh0 = h2f(bhu.x), bh1 = h2f(bhu.y);
                float4 x;
                x.x = cc.x + bc.x + ah0.x + bh0.x;
                x.y = cc.y + bc.y + ah0.y + bh0.y;
                x.z = cc.z + bc.z + ah1.x + bh1.x;
                x.w = cc.w + bc.w + ah1.y + bh1.y;
                uint2 u;
                u.x = hpack(x.x, x.y);
                u.y = hpack(x.z, x.w);
                *(uint2*)(g_epre + (size_t)ei * H + lane * 4) = u;
                float ga = vn0.x / (1.f + __expf(-x.x));
                float gb = vn0.y / (1.f + __expf(-x.y));
                float gc = vn1.x / (1.f + __expf(-x.z));
                float gd = vn1.y / (1.f + __expf(-x.w));
                redv4(agp_cur + lane * 4, ga, gb, gc, gd);
                ss[0] += x.x; ss[1] += x.y; ss[2] += x.z; ss[3] += x.w;
                sq[0] += x.x * x.x; sq[1] += x.y * x.y;
                sq[2] += x.z * x.z; sq[3] += x.w * x.w;
            }
            cc = ccn; vnu = vnn; ahu = ahn; bhu = bhn; agp_cur = agp_nxt;
        }
    }

    __syncthreads();
    float* sr = (float*)(sm + E_C);
    float* qr = sr + 1024;
    *(float4*)(sr + w * 128 + lane * 4) = make_float4(ss[0], ss[1], ss[2], ss[3]);
    *(float4*)(qr + w * 128 + lane * 4) = make_float4(sq[0], sq[1], sq[2], sq[3]);
    __syncthreads();
    if (tid < 128) {
        float a = 0.f, b = 0.f;
#pragma unroll
        for (int ww = 0; ww < 8; ww++) { a += sr[ww * 128 + tid]; b += qr[ww * 128 + tid]; }
        atomicAdd(&g_stats[2 * H + tid], a);
        atomicAdd(&g_stats[3 * H + tid], b);
    }
}

// ---------------------------------------------------------------------------
// k_edgeout: 2 CTAs/SM, M=64, fp16 MMA, staged fp16 epre, direct fragment
//            epilogue (no SMEM C, no stats).
// ---------------------------------------------------------------------------
__global__ __launch_bounds__(256, 2) void k_edgeout(
        const float* __restrict__ e, float* __restrict__ out, int E, int nTiles) {
    extern __shared__ char sm[];
    uint32_t sb = smem_u32(sm);
    int tid = threadIdx.x, lane = tid & 31, wid = tid >> 5;
    int rm = (wid & 3) * 16, cn = (wid >> 2) * 64;
    int r_in = lane >> 2, c2 = 2 * (lane & 3);

    copy_Bh256(4, sm + EO_B);   // Wo fp16
    if (tid < 128) {
        ((float*)(sm + EO_SC))[tid] = g_scale_e[tid];
        ((float*)(sm + EO_SH))[tid] = g_shift_e[tid];
    }
    float2 cv2[8];
#pragma unroll
    for (int nf = 0; nf < 8; nf++) cv2[nf] = *(const float2*)(g_cvec + cn + nf * 8 + c2);

    int t0 = blockIdx.x;
    if (t0 < nTiles) stage64_h(sb, g_epre, t0 * 64, E);
    __syncthreads();  // B + scale/shift visible

    for (int t = t0; t < nTiles; t += gridDim.x) {
        int e0 = t * 64;
        CP_WAIT0();
        __syncthreads();          // stage ready; A free (prev gemm done)
        convert_bn64(sm);
        // prefetch this tile's e rows (residual read in epilogue)
        {
            int row = tid >> 2, part = (tid & 3) * 32;
            if (e0 + row < E) pf_l2(e + (size_t)(e0 + row) * H + part);
        }
        __syncthreads();          // A ready

        int nxt = t + gridDim.x;
        if (nxt < nTiles) stage64_h(sb, g_epre, nxt * 64, E);

        float C[8][4];
        gemm64_f16(sb + EO_A, sb + EO_B, C);

#pragma unroll
        for (int nf = 0; nf < 8; nf++) {
#pragma unroll
            for (int hf = 0; hf < 2; hf++) {
                int ei = e0 + rm + hf * 8 + r_in;
                if (ei < E) {
                    int col = cn + nf * 8 + c2;
                    float2 ev = *(const float2*)(e + (size_t)ei * H + col);
                    float2 o = make_float2(ev.x + C[nf][2 * hf] + cv2[nf].x,
                                           ev.y + C[nf][2 * hf + 1] + cv2[nf].y);
                    *(float2*)(out + (size_t)ei * H + col) = o;
                }
            }
        }
    }
}

// ---------------------------------------------------------------------------
__global__ void k_nstats(int rows) {
    int tid = threadIdx.x;
    int cg = tid & 31, wr = tid >> 5;
    float4 s = make_float4(0.f, 0.f, 0.f, 0.f);
    float4 qq = make_float4(0.f, 0.f, 0.f, 0.f);
    const float4* s4 = (const float4*)g_agg;
    for (int r = blockIdx.x * 8 + wr; r < rows; r += gridDim.x * 8) {
        float4 x = s4[(size_t)r * 32 + cg];
        s.x += x.x; s.y += x.y; s.z += x.z; s.w += x.w;
        qq.x += x.x * x.x; qq.y += x.y * x.y; qq.z += x.z * x.z; qq.w += x.w * x.w;
    }
    __shared__ float sh1[8][128], sh2[8][128];
    *(float4*)&sh1[wr][cg * 4] = s;
    *(float4*)&sh2[wr][cg * 4] = qq;
    __syncthreads();
    if (tid < 128) {
        float a = 0.f, b = 0.f;
#pragma unroll
        for (int ww = 0; ww < 8; ww++) { a += sh1[ww][tid]; b += sh2[ww][tid]; }
        atomicAdd(&g_stats[tid], a);
        atomicAdd(&g_stats[H + tid], b);
    }
}

// ---------------------------------------------------------------------------
__global__ void k_finalize(const float* __restrict__ gh, const float* __restrict__ bh,
                           const float* __restrict__ ge, const float* __restrict__ be,
                           int V, int E) {
    int j = threadIdx.x;
    float invV = 1.0f / (float)V, invE = 1.0f / (float)E;
    float mh = g_stats[j] * invV;
    float vh = g_stats[H + j] * invV - mh * mh;
    float sc = gh[j] * rsqrtf(vh + 1e-5f);
    g_scale_h[j] = sc;
    g_shift_h[j] = bh[j] - mh * sc;
    float me = g_stats[2 * H + j] * invE;
    float ve = g_stats[3 * H + j] * invE - me * me;
    float se = ge[j] * rsqrtf(ve + 1e-5f);
    g_scale_e[j] = se;
    g_shift_e[j] = be[j] - me * se;
}

// ---------------------------------------------------------------------------
__global__ void k_nodeout(const float* __restrict__ h, float* __restrict__ out, int V) {
    int idx = blockIdx.x * blockDim.x + threadIdx.x;
    int total = V * (H / 4);
    if (idx >= total) return;
    int j = (idx & 31) * 4;
    float4 a  = *(const float4*)&g_agg[(size_t)idx * 4];
    float4 sc = *(const float4*)&g_scale_h[j];
    float4 sh = *(const float4*)&g_shift_h[j];
    float4 hv = *(const float4*)&h[(size_t)idx * 4];
    float4 r;
    r.x = hv.x + fmaxf(fmaf(a.x, sc.x, sh.x), 0.f);
    r.y = hv.y + fmaxf(fmaf(a.y, sc.y, sh.y), 0.f);
    r.z = hv.z + fmaxf(fmaf(a.z, sc.z, sh.z), 0.f);
    r.w = hv.w + fmaxf(fmaf(a.w, sc.w, sh.w), 0.f);
    *(float4*)&out[(size_t)idx * 4] = r;
}

// ---------------------------------------------------------------------------
extern "C" void kernel_launch(void* const* d_in, const int* in_sizes, int n_in,
                              void* d_out, int out_size) {
    const float* h        = (const float*)d_in[0];
    const float* e        = (const float*)d_in[1];
    const float* time_emb = (const float*)d_in[2];
    const int*   eidx     = (const int*)d_in[3];
    const float* WU = (const float*)d_in[4];  const float* bU = (const float*)d_in[5];
    const float* WV = (const float*)d_in[6];  const float* bV = (const float*)d_in[7];
    const float* WA = (const float*)d_in[8];  const float* bA = (const float*)d_in[9];
    const float* WB = (const float*)d_in[10]; const float* bB = (const float*)d_in[11];
    const float* WC = (const float*)d_in[12]; const float* bC = (const float*)d_in[13];
    const float* Wt = (const float*)d_in[14]; const float* bt = (const float*)d_in[15];
    const float* Wo = (const float*)d_in[16]; const float* bo = (const float*)d_in[17];
    const float* gh = (const float*)d_in[18]; const float* bh = (const float*)d_in[19];
    const float* ge = (const float*)d_in[20]; const float* be = (const float*)d_in[21];

    int V = in_sizes[0] / H;
    int E = in_sizes[3] / 2;

    float* xout = (float*)d_out;
    float* eout = xout + (size_t)V * H;

    cudaFuncSetAttribute(k_node,    cudaFuncAttributeMaxDynamicSharedMemorySize, SMEM_BYTES);
    cudaFuncSetAttribute(k_edge,    cudaFuncAttributeMaxDynamicSharedMemorySize, E_SMEM);
    cudaFuncSetAttribute(k_edgeout, cudaFuncAttributeMaxDynamicSharedMemorySize, EO_SMEM);

    int vTiles   = (V + 127) / 128;
    int eTiles64 = (E + 63) / 64;
    int gxNode = vTiles < 37 ? vTiles : 37;
    int gxE64 = eTiles64 < 296 ? eTiles64 : 296;

    k_init<<<1, 128>>>(time_emb, Wt, bt, Wo, bo);
    k_prep<<<6, 256>>>(WU, WV, WA, WB, WC, Wo);
    k_node<<<dim3(gxNode, 4), NT, SMEM_BYTES>>>(h, bU, bV, bA, bB, V, vTiles);
    k_edge<<<gxE64, 256, E_SMEM>>>(e, bC, eidx, E, eTiles64);
    k_nstats<<<512, 256>>>(V);
    k_finalize<<<1, 128>>>(gh, bh, ge, be, V, E);
    k_nodeout<<<(V * (H / 4) + 255) / 256, 256>>>(h, xout, V);
    k_edgeout<<<gxE64, 256, EO_SMEM>>>(e, eout, E, eTiles64);
}

// round 16
// speedup vs baseline: 1.4953x; 1.1085x over previous
#include <cuda_runtime.h>
#include <cuda_bf16.h>
#include <cuda_fp16.h>
#include <cstdint>

// ---------------------------------------------------------------------------
// DAGCondGNNEncoder (sm_103 HMMA path).
// R16: k_node split into k_nodeU (Uh, split-bf16) + k_nodeVAB (Vn/Ah/Bh fused:
//      one h read, 3 fp16 GEMMs vs 3 resident B images). k_prep widened.
//      k_edge / k_edgeout unchanged from R15.
// ---------------------------------------------------------------------------

#define H 128
#define VMAX 50000
#define EMAX 625000
#define NT 512

// ---- device scratch ----
__device__ __align__(16) __half g_colpack_h[(size_t)VMAX * 256];  // [Vn|Ah] fp16
__device__ __align__(16) __half g_Bh_h[(size_t)VMAX * 128];       // Bh fp16
__device__ __align__(16) float  g_agg[(size_t)VMAX * 128];        // Uh + scatter
__device__ __align__(16) __half g_epre[(size_t)EMAX * H];         // fp16 e_pre
__device__ __align__(16) float g_stats[4 * H];
__device__ __align__(16) float g_cvec[H];
__device__ __align__(16) float g_scale_h[H];
__device__ __align__(16) float g_shift_h[H];
__device__ __align__(16) float g_scale_e[H];
__device__ __align__(16) float g_shift_e[H];
__device__ __align__(16) unsigned char g_Bimg[65536];       // split-bf16 WU only
__device__ __align__(16) unsigned char g_Bimg_h[5 * 32768]; // fp16: WV,WA,WB,WC,Wo

// ---- smem layout: k_nodeU (512 thr, split-bf16, M=128) ----
#define SM_A     4096
#define CSTRIDE  132
#define SM_STAGE 71680
#define SM_B     137216
#define SMEM_BYTES 202752

// ---- smem layout: k_nodeVAB (512 thr, fp16, M=128, 3 Bs) ----
#define NV_A    4096          // fp16 A 32KB
#define NV_STG  36864         // fp32 stage 64KB
#define NV_B    102400        // 3 x 32KB fp16 B
#define NV_SMEM 200704

// ---- smem layout: k_edge (2 CTAs/SM, 256 thr, M=64, fp16, staged) ----
#define E_IDX   0
#define E_C     2048          // A fp16 16KB / C fp32 33792 overlay
#define E_STG   36864         // raw fp32 stage 32KB
#define E_B     69632         // B fp16 32KB
#define E_SMEM  102400

// ---- smem layout: k_edgeout (2 CTAs/SM, 256 thr, M=64, fp16, staged) ----
#define EO_SC   0
#define EO_SH   512
#define EO_A    2048
#define EO_STG  18432
#define EO_B    34816
#define EO_SMEM 67584

// ---- helpers ----
__device__ __forceinline__ uint32_t smem_u32(const void* p) {
    uint32_t a;
    asm("{ .reg .u64 t; cvta.to.shared.u64 t, %1; cvt.u32.u64 %0, t; }" : "=r"(a) : "l"(p));
    return a;
}
__device__ __forceinline__ uint32_t bpack(float a, float b) {
    __nv_bfloat162 t = __floats2bfloat162_rn(a, b);
    return *reinterpret_cast<uint32_t*>(&t);
}
__device__ __forceinline__ float bres(float a) {
    __nv_bfloat16 hh = __float2bfloat16_rn(a);
    return a - __bfloat162float(hh);
}
__device__ __forceinline__ uint32_t hpack(float a, float b) {
    __half2 t = __floats2half2_rn(a, b);
    return *reinterpret_cast<uint32_t*>(&t);
}
__device__ __forceinline__ void storeA8(char* hiP, char* loP, uint32_t off, const float* v) {
    uint4 hv, lv;
    hv.x = bpack(v[0], v[1]); hv.y = bpack(v[2], v[3]);
    hv.z = bpack(v[4], v[5]); hv.w = bpack(v[6], v[7]);
    lv.x = bpack(bres(v[0]), bres(v[1])); lv.y = bpack(bres(v[2]), bres(v[3]));
    lv.z = bpack(bres(v[4]), bres(v[5])); lv.w = bpack(bres(v[6]), bres(v[7]));
    *(uint4*)(hiP + off) = hv;
    *(uint4*)(loP + off) = lv;
}
__device__ __forceinline__ void storeA8h(char* dst, uint32_t off, const float* v) {
    uint4 hv;
    hv.x = hpack(v[0], v[1]); hv.y = hpack(v[2], v[3]);
    hv.z = hpack(v[4], v[5]); hv.w = hpack(v[6], v[7]);
    *(uint4*)(dst + off) = hv;
}
__device__ __forceinline__ void ldsm4(uint32_t r[4], uint32_t addr) {
    asm volatile("ldmatrix.sync.aligned.m8n8.x4.shared.b16 {%0,%1,%2,%3}, [%4];"
        : "=r"(r[0]), "=r"(r[1]), "=r"(r[2]), "=r"(r[3]) : "r"(addr));
}
__device__ __forceinline__ void mma16816(float c[4], const uint32_t a[4], uint32_t b0, uint32_t b1) {
    asm volatile("mma.sync.aligned.m16n8k16.row.col.f32.bf16.bf16.f32 "
        "{%0,%1,%2,%3},{%4,%5,%6,%7},{%8,%9},{%0,%1,%2,%3};"
        : "+f"(c[0]), "+f"(c[1]), "+f"(c[2]), "+f"(c[3])
        : "r"(a[0]), "r"(a[1]), "r"(a[2]), "r"(a[3]), "r"(b0), "r"(b1));
}
__device__ __forceinline__ void mma16816h(float c[4], const uint32_t a[4], uint32_t b0, uint32_t b1) {
    asm volatile("mma.sync.aligned.m16n8k16.row.col.f32.f16.f16.f32 "
        "{%0,%1,%2,%3},{%4,%5,%6,%7},{%8,%9},{%0,%1,%2,%3};"
        : "+f"(c[0]), "+f"(c[1]), "+f"(c[2]), "+f"(c[3])
        : "r"(a[0]), "r"(a[1]), "r"(a[2]), "r"(a[3]), "r"(b0), "r"(b1));
}
__device__ __forceinline__ void redv4(float* p, float a, float b, float c, float d) {
    asm volatile("red.global.add.v4.f32 [%0], {%1, %2, %3, %4};"
        :: "l"(p), "f"(a), "f"(b), "f"(c), "f"(d) : "memory");
}
__device__ __forceinline__ void pf_l2(const void* p) {
    asm volatile("prefetch.global.L2 [%0];" :: "l"(p));
}
__device__ __forceinline__ void cpa16(uint32_t dst, const void* src, int pred) {
    asm volatile("{ .reg .pred p; setp.ne.b32 p, %2, 0;\n\t"
        "@p cp.async.cg.shared.global [%0], [%1], 16; }"
        :: "r"(dst), "l"(src), "r"(pred));
}
#define CP_COMMIT() asm volatile("cp.async.commit_group;" ::: "memory")
#define CP_WAIT0()  asm volatile("cp.async.wait_group 0;" ::: "memory")

// ---- GEMM core: 128x128, 16 warps, split-bf16 (k_nodeU) ----
__device__ __forceinline__ void gemm_compute(uint32_t sAu, uint32_t sBu, float C[8][4]) {
    int tid = threadIdx.x, lane = tid & 31, wid = tid >> 5;
    int rm = (wid & 7) * 16, cn = (wid >> 3) * 64;
#pragma unroll
    for (int nf = 0; nf < 8; nf++)
#pragma unroll
        for (int q = 0; q < 4; q++) C[nf][q] = 0.f;

    int xr = lane & 7;
    int arow = xr + ((lane >> 3) & 1) * 8;
    int ahs = lane >> 4;
    int bhs = (lane >> 3) & 1;
    int bnr = xr + (lane >> 4) * 8;
    uint32_t aB = sAu + (uint32_t)(rm + arow) * 256;
    uint32_t bB[4];
#pragma unroll
    for (int g = 0; g < 4; g++) bB[g] = sBu + (uint32_t)(cn + g * 16 + bnr) * 256;

#pragma unroll
    for (int ks = 0; ks < 8; ks++) {
        uint32_t oA = (uint32_t)(((ks * 2 + ahs) ^ xr) << 4);
        uint32_t oB = (uint32_t)(((ks * 2 + bhs) ^ xr) << 4);
        uint32_t aH[4], aL[4];
        ldsm4(aH, aB + oA);
        ldsm4(aL, aB + 32768 + oA);
        uint32_t bH[4][4], bL[4][4];
#pragma unroll
        for (int g = 0; g < 4; g++) {
            ldsm4(bH[g], bB[g] + oB);
            ldsm4(bL[g], bB[g] + 32768 + oB);
        }
#pragma unroll
        for (int g = 0; g < 4; g++) {
            mma16816(C[2*g],   aH, bH[g][0], bH[g][1]);
            mma16816(C[2*g+1], aH, bH[g][2], bH[g][3]);
            mma16816(C[2*g],   aH, bL[g][0], bL[g][1]);
            mma16816(C[2*g+1], aH, bL[g][2], bL[g][3]);
            mma16816(C[2*g],   aL, bH[g][0], bH[g][1]);
            mma16816(C[2*g+1], aL, bH[g][2], bH[g][3]);
        }
    }
}

// ---- GEMM core: 128x128, 16 warps, fp16 single-pass ----
__device__ __forceinline__ void gemm_f16(uint32_t sAu, uint32_t sBu, float C[8][4]) {
    int tid = threadIdx.x, lane = tid & 31, wid = tid >> 5;
    int rm = (wid & 7) * 16, cn = (wid >> 3) * 64;
#pragma unroll
    for (int nf = 0; nf < 8; nf++)
#pragma unroll
        for (int q = 0; q < 4; q++) C[nf][q] = 0.f;

    int xr = lane & 7;
    int arow = xr + ((lane >> 3) & 1) * 8;
    int ahs = lane >> 4;
    int bhs = (lane >> 3) & 1;
    int bnr = xr + (lane >> 4) * 8;
    uint32_t aB = sAu + (uint32_t)(rm + arow) * 256;
    uint32_t bB[4];
#pragma unroll
    for (int g = 0; g < 4; g++) bB[g] = sBu + (uint32_t)(cn + g * 16 + bnr) * 256;

#pragma unroll
    for (int ks = 0; ks < 8; ks++) {
        uint32_t oA = (uint32_t)(((ks * 2 + ahs) ^ xr) << 4);
        uint32_t oB = (uint32_t)(((ks * 2 + bhs) ^ xr) << 4);
        uint32_t aH[4];
        ldsm4(aH, aB + oA);
        uint32_t bH[4][4];
#pragma unroll
        for (int g = 0; g < 4; g++) ldsm4(bH[g], bB[g] + oB);
#pragma unroll
        for (int g = 0; g < 4; g++) {
            mma16816h(C[2*g],   aH, bH[g][0], bH[g][1]);
            mma16816h(C[2*g+1], aH, bH[g][2], bH[g][3]);
        }
    }
}

// ---- GEMM core: 64x128, 8 warps, fp16 single-pass ----
__device__ __forceinline__ void gemm64_f16(uint32_t sAu, uint32_t sBu, float C[8][4]) {
    int tid = threadIdx.x, lane = tid & 31, wid = tid >> 5;
    int rm = (wid & 3) * 16, cn = (wid >> 2) * 64;
#pragma unroll
    for (int nf = 0; nf < 8; nf++)
#pragma unroll
        for (int q = 0; q < 4; q++) C[nf][q] = 0.f;

    int xr = lane & 7;
    int arow = xr + ((lane >> 3) & 1) * 8;
    int ahs = lane >> 4;
    int bhs = (lane >> 3) & 1;
    int bnr = xr + (lane >> 4) * 8;
    uint32_t aB = sAu + (uint32_t)(rm + arow) * 256;
    uint32_t bB[4];
#pragma unroll
    for (int g = 0; g < 4; g++) bB[g] = sBu + (uint32_t)(cn + g * 16 + bnr) * 256;

#pragma unroll
    for (int ks = 0; ks < 8; ks++) {
        uint32_t oA = (uint32_t)(((ks * 2 + ahs) ^ xr) << 4);
        uint32_t oB = (uint32_t)(((ks * 2 + bhs) ^ xr) << 4);
        uint32_t aH[4];
        ldsm4(aH, aB + oA);
        uint32_t bH[4][4];
#pragma unroll
        for (int g = 0; g < 4; g++) ldsm4(bH[g], bB[g] + oB);
#pragma unroll
        for (int g = 0; g < 4; g++) {
            mma16816h(C[2*g],   aH, bH[g][0], bH[g][1]);
            mma16816h(C[2*g+1], aH, bH[g][2], bH[g][3]);
        }
    }
}

__device__ __forceinline__ void storeC64(float* Cs, float C[8][4]) {
    int tid = threadIdx.x, lane = tid & 31, wid = tid >> 5;
    int rm = (wid & 3) * 16, cn = (wid >> 2) * 64;
    int r = lane >> 2, c2 = 2 * (lane & 3);
#pragma unroll
    for (int nf = 0; nf < 8; nf++) {
        int col = cn + nf * 8 + c2;
        *(float2*)(Cs + (rm + r) * CSTRIDE + col)     = make_float2(C[nf][0], C[nf][1]);
        *(float2*)(Cs + (rm + r + 8) * CSTRIDE + col) = make_float2(C[nf][2], C[nf][3]);
    }
}

// ---- 512-thr pipeline pieces ----
__device__ __forceinline__ void stage128(uint32_t dst, const float* src, int r0, int limit) {
    int tid = threadIdx.x;
#pragma unroll
    for (int it = 0; it < 8; it++) {
        int c = it * NT + tid;
        int row = c >> 5, part = c & 31;
        cpa16(dst + c * 16, src + (size_t)(r0 + row) * H + part * 4, (r0 + row) < limit);
    }
    CP_COMMIT();
}

__device__ __forceinline__ void convert_plain(char* stgP, char* sA) {
    const float* stg = (const float*)stgP;
    int tid = threadIdx.x;
#pragma unroll
    for (int it = 0; it < 4; it++) {
        int s = it * NT + tid;
        int row = s >> 4, kseg = s & 15;
        const float4* p = (const float4*)(stg + row * 128 + kseg * 8);
        float4 f0 = p[0], f1 = p[1];
        float v[8] = {f0.x, f0.y, f0.z, f0.w, f1.x, f1.y, f1.z, f1.w};
        uint32_t off = (uint32_t)row * 256 + (uint32_t)((kseg ^ (row & 7)) << 4);
        storeA8(sA, sA + 32768, off, v);
    }
}

__device__ __forceinline__ void convert_plain_h(char* stgP, char* sA) {
    const float* stg = (const float*)stgP;
    int tid = threadIdx.x;
#pragma unroll
    for (int it = 0; it < 4; it++) {
        int s = it * NT + tid;
        int row = s >> 4, kseg = s & 15;
        const float4* p = (const float4*)(stg + row * 128 + kseg * 8);
        float4 f0 = p[0], f1 = p[1];
        float v[8] = {f0.x, f0.y, f0.z, f0.w, f1.x, f1.y, f1.z, f1.w};
        uint32_t off = (uint32_t)row * 256 + (uint32_t)((kseg ^ (row & 7)) << 4);
        storeA8h(sA, off, v);
    }
}

__device__ __forceinline__ void copy_Bu(char* sB) {
    const uint4* g = (const uint4*)g_Bimg;
    uint4* d = (uint4*)sB;
    int tid = threadIdx.x;
#pragma unroll
    for (int it = 0; it < 8; it++) d[it * NT + tid] = g[it * NT + tid];
}

__device__ __forceinline__ void copy_Bh512(int hidx, char* sB) {
    const uint4* g = (const uint4*)(g_Bimg_h + (size_t)hidx * 32768);
    uint4* d = (uint4*)sB;
    int tid = threadIdx.x;
#pragma unroll
    for (int it = 0; it < 4; it++) d[it * NT + tid] = g[it * NT + tid];
}

// ---- 256-thr pieces ----
__device__ __forceinline__ void copy_Bh256(int hidx, char* sB) {
    const uint4* g = (const uint4*)(g_Bimg_h + (size_t)hidx * 32768);
    uint4* d = (uint4*)sB;
    int tid = threadIdx.x;
#pragma unroll
    for (int it = 0; it < 8; it++) d[it * 256 + tid] = g[it * 256 + tid];
}

__device__ __forceinline__ void stage_A64(uint32_t sb, const float* src, int r0, int limit) {
    int tid = threadIdx.x;
    uint32_t dst = sb + E_STG;
#pragma unroll
    for (int it = 0; it < 8; it++) {
        int c = it * 256 + tid;
        int row = c >> 5, part = c & 31;
        cpa16(dst + c * 16, src + (size_t)(r0 + row) * H + part * 4, (r0 + row) < limit);
    }
    CP_COMMIT();
}

__device__ __forceinline__ void convert64_h(char* sm) {
    const float* stg = (const float*)(sm + E_STG);
    char* sA = sm + E_C;
    int tid = threadIdx.x;
#pragma unroll
    for (int it = 0; it < 4; it++) {
        int s = it * 256 + tid;
        int row = s >> 4, kseg = s & 15;
        const float4* p = (const float4*)(stg + row * 128 + kseg * 8);
        float4 f0 = p[0], f1 = p[1];
        float v[8] = {f0.x, f0.y, f0.z, f0.w, f1.x, f1.y, f1.z, f1.w};
        uint32_t off = (uint32_t)row * 256 + (uint32_t)((kseg ^ (row & 7)) << 4);
        storeA8h(sA, off, v);
    }
}

__device__ __forceinline__ void load_idx64(char* sm, const int* eidx, int t, int E, int p) {
    int tid = threadIdx.x;
    int e0 = t * 64;
    int* rI = (int*)(sm + E_IDX + p * 512);
    if (tid < 64) {
        int ei = e0 + tid;
        rI[tid] = (ei < E) ? eidx[ei] : 0;
    } else if (tid < 128) {
        int q = tid - 64, ei = e0 + q;
        rI[64 + q] = (ei < E) ? eidx[(size_t)E + ei] : 0;
    }
}

__device__ __forceinline__ void stage64_h(uint32_t sb, const __half* src, int r0, int limit) {
    int tid = threadIdx.x;
    uint32_t dst = sb + EO_STG;
#pragma unroll
    for (int it = 0; it < 4; it++) {
        int c = it * 256 + tid;
        int row = c >> 4, part = c & 15;
        cpa16(dst + c * 16, src + (size_t)(r0 + row) * H + part * 8, (r0 + row) < limit);
    }
    CP_COMMIT();
}

__device__ __forceinline__ void convert_bn64(char* sm) {
    const __half* stg = (const __half*)(sm + EO_STG);
    const float4* sc4 = (const float4*)(sm + EO_SC);
    const float4* sh4 = (const float4*)(sm + EO_SH);
    char* sA = sm + EO_A;
    int tid = threadIdx.x;
#pragma unroll
    for (int it = 0; it < 4; it++) {
        int s = it * 256 + tid;
        int row = s >> 4, kseg = s & 15;
        const __half2* p = (const __half2*)(stg + row * 128 + kseg * 8);
        float2 a0 = __half22float2(p[0]);
        float2 a1 = __half22float2(p[1]);
        float2 a2 = __half22float2(p[2]);
        float2 a3 = __half22float2(p[3]);
        float4 s0 = sc4[kseg * 2], s1 = sc4[kseg * 2 + 1];
        float4 t0 = sh4[kseg * 2], t1 = sh4[kseg * 2 + 1];
        float v[8];
        v[0] = fmaxf(fmaf(a0.x, s0.x, t0.x), 0.f);
        v[1] = fmaxf(fmaf(a0.y, s0.y, t0.y), 0.f);
        v[2] = fmaxf(fmaf(a1.x, s0.z, t0.z), 0.f);
        v[3] = fmaxf(fmaf(a1.y, s0.w, t0.w), 0.f);
        v[4] = fmaxf(fmaf(a2.x, s1.x, t1.x), 0.f);
        v[5] = fmaxf(fmaf(a2.y, s1.y, t1.y), 0.f);
        v[6] = fmaxf(fmaf(a3.x, s1.z, t1.z), 0.f);
        v[7] = fmaxf(fmaf(a3.y, s1.w, t1.w), 0.f);
        uint32_t off = (uint32_t)row * 256 + (uint32_t)((kseg ^ (row & 7)) << 4);
        storeA8h(sA, off, v);
    }
}

__device__ __forceinline__ float2 h2f(uint32_t u) {
    __half2 h = *reinterpret_cast<__half2*>(&u);
    return __half22float2(h);
}

// ---------------------------------------------------------------------------
__global__ void k_init(const float* __restrict__ time_emb,
                       const float* __restrict__ Wt, const float* __restrict__ bt,
                       const float* __restrict__ Wo, const float* __restrict__ bo) {
    int j = threadIdx.x;
    for (int i = j; i < 4 * H; i += H) g_stats[i] = 0.0f;
    __shared__ float tv[H];
    float acc = bt[j];
    for (int k = 0; k < H; k++) acc += time_emb[k] * Wt[k * H + j];
    tv[j] = acc;
    __syncthreads();
    float c = bo[j];
    for (int k = 0; k < H; k++) c += tv[k] * Wo[k * H + j];
    g_cvec[j] = c;
}

// ---------------------------------------------------------------------------
// k_prep: grid (6, 8). blockIdx.x 0 -> WU split-bf16; 1-5 -> fp16 images.
// ---------------------------------------------------------------------------
__global__ void k_prep(const float* __restrict__ WU, const float* __restrict__ WV,
                       const float* __restrict__ WA, const float* __restrict__ WB,
                       const float* __restrict__ WC, const float* __restrict__ Wo) {
    const float* Ws[6] = {WU, WV, WA, WB, WC, Wo};
    const float* W = Ws[blockIdx.x];
    int base = blockIdx.y * 2048;
    int tid = threadIdx.x;
    if (blockIdx.x == 0) {
        for (int idx = base + tid; idx < base + 2048; idx += 256) {
            int k = idx >> 7, n = idx & 127;
            float v = W[k * H + n];
            __nv_bfloat16 hi = __float2bfloat16_rn(v);
            __nv_bfloat16 lo = __float2bfloat16_rn(v - __bfloat162float(hi));
            uint32_t off = (uint32_t)n * 256 + (uint32_t)((((k >> 3) ^ (n & 7))) << 4) + (k & 7) * 2;
            *(__nv_bfloat16*)(g_Bimg + off) = hi;
            *(__nv_bfloat16*)(g_Bimg + 32768 + off) = lo;
        }
    } else {
        unsigned char* imgh = g_Bimg_h + (size_t)(blockIdx.x - 1) * 32768;
        for (int idx = base + tid; idx < base + 2048; idx += 256) {
            int k = idx >> 7, n = idx & 127;
            float v = W[k * H + n];
            uint32_t off = (uint32_t)n * 256 + (uint32_t)((((k >> 3) ^ (n & 7))) << 4) + (k & 7) * 2;
            *(__half*)(imgh + off) = __float2half_rn(v);
        }
    }
}

// ---------------------------------------------------------------------------
// k_nodeU: persistent, Uh = h@WU + bU (split-bf16) -> g_agg fp32
// ---------------------------------------------------------------------------
__global__ __launch_bounds__(NT, 1) void k_nodeU(
        const float* __restrict__ h, const float* __restrict__ bU,
        int V, int nTiles) {
    extern __shared__ char sm[];
    uint32_t sb = smem_u32(sm);
    int tid = threadIdx.x, lane = tid & 31, wid = tid >> 5;
    int rm = (wid & 7) * 16, cn = (wid >> 3) * 64;
    int r_in = lane >> 2, c2 = 2 * (lane & 3);

    copy_Bu(sm + SM_B);
    float2 bv[8];
#pragma unroll
    for (int nf = 0; nf < 8; nf++) bv[nf] = *(const float2*)(bU + cn + nf * 8 + c2);

    int t = blockIdx.x;
    if (t >= nTiles) return;
    stage128(sb + SM_STAGE, h, t * 128, V);
    CP_WAIT0(); __syncthreads();
    convert_plain(sm + SM_STAGE, sm + SM_A);
    __syncthreads();

    while (t < nTiles) {
        int nxt = t + gridDim.x;
        if (nxt < nTiles) stage128(sb + SM_STAGE, h, nxt * 128, V);

        float C[8][4];
        gemm_compute(sb + SM_A, sb + SM_B, C);

        int r0 = t * 128;
#pragma unroll
        for (int nf = 0; nf < 8; nf++) {
#pragma unroll
            for (int hf = 0; hf < 2; hf++) {
                int row = r0 + rm + hf * 8 + r_in;
                if (row < V) {
                    int col = cn + nf * 8 + c2;
                    *(float2*)(g_agg + (size_t)row * 128 + col) =
                        make_float2(C[nf][2 * hf] + bv[nf].x, C[nf][2 * hf + 1] + bv[nf].y);
                }
            }
        }
        CP_WAIT0();
        __syncthreads();
        if (nxt < nTiles) convert_plain(sm + SM_STAGE, sm + SM_A);
        __syncthreads();
        t = nxt;
    }
}

// ---------------------------------------------------------------------------
// k_nodeVAB: persistent. One h tile read -> 3 fp16 GEMMs (WV, WA, WB).
// ---------------------------------------------------------------------------
__global__ __launch_bounds__(NT, 1) void k_nodeVAB(
        const float* __restrict__ h,
        const float* __restrict__ bV, const float* __restrict__ bA,
        const float* __restrict__ bB, int V, int nTiles) {
    extern __shared__ char sm[];
    uint32_t sb = smem_u32(sm);
    int tid = threadIdx.x, lane = tid & 31, wid = tid >> 5;
    int rm = (wid & 7) * 16, cn = (wid >> 3) * 64;
    int r_in = lane >> 2, c2 = 2 * (lane & 3);

    copy_Bh512(0, sm + NV_B);               // WV
    copy_Bh512(1, sm + NV_B + 32768);       // WA
    copy_Bh512(2, sm + NV_B + 65536);       // WB
    const float* biases[3] = {bV, bA, bB};

    int t = blockIdx.x;
    if (t >= nTiles) return;
    stage128(sb + NV_STG, h, t * 128, V);
    CP_WAIT0(); __syncthreads();
    convert_plain_h(sm + NV_STG, sm + NV_A);
    __syncthreads();

    while (t < nTiles) {
        int nxt = t + gridDim.x;
        if (nxt < nTiles) stage128(sb + NV_STG, h, nxt * 128, V);

        int r0 = t * 128;
#pragma unroll
        for (int g = 0; g < 3; g++) {
            float C[8][4];
            gemm_f16(sb + NV_A, sb + NV_B + g * 32768, C);
            float2 bv[8];
#pragma unroll
            for (int nf = 0; nf < 8; nf++)
                bv[nf] = *(const float2*)(biases[g] + cn + nf * 8 + c2);
#pragma unroll
            for (int nf = 0; nf < 8; nf++) {
#pragma unroll
                for (int hf = 0; hf < 2; hf++) {
                    int row = r0 + rm + hf * 8 + r_in;
                    if (row < V) {
                        int col = cn + nf * 8 + c2;
                        __half2 hv = __floats2half2_rn(C[nf][2 * hf] + bv[nf].x,
                                                       C[nf][2 * hf + 1] + bv[nf].y);
                        __half* dst;
                        if (g == 0)      dst = g_colpack_h + (size_t)row * 256 + col;        // Vn
                        else if (g == 1) dst = g_colpack_h + (size_t)row * 256 + 128 + col;  // Ah
                        else             dst = g_Bh_h + (size_t)row * 128 + col;             // Bh
                        *(__half2*)dst = hv;
                    }
                }
            }
        }
        CP_WAIT0();
        __syncthreads();
        if (nxt < nTiles) convert_plain_h(sm + NV_STG, sm + NV_A);
        __syncthreads();
        t = nxt;
    }
}

// ---------------------------------------------------------------------------
// k_edge: 2 CTAs/SM, M=64, fp16 MMA, cp.async staged e, fp16 gathers (R14)
// ---------------------------------------------------------------------------
__global__ __launch_bounds__(256, 2) void k_edge(
        const float* __restrict__ e, const float* __restrict__ bC,
        const int* __restrict__ eidx, int E, int nTiles) {
    extern __shared__ char sm[];
    uint32_t sb = smem_u32(sm);
    int tid = threadIdx.x, lane = tid & 31, w = tid >> 5;

    copy_Bh256(3, sm + E_B);   // WC fp16
    float4 bc = *(const float4*)(bC + lane * 4);
    float ss[4] = {0.f, 0.f, 0.f, 0.f}, sq[4] = {0.f, 0.f, 0.f, 0.f};

    int p = 0;
    int t0 = blockIdx.x;
    if (t0 < nTiles) {
        load_idx64(sm, eidx, t0, E, 0);
        stage_A64(sb, e, t0 * 64, E);
    }
    __syncthreads();

    for (int t = t0; t < nTiles; t += gridDim.x, p ^= 1) {
        int e0 = t * 64;
        const int* rI = (const int*)(sm + E_IDX + p * 512);
        const int* cI = rI + 64;

        CP_WAIT0();
        __syncthreads();
        convert64_h(sm);

#pragma unroll
        for (int i = tid; i < 640; i += 256) {
            int m = i & 63, sel = i >> 6;
            const char* ptr;
            if (sel < 4)      ptr = (const char*)g_colpack_h + (size_t)cI[m] * 512 + sel * 128;
            else if (sel < 6) ptr = (const char*)g_Bh_h + (size_t)rI[m] * 256 + (sel - 4) * 128;
            else              ptr = (const char*)g_agg + (size_t)rI[m] * 512 + (sel - 6) * 128;
            pf_l2(ptr);
        }
        __syncthreads();

        int nxt = t + gridDim.x;
        if (nxt < nTiles) {
            stage_A64(sb, e, nxt * 64, E);
            load_idx64(sm, eidx, nxt, E, p ^ 1);
        }

        float C[8][4];
        gemm64_f16(sb + E_C, sb + E_B, C);
        __syncthreads();
        storeC64((float*)(sm + E_C), C);
        __syncthreads();

        const float* Cs = (const float*)(sm + E_C);
        int m0 = w * 8;

        float4 cc; uint2 vnu, ahu, bhu;
        float* agp_cur;
        {
            int m = m0;
            int rv = rI[m], cv = cI[m];
            const __half* cp = g_colpack_h + (size_t)cv * 256;
            agp_cur = g_agg + (size_t)rv * 128;
            cc  = *(const float4*)(Cs + m * CSTRIDE + lane * 4);
            vnu = *(const uint2*)(cp + lane * 4);
            ahu = *(const uint2*)(cp + 128 + lane * 4);
            bhu = *(const uint2*)(g_Bh_h + (size_t)rv * 128 + lane * 4);
        }
#pragma unroll
        for (int k = 0; k < 8; k++) {
            int m = m0 + k;
            int ei = e0 + m;
            float4 ccn; uint2 vnn, ahn, bhn;
            float* agp_nxt = agp_cur;
            if (k < 7) {
                int mn = m + 1;
                int rv = rI[mn], cv = cI[mn];
                const __half* cp = g_colpack_h + (size_t)cv * 256;
                agp_nxt = g_agg + (size_t)rv * 128;
                ccn = *(const float4*)(Cs + mn * CSTRIDE + lane * 4);
                vnn = *(const uint2*)(cp + lane * 4);
                ahn = *(const uint2*)(cp + 128 + lane * 4);
                bhn = *(const uint2*)(g_Bh_h + (size_t)rv * 128 + lane * 4);
            }
            if (ei < E) {
                float2 vn0 = h2f(vnu.x), vn1 = h2f(vnu.y);
                float2 ah0 = h2f(ahu.x), ah1 = h2f(ahu.y);
                float2 bh0 = h2f(bhu.x), bh1 = h2f(bhu.y);
                float4 x;
                x.x = cc.x + bc.x + ah0.x + bh0.x;
                x.y = cc.y + bc.y + ah0.y + bh0.y;
                x.z = cc.z + bc.z + ah1.x + bh1.x;
                x.w = cc.w + bc.w + ah1.y + bh1.y;
                uint2 u;
                u.x = hpack(x.x, x.y);
                u.y = hpack(x.z, x.w);
                *(uint2*)(g_epre + (size_t)ei * H + lane * 4) = u;
                float ga = vn0.x / (1.f + __expf(-x.x));
                float gb = vn0.y / (1.f + __expf(-x.y));
                float gc = vn1.x / (1.f + __expf(-x.z));
                float gd = vn1.y / (1.f + __expf(-x.w));
                redv4(agp_cur + lane * 4, ga, gb, gc, gd);
                ss[0] += x.x; ss[1] += x.y; ss[2] += x.z; ss[3] += x.w;
                sq[0] += x.x * x.x; sq[1] += x.y * x.y;
                sq[2] += x.z * x.z; sq[3] += x.w * x.w;
            }
            cc = ccn; vnu = vnn; ahu = ahn; bhu = bhn; agp_cur = agp_nxt;
        }
    }

    __syncthreads();
    float* sr = (float*)(sm + E_C);
    float* qr = sr + 1024;
    *(float4*)(sr + w * 128 + lane * 4) = make_float4(ss[0], ss[1], ss[2], ss[3]);
    *(float4*)(qr + w * 128 + lane * 4) = make_float4(sq[0], sq[1], sq[2], sq[3]);
    __syncthreads();
    if (tid < 128) {
        float a = 0.f, b = 0.f;
#pragma unroll
        for (int ww = 0; ww < 8; ww++) { a += sr[ww * 128 + tid]; b += qr[ww * 128 + tid]; }
        atomicAdd(&g_stats[2 * H + tid], a);
        atomicAdd(&g_stats[3 * H + tid], b);
    }
}

// ---------------------------------------------------------------------------
// k_edgeout: 2 CTAs/SM, M=64, fp16 MMA, staged fp16 epre, fragment epilogue
// ---------------------------------------------------------------------------
__global__ __launch_bounds__(256, 2) void k_edgeout(
        const float* __restrict__ e, float* __restrict__ out, int E, int nTiles) {
    extern __shared__ char sm[];
    uint32_t sb = smem_u32(sm);
    int tid = threadIdx.x, lane = tid & 31, wid = tid >> 5;
    int rm = (wid & 3) * 16, cn = (wid >> 2) * 64;
    int r_in = lane >> 2, c2 = 2 * (lane & 3);

    copy_Bh256(4, sm + EO_B);   // Wo fp16
    if (tid < 128) {
        ((float*)(sm + EO_SC))[tid] = g_scale_e[tid];
        ((float*)(sm + EO_SH))[tid] = g_shift_e[tid];
    }
    float2 cv2[8];
#pragma unroll
    for (int nf = 0; nf < 8; nf++) cv2[nf] = *(const float2*)(g_cvec + cn + nf * 8 + c2);

    int t0 = blockIdx.x;
    if (t0 < nTiles) stage64_h(sb, g_epre, t0 * 64, E);
    __syncthreads();

    for (int t = t0; t < nTiles; t += gridDim.x) {
        int e0 = t * 64;
        CP_WAIT0();
        __syncthreads();
        convert_bn64(sm);
        {
            int row = tid >> 2, part = (tid & 3) * 32;
            if (e0 + row < E) pf_l2(e + (size_t)(e0 + row) * H + part);
        }
        __syncthreads();

        int nxt = t + gridDim.x;
        if (nxt < nTiles) stage64_h(sb, g_epre, nxt * 64, E);

        float C[8][4];
        gemm64_f16(sb + EO_A, sb + EO_B, C);

#pragma unroll
        for (int nf = 0; nf < 8; nf++) {
#pragma unroll
            for (int hf = 0; hf < 2; hf++) {
                int ei = e0 + rm + hf * 8 + r_in;
                if (ei < E) {
                    int col = cn + nf * 8 + c2;
                    float2 ev = *(const float2*)(e + (size_t)ei * H + col);
                    float2 o = make_float2(ev.x + C[nf][2 * hf] + cv2[nf].x,
                                           ev.y + C[nf][2 * hf + 1] + cv2[nf].y);
                    *(float2*)(out + (size_t)ei * H + col) = o;
                }
            }
        }
    }
}

// ---------------------------------------------------------------------------
__global__ void k_nstats(int rows) {
    int tid = threadIdx.x;
    int cg = tid & 31, wr = tid >> 5;
    float4 s = make_float4(0.f, 0.f, 0.f, 0.f);
    float4 qq = make_float4(0.f, 0.f, 0.f, 0.f);
    const float4* s4 = (const float4*)g_agg;
    for (int r = blockIdx.x * 8 + wr; r < rows; r += gridDim.x * 8) {
        float4 x = s4[(size_t)r * 32 + cg];
        s.x += x.x; s.y += x.y; s.z += x.z; s.w += x.w;
        qq.x += x.x * x.x; qq.y += x.y * x.y; qq.z += x.z * x.z; qq.w += x.w * x.w;
    }
    __shared__ float sh1[8][128], sh2[8][128];
    *(float4*)&sh1[wr][cg * 4] = s;
    *(float4*)&sh2[wr][cg * 4] = qq;
    __syncthreads();
    if (tid < 128) {
        float a = 0.f, b = 0.f;
#pragma unroll
        for (int ww = 0; ww < 8; ww++) { a += sh1[ww][tid]; b += sh2[ww][tid]; }
        atomicAdd(&g_stats[tid], a);
        atomicAdd(&g_stats[H + tid], b);
    }
}

// ---------------------------------------------------------------------------
__global__ void k_finalize(const float* __restrict__ gh, const float* __restrict__ bh,
                           const float* __restrict__ ge, const float* __restrict__ be,
                           int V, int E) {
    int j = threadIdx.x;
    float invV = 1.0f / (float)V, invE = 1.0f / (float)E;
    float mh = g_stats[j] * invV;
    float vh = g_stats[H + j] * invV - mh * mh;
    float sc = gh[j] * rsqrtf(vh + 1e-5f);
    g_scale_h[j] = sc;
    g_shift_h[j] = bh[j] - mh * sc;
    float me = g_stats[2 * H + j] * invE;
    float ve = g_stats[3 * H + j] * invE - me * me;
    float se = ge[j] * rsqrtf(ve + 1e-5f);
    g_scale_e[j] = se;
    g_shift_e[j] = be[j] - me * se;
}

// ---------------------------------------------------------------------------
__global__ void k_nodeout(const float* __restrict__ h, float* __restrict__ out, int V) {
    int idx = blockIdx.x * blockDim.x + threadIdx.x;
    int total = V * (H / 4);
    if (idx >= total) return;
    int j = (idx & 31) * 4;
    float4 a  = *(const float4*)&g_agg[(size_t)idx * 4];
    float4 sc = *(const float4*)&g_scale_h[j];
    float4 sh = *(const float4*)&g_shift_h[j];
    float4 hv = *(const float4*)&h[(size_t)idx * 4];
    float4 r;
    r.x = hv.x + fmaxf(fmaf(a.x, sc.x, sh.x), 0.f);
    r.y = hv.y + fmaxf(fmaf(a.y, sc.y, sh.y), 0.f);
    r.z = hv.z + fmaxf(fmaf(a.z, sc.z, sh.z), 0.f);
    r.w = hv.w + fmaxf(fmaf(a.w, sc.w, sh.w), 0.f);
    *(float4*)&out[(size_t)idx * 4] = r;
}

// ---------------------------------------------------------------------------
extern "C" void kernel_launch(void* const* d_in, const int* in_sizes, int n_in,
                              void* d_out, int out_size) {
    const float* h        = (const float*)d_in[0];
    const float* e        = (const float*)d_in[1];
    const float* time_emb = (const float*)d_in[2];
    const int*   eidx     = (const int*)d_in[3];
    const float* WU = (const float*)d_in[4];  const float* bU = (const float*)d_in[5];
    const float* WV = (const float*)d_in[6];  const float* bV = (const float*)d_in[7];
    const float* WA = (const float*)d_in[8];  const float* bA = (const float*)d_in[9];
    const float* WB = (const float*)d_in[10]; const float* bB = (const float*)d_in[11];
    const float* WC = (const float*)d_in[12]; const float* bC = (const float*)d_in[13];
    const float* Wt = (const float*)d_in[14]; const float* bt = (const float*)d_in[15];
    const float* Wo = (const float*)d_in[16]; const float* bo = (const float*)d_in[17];
    const float* gh = (const float*)d_in[18]; const float* bh = (const float*)d_in[19];
    const float* ge = (const float*)d_in[20]; const float* be = (const float*)d_in[21];

    int V = in_sizes[0] / H;
    int E = in_sizes[3] / 2;

    float* xout = (float*)d_out;
    float* eout = xout + (size_t)V * H;

    cudaFuncSetAttribute(k_nodeU,   cudaFuncAttributeMaxDynamicSharedMemorySize, SMEM_BYTES);
    cudaFuncSetAttribute(k_nodeVAB, cudaFuncAttributeMaxDynamicSharedMemorySize, NV_SMEM);
    cudaFuncSetAttribute(k_edge,    cudaFuncAttributeMaxDynamicSharedMemorySize, E_SMEM);
    cudaFuncSetAttribute(k_edgeout, cudaFuncAttributeMaxDynamicSharedMemorySize, EO_SMEM);

    int vTiles   = (V + 127) / 128;
    int eTiles64 = (E + 63) / 64;
    int gxNode = vTiles < 148 ? vTiles : 148;
    int gxE64 = eTiles64 < 296 ? eTiles64 : 296;

    k_init<<<1, 128>>>(time_emb, Wt, bt, Wo, bo);
    k_prep<<<dim3(6, 8), 256>>>(WU, WV, WA, WB, WC, Wo);
    k_nodeVAB<<<gxNode, NT, NV_SMEM>>>(h, bV, bA, bB, V, vTiles);
    k_nodeU<<<gxNode, NT, SMEM_BYTES>>>(h, bU, V, vTiles);
    k_edge<<<gxE64, 256, E_SMEM>>>(e, bC, eidx, E, eTiles64);
    k_nstats<<<512, 256>>>(V);
    k_finalize<<<1, 128>>>(gh, bh, ge, be, V, E);
    k_nodeout<<<(V * (H / 4) + 255) / 256, 256>>>(h, xout, V);
    k_edgeout<<<gxE64, 256, EO_SMEM>>>(e, eout, E, eTiles64);
}

// round 17
// speedup vs baseline: 1.5438x; 1.0324x over previous
#include <cuda_runtime.h>
#include <cuda_fp16.h>
#include <cstdint>

// ---------------------------------------------------------------------------
// DAGCondGNNEncoder (sm_103 HMMA path).
// R17: all-fp16 GEMMs. k_node4 = one h read -> 4 fp16 GEMMs (Vn/Ah/Bh/Uh,
//      4 resident B images, 224KB smem). k_edge stores its C tile as fp16
//      (halves the SMEM C round-trip on the L1-bound kernel). Everything
//      else identical to R16.
// ---------------------------------------------------------------------------

#define H 128
#define VMAX 50000
#define EMAX 625000
#define NT 512

// ---- device scratch ----
__device__ __align__(16) __half g_colpack_h[(size_t)VMAX * 256];  // [Vn|Ah] fp16
__device__ __align__(16) __half g_Bh_h[(size_t)VMAX * 128];       // Bh fp16
__device__ __align__(16) float  g_agg[(size_t)VMAX * 128];        // Uh + scatter
__device__ __align__(16) __half g_epre[(size_t)EMAX * H];         // fp16 e_pre
__device__ __align__(16) float g_stats[4 * H];
__device__ __align__(16) float g_cvec[H];
__device__ __align__(16) float g_scale_h[H];
__device__ __align__(16) float g_shift_h[H];
__device__ __align__(16) float g_scale_e[H];
__device__ __align__(16) float g_shift_e[H];
__device__ __align__(16) unsigned char g_Bimg_h[6 * 32768]; // fp16: WU,WV,WA,WB,WC,Wo

#define CSTRIDE 132

// ---- smem layout: k_node4 (512 thr, fp16, M=128, 4 Bs) ----
#define N4_A    0             // fp16 A 32KB
#define N4_STG  32768         // fp32 stage 64KB
#define N4_B    98304         // 4 x 32KB fp16 B
#define N4_SMEM 229376

// ---- smem layout: k_edge (2 CTAs/SM, 256 thr, M=64, fp16, staged) ----
#define E_IDX   0
#define E_C     2048          // A fp16 16KB / C fp16 16896B overlay
#define E_STG   36864         // raw fp32 stage 32KB
#define E_B     69632         // B fp16 32KB
#define E_SMEM  102400

// ---- smem layout: k_edgeout (2 CTAs/SM, 256 thr, M=64, fp16, staged) ----
#define EO_SC   0
#define EO_SH   512
#define EO_A    2048
#define EO_STG  18432
#define EO_B    34816
#define EO_SMEM 67584

// ---- helpers ----
__device__ __forceinline__ uint32_t smem_u32(const void* p) {
    uint32_t a;
    asm("{ .reg .u64 t; cvta.to.shared.u64 t, %1; cvt.u32.u64 %0, t; }" : "=r"(a) : "l"(p));
    return a;
}
__device__ __forceinline__ uint32_t hpack(float a, float b) {
    __half2 t = __floats2half2_rn(a, b);
    return *reinterpret_cast<uint32_t*>(&t);
}
__device__ __forceinline__ void storeA8h(char* dst, uint32_t off, const float* v) {
    uint4 hv;
    hv.x = hpack(v[0], v[1]); hv.y = hpack(v[2], v[3]);
    hv.z = hpack(v[4], v[5]); hv.w = hpack(v[6], v[7]);
    *(uint4*)(dst + off) = hv;
}
__device__ __forceinline__ void ldsm4(uint32_t r[4], uint32_t addr) {
    asm volatile("ldmatrix.sync.aligned.m8n8.x4.shared.b16 {%0,%1,%2,%3}, [%4];"
        : "=r"(r[0]), "=r"(r[1]), "=r"(r[2]), "=r"(r[3]) : "r"(addr));
}
__device__ __forceinline__ void mma16816h(float c[4], const uint32_t a[4], uint32_t b0, uint32_t b1) {
    asm volatile("mma.sync.aligned.m16n8k16.row.col.f32.f16.f16.f32 "
        "{%0,%1,%2,%3},{%4,%5,%6,%7},{%8,%9},{%0,%1,%2,%3};"
        : "+f"(c[0]), "+f"(c[1]), "+f"(c[2]), "+f"(c[3])
        : "r"(a[0]), "r"(a[1]), "r"(a[2]), "r"(a[3]), "r"(b0), "r"(b1));
}
__device__ __forceinline__ void redv4(float* p, float a, float b, float c, float d) {
    asm volatile("red.global.add.v4.f32 [%0], {%1, %2, %3, %4};"
        :: "l"(p), "f"(a), "f"(b), "f"(c), "f"(d) : "memory");
}
__device__ __forceinline__ void pf_l2(const void* p) {
    asm volatile("prefetch.global.L2 [%0];" :: "l"(p));
}
__device__ __forceinline__ void cpa16(uint32_t dst, const void* src, int pred) {
    asm volatile("{ .reg .pred p; setp.ne.b32 p, %2, 0;\n\t"
        "@p cp.async.cg.shared.global [%0], [%1], 16; }"
        :: "r"(dst), "l"(src), "r"(pred));
}
#define CP_COMMIT() asm volatile("cp.async.commit_group;" ::: "memory")
#define CP_WAIT0()  asm volatile("cp.async.wait_group 0;" ::: "memory")

// ---- GEMM core: 128x128, 16 warps, fp16 single-pass ----
__device__ __forceinline__ void gemm_f16(uint32_t sAu, uint32_t sBu, float C[8][4]) {
    int tid = threadIdx.x, lane = tid & 31, wid = tid >> 5;
    int rm = (wid & 7) * 16, cn = (wid >> 3) * 64;
#pragma unroll
    for (int nf = 0; nf < 8; nf++)
#pragma unroll
        for (int q = 0; q < 4; q++) C[nf][q] = 0.f;

    int xr = lane & 7;
    int arow = xr + ((lane >> 3) & 1) * 8;
    int ahs = lane >> 4;
    int bhs = (lane >> 3) & 1;
    int bnr = xr + (lane >> 4) * 8;
    uint32_t aB = sAu + (uint32_t)(rm + arow) * 256;
    uint32_t bB[4];
#pragma unroll
    for (int g = 0; g < 4; g++) bB[g] = sBu + (uint32_t)(cn + g * 16 + bnr) * 256;

#pragma unroll
    for (int ks = 0; ks < 8; ks++) {
        uint32_t oA = (uint32_t)(((ks * 2 + ahs) ^ xr) << 4);
        uint32_t oB = (uint32_t)(((ks * 2 + bhs) ^ xr) << 4);
        uint32_t aH[4];
        ldsm4(aH, aB + oA);
        uint32_t bH[4][4];
#pragma unroll
        for (int g = 0; g < 4; g++) ldsm4(bH[g], bB[g] + oB);
#pragma unroll
        for (int g = 0; g < 4; g++) {
            mma16816h(C[2*g],   aH, bH[g][0], bH[g][1]);
            mma16816h(C[2*g+1], aH, bH[g][2], bH[g][3]);
        }
    }
}

// ---- GEMM core: 64x128, 8 warps, fp16 single-pass ----
__device__ __forceinline__ void gemm64_f16(uint32_t sAu, uint32_t sBu, float C[8][4]) {
    int tid = threadIdx.x, lane = tid & 31, wid = tid >> 5;
    int rm = (wid & 3) * 16, cn = (wid >> 2) * 64;
#pragma unroll
    for (int nf = 0; nf < 8; nf++)
#pragma unroll
        for (int q = 0; q < 4; q++) C[nf][q] = 0.f;

    int xr = lane & 7;
    int arow = xr + ((lane >> 3) & 1) * 8;
    int ahs = lane >> 4;
    int bhs = (lane >> 3) & 1;
    int bnr = xr + (lane >> 4) * 8;
    uint32_t aB = sAu + (uint32_t)(rm + arow) * 256;
    uint32_t bB[4];
#pragma unroll
    for (int g = 0; g < 4; g++) bB[g] = sBu + (uint32_t)(cn + g * 16 + bnr) * 256;

#pragma unroll
    for (int ks = 0; ks < 8; ks++) {
        uint32_t oA = (uint32_t)(((ks * 2 + ahs) ^ xr) << 4);
        uint32_t oB = (uint32_t)(((ks * 2 + bhs) ^ xr) << 4);
        uint32_t aH[4];
        ldsm4(aH, aB + oA);
        uint32_t bH[4][4];
#pragma unroll
        for (int g = 0; g < 4; g++) ldsm4(bH[g], bB[g] + oB);
#pragma unroll
        for (int g = 0; g < 4; g++) {
            mma16816h(C[2*g],   aH, bH[g][0], bH[g][1]);
            mma16816h(C[2*g+1], aH, bH[g][2], bH[g][3]);
        }
    }
}

// fp16 C store (k_edge): halves the SMEM round trip
__device__ __forceinline__ void storeC64h(__half* Cs, float C[8][4]) {
    int tid = threadIdx.x, lane = tid & 31, wid = tid >> 5;
    int rm = (wid & 3) * 16, cn = (wid >> 2) * 64;
    int r = lane >> 2, c2 = 2 * (lane & 3);
#pragma unroll
    for (int nf = 0; nf < 8; nf++) {
        int col = cn + nf * 8 + c2;
        *(__half2*)(Cs + (rm + r) * CSTRIDE + col)     = __floats2half2_rn(C[nf][0], C[nf][1]);
        *(__half2*)(Cs + (rm + r + 8) * CSTRIDE + col) = __floats2half2_rn(C[nf][2], C[nf][3]);
    }
}

// ---- 512-thr pipeline pieces (k_node4) ----
__device__ __forceinline__ void stage128(uint32_t dst, const float* src, int r0, int limit) {
    int tid = threadIdx.x;
#pragma unroll
    for (int it = 0; it < 8; it++) {
        int c = it * NT + tid;
        int row = c >> 5, part = c & 31;
        cpa16(dst + c * 16, src + (size_t)(r0 + row) * H + part * 4, (r0 + row) < limit);
    }
    CP_COMMIT();
}

__device__ __forceinline__ void convert_plain_h(char* stgP, char* sA) {
    const float* stg = (const float*)stgP;
    int tid = threadIdx.x;
#pragma unroll
    for (int it = 0; it < 4; it++) {
        int s = it * NT + tid;
        int row = s >> 4, kseg = s & 15;
        const float4* p = (const float4*)(stg + row * 128 + kseg * 8);
        float4 f0 = p[0], f1 = p[1];
        float v[8] = {f0.x, f0.y, f0.z, f0.w, f1.x, f1.y, f1.z, f1.w};
        uint32_t off = (uint32_t)row * 256 + (uint32_t)((kseg ^ (row & 7)) << 4);
        storeA8h(sA, off, v);
    }
}

__device__ __forceinline__ void copy_Bh512(int hidx, char* sB) {
    const uint4* g = (const uint4*)(g_Bimg_h + (size_t)hidx * 32768);
    uint4* d = (uint4*)sB;
    int tid = threadIdx.x;
#pragma unroll
    for (int it = 0; it < 4; it++) d[it * NT + tid] = g[it * NT + tid];
}

// ---- 256-thr pieces ----
__device__ __forceinline__ void copy_Bh256(int hidx, char* sB) {
    const uint4* g = (const uint4*)(g_Bimg_h + (size_t)hidx * 32768);
    uint4* d = (uint4*)sB;
    int tid = threadIdx.x;
#pragma unroll
    for (int it = 0; it < 8; it++) d[it * 256 + tid] = g[it * 256 + tid];
}

__device__ __forceinline__ void stage_A64(uint32_t sb, const float* src, int r0, int limit) {
    int tid = threadIdx.x;
    uint32_t dst = sb + E_STG;
#pragma unroll
    for (int it = 0; it < 8; it++) {
        int c = it * 256 + tid;
        int row = c >> 5, part = c & 31;
        cpa16(dst + c * 16, src + (size_t)(r0 + row) * H + part * 4, (r0 + row) < limit);
    }
    CP_COMMIT();
}

__device__ __forceinline__ void convert64_h(char* sm) {
    const float* stg = (const float*)(sm + E_STG);
    char* sA = sm + E_C;
    int tid = threadIdx.x;
#pragma unroll
    for (int it = 0; it < 4; it++) {
        int s = it * 256 + tid;
        int row = s >> 4, kseg = s & 15;
        const float4* p = (const float4*)(stg + row * 128 + kseg * 8);
        float4 f0 = p[0], f1 = p[1];
        float v[8] = {f0.x, f0.y, f0.z, f0.w, f1.x, f1.y, f1.z, f1.w};
        uint32_t off = (uint32_t)row * 256 + (uint32_t)((kseg ^ (row & 7)) << 4);
        storeA8h(sA, off, v);
    }
}

__device__ __forceinline__ void load_idx64(char* sm, const int* eidx, int t, int E, int p) {
    int tid = threadIdx.x;
    int e0 = t * 64;
    int* rI = (int*)(sm + E_IDX + p * 512);
    if (tid < 64) {
        int ei = e0 + tid;
        rI[tid] = (ei < E) ? eidx[ei] : 0;
    } else if (tid < 128) {
        int q = tid - 64, ei = e0 + q;
        rI[64 + q] = (ei < E) ? eidx[(size_t)E + ei] : 0;
    }
}

__device__ __forceinline__ void stage64_h(uint32_t sb, const __half* src, int r0, int limit) {
    int tid = threadIdx.x;
    uint32_t dst = sb + EO_STG;
#pragma unroll
    for (int it = 0; it < 4; it++) {
        int c = it * 256 + tid;
        int row = c >> 4, part = c & 15;
        cpa16(dst + c * 16, src + (size_t)(r0 + row) * H + part * 8, (r0 + row) < limit);
    }
    CP_COMMIT();
}

__device__ __forceinline__ void convert_bn64(char* sm) {
    const __half* stg = (const __half*)(sm + EO_STG);
    const float4* sc4 = (const float4*)(sm + EO_SC);
    const float4* sh4 = (const float4*)(sm + EO_SH);
    char* sA = sm + EO_A;
    int tid = threadIdx.x;
#pragma unroll
    for (int it = 0; it < 4; it++) {
        int s = it * 256 + tid;
        int row = s >> 4, kseg = s & 15;
        const __half2* p = (const __half2*)(stg + row * 128 + kseg * 8);
        float2 a0 = __half22float2(p[0]);
        float2 a1 = __half22float2(p[1]);
        float2 a2 = __half22float2(p[2]);
        float2 a3 = __half22float2(p[3]);
        float4 s0 = sc4[kseg * 2], s1 = sc4[kseg * 2 + 1];
        float4 t0 = sh4[kseg * 2], t1 = sh4[kseg * 2 + 1];
        float v[8];
        v[0] = fmaxf(fmaf(a0.x, s0.x, t0.x), 0.f);
        v[1] = fmaxf(fmaf(a0.y, s0.y, t0.y), 0.f);
        v[2] = fmaxf(fmaf(a1.x, s0.z, t0.z), 0.f);
        v[3] = fmaxf(fmaf(a1.y, s0.w, t0.w), 0.f);
        v[4] = fmaxf(fmaf(a2.x, s1.x, t1.x), 0.f);
        v[5] = fmaxf(fmaf(a2.y, s1.y, t1.y), 0.f);
        v[6] = fmaxf(fmaf(a3.x, s1.z, t1.z), 0.f);
        v[7] = fmaxf(fmaf(a3.y, s1.w, t1.w), 0.f);
        uint32_t off = (uint32_t)row * 256 + (uint32_t)((kseg ^ (row & 7)) << 4);
        storeA8h(sA, off, v);
    }
}

__device__ __forceinline__ float2 h2f(uint32_t u) {
    __half2 h = *reinterpret_cast<__half2*>(&u);
    return __half22float2(h);
}

// ---------------------------------------------------------------------------
__global__ void k_init(const float* __restrict__ time_emb,
                       const float* __restrict__ Wt, const float* __restrict__ bt,
                       const float* __restrict__ Wo, const float* __restrict__ bo) {
    int j = threadIdx.x;
    for (int i = j; i < 4 * H; i += H) g_stats[i] = 0.0f;
    __shared__ float tv[H];
    float acc = bt[j];
    for (int k = 0; k < H; k++) acc += time_emb[k] * Wt[k * H + j];
    tv[j] = acc;
    __syncthreads();
    float c = bo[j];
    for (int k = 0; k < H; k++) c += tv[k] * Wo[k * H + j];
    g_cvec[j] = c;
}

// ---------------------------------------------------------------------------
// k_prep: grid (6, 8). fp16 swizzled images of all 6 weights.
// ---------------------------------------------------------------------------
__global__ void k_prep(const float* __restrict__ WU, const float* __restrict__ WV,
                       const float* __restrict__ WA, const float* __restrict__ WB,
                       const float* __restrict__ WC, const float* __restrict__ Wo) {
    const float* Ws[6] = {WU, WV, WA, WB, WC, Wo};
    const float* W = Ws[blockIdx.x];
    unsigned char* imgh = g_Bimg_h + (size_t)blockIdx.x * 32768;
    int base = blockIdx.y * 2048;
    int tid = threadIdx.x;
    for (int idx = base + tid; idx < base + 2048; idx += 256) {
        int k = idx >> 7, n = idx & 127;
        float v = W[k * H + n];
        uint32_t off = (uint32_t)n * 256 + (uint32_t)((((k >> 3) ^ (n & 7))) << 4) + (k & 7) * 2;
        *(__half*)(imgh + off) = __float2half_rn(v);
    }
}

// ---------------------------------------------------------------------------
// k_node4: persistent. One h tile read -> 4 fp16 GEMMs (WV, WA, WB, WU).
// ---------------------------------------------------------------------------
__global__ __launch_bounds__(NT, 1) void k_node4(
        const float* __restrict__ h,
        const float* __restrict__ bV, const float* __restrict__ bA,
        const float* __restrict__ bB, const float* __restrict__ bU,
        int V, int nTiles) {
    extern __shared__ char sm[];
    uint32_t sb = smem_u32(sm);
    int tid = threadIdx.x, lane = tid & 31, wid = tid >> 5;
    int rm = (wid & 7) * 16, cn = (wid >> 3) * 64;
    int r_in = lane >> 2, c2 = 2 * (lane & 3);

    copy_Bh512(1, sm + N4_B);               // WV
    copy_Bh512(2, sm + N4_B + 32768);       // WA
    copy_Bh512(3, sm + N4_B + 65536);       // WB
    copy_Bh512(0, sm + N4_B + 98304);       // WU
    const float* biases[4] = {bV, bA, bB, bU};

    int t = blockIdx.x;
    if (t >= nTiles) return;
    stage128(sb + N4_STG, h, t * 128, V);
    CP_WAIT0(); __syncthreads();
    convert_plain_h(sm + N4_STG, sm + N4_A);
    __syncthreads();

    while (t < nTiles) {
        int nxt = t + gridDim.x;
        if (nxt < nTiles) stage128(sb + N4_STG, h, nxt * 128, V);

        int r0 = t * 128;
#pragma unroll
        for (int g = 0; g < 4; g++) {
            float C[8][4];
            gemm_f16(sb + N4_A, sb + N4_B + g * 32768, C);
            float2 bv[8];
#pragma unroll
            for (int nf = 0; nf < 8; nf++)
                bv[nf] = *(const float2*)(biases[g] + cn + nf * 8 + c2);
#pragma unroll
            for (int nf = 0; nf < 8; nf++) {
#pragma unroll
                for (int hf = 0; hf < 2; hf++) {
                    int row = r0 + rm + hf * 8 + r_in;
                    if (row < V) {
                        int col = cn + nf * 8 + c2;
                        float ox = C[nf][2 * hf] + bv[nf].x;
                        float oy = C[nf][2 * hf + 1] + bv[nf].y;
                        if (g == 3) {
                            *(float2*)(g_agg + (size_t)row * 128 + col) = make_float2(ox, oy);
                        } else {
                            __half2 hv = __floats2half2_rn(ox, oy);
                            __half* dst;
                            if (g == 0)      dst = g_colpack_h + (size_t)row * 256 + col;
                            else if (g == 1) dst = g_colpack_h + (size_t)row * 256 + 128 + col;
                            else             dst = g_Bh_h + (size_t)row * 128 + col;
                            *(__half2*)dst = hv;
                        }
                    }
                }
            }
        }
        CP_WAIT0();
        __syncthreads();
        if (nxt < nTiles) convert_plain_h(sm + N4_STG, sm + N4_A);
        __syncthreads();
        t = nxt;
    }
}

// ---------------------------------------------------------------------------
// k_edge: 2 CTAs/SM, M=64, fp16 MMA, staged e, fp16 gathers, fp16 SMEM C
// ---------------------------------------------------------------------------
__global__ __launch_bounds__(256, 2) void k_edge(
        const float* __restrict__ e, const float* __restrict__ bC,
        const int* __restrict__ eidx, int E, int nTiles) {
    extern __shared__ char sm[];
    uint32_t sb = smem_u32(sm);
    int tid = threadIdx.x, lane = tid & 31, w = tid >> 5;

    copy_Bh256(4, sm + E_B);   // WC fp16
    float4 bc = *(const float4*)(bC + lane * 4);
    float ss[4] = {0.f, 0.f, 0.f, 0.f}, sq[4] = {0.f, 0.f, 0.f, 0.f};

    int p = 0;
    int t0 = blockIdx.x;
    if (t0 < nTiles) {
        load_idx64(sm, eidx, t0, E, 0);
        stage_A64(sb, e, t0 * 64, E);
    }
    __syncthreads();

    for (int t = t0; t < nTiles; t += gridDim.x, p ^= 1) {
        int e0 = t * 64;
        const int* rI = (const int*)(sm + E_IDX + p * 512);
        const int* cI = rI + 64;

        CP_WAIT0();
        __syncthreads();
        convert64_h(sm);

#pragma unroll
        for (int i = tid; i < 640; i += 256) {
            int m = i & 63, sel = i >> 6;
            const char* ptr;
            if (sel < 4)      ptr = (const char*)g_colpack_h + (size_t)cI[m] * 512 + sel * 128;
            else if (sel < 6) ptr = (const char*)g_Bh_h + (size_t)rI[m] * 256 + (sel - 4) * 128;
            else              ptr = (const char*)g_agg + (size_t)rI[m] * 512 + (sel - 6) * 128;
            pf_l2(ptr);
        }
        __syncthreads();

        int nxt = t + gridDim.x;
        if (nxt < nTiles) {
            stage_A64(sb, e, nxt * 64, E);
            load_idx64(sm, eidx, nxt, E, p ^ 1);
        }

        float C[8][4];
        gemm64_f16(sb + E_C, sb + E_B, C);
        __syncthreads();
        storeC64h((__half*)(sm + E_C), C);
        __syncthreads();

        const __half* Cs = (const __half*)(sm + E_C);
        int m0 = w * 8;

        uint2 ccu, vnu, ahu, bhu;
        float* agp_cur;
        {
            int m = m0;
            int rv = rI[m], cv = cI[m];
            const __half* cp = g_colpack_h + (size_t)cv * 256;
            agp_cur = g_agg + (size_t)rv * 128;
            ccu = *(const uint2*)(Cs + m * CSTRIDE + lane * 4);
            vnu = *(const uint2*)(cp + lane * 4);
            ahu = *(const uint2*)(cp + 128 + lane * 4);
            bhu = *(const uint2*)(g_Bh_h + (size_t)rv * 128 + lane * 4);
        }
#pragma unroll
        for (int k = 0; k < 8; k++) {
            int m = m0 + k;
            int ei = e0 + m;
            uint2 ccn, vnn, ahn, bhn;
            float* agp_nxt = agp_cur;
            if (k < 7) {
                int mn = m + 1;
                int rv = rI[mn], cv = cI[mn];
                const __half* cp = g_colpack_h + (size_t)cv * 256;
                agp_nxt = g_agg + (size_t)rv * 128;
                ccn = *(const uint2*)(Cs + mn * CSTRIDE + lane * 4);
                vnn = *(const uint2*)(cp + lane * 4);
                ahn = *(const uint2*)(cp + 128 + lane * 4);
                bhn = *(const uint2*)(g_Bh_h + (size_t)rv * 128 + lane * 4);
            }
            if (ei < E) {
                float2 cc0 = h2f(ccu.x), cc1 = h2f(ccu.y);
                float2 vn0 = h2f(vnu.x), vn1 = h2f(vnu.y);
                float2 ah0 = h2f(ahu.x), ah1 = h2f(ahu.y);
                float2 bh0 = h2f(bhu.x), bh1 = h2f(bhu.y);
                float4 x;
                x.x = cc0.x + bc.x + ah0.x + bh0.x;
                x.y = cc0.y + bc.y + ah0.y + bh0.y;
                x.z = cc1.x + bc.z + ah1.x + bh1.x;
                x.w = cc1.y + bc.w + ah1.y + bh1.y;
                uint2 u;
                u.x = hpack(x.x, x.y);
                u.y = hpack(x.z, x.w);
                *(uint2*)(g_epre + (size_t)ei * H + lane * 4) = u;
                float ga = vn0.x / (1.f + __expf(-x.x));
                float gb = vn0.y / (1.f + __expf(-x.y));
                float gc = vn1.x / (1.f + __expf(-x.z));
                float gd = vn1.y / (1.f + __expf(-x.w));
                redv4(agp_cur + lane * 4, ga, gb, gc, gd);
                ss[0] += x.x; ss[1] += x.y; ss[2] += x.z; ss[3] += x.w;
                sq[0] += x.x * x.x; sq[1] += x.y * x.y;
                sq[2] += x.z * x.z; sq[3] += x.w * x.w;
            }
            ccu = ccn; vnu = vnn; ahu = ahn; bhu = bhn; agp_cur = agp_nxt;
        }
    }

    __syncthreads();
    float* sr = (float*)(sm + E_C);
    float* qr = sr + 1024;
    *(float4*)(sr + w * 128 + lane * 4) = make_float4(ss[0], ss[1], ss[2], ss[3]);
    *(float4*)(qr + w * 128 + lane * 4) = make_float4(sq[0], sq[1], sq[2], sq[3]);
    __syncthreads();
    if (tid < 128) {
        float a = 0.f, b = 0.f;
#pragma unroll
        for (int ww = 0; ww < 8; ww++) { a += sr[ww * 128 + tid]; b += qr[ww * 128 + tid]; }
        atomicAdd(&g_stats[2 * H + tid], a);
        atomicAdd(&g_stats[3 * H + tid], b);
    }
}

// ---------------------------------------------------------------------------
// k_edgeout: 2 CTAs/SM, M=64, fp16 MMA, staged fp16 epre, fragment epilogue
// ---------------------------------------------------------------------------
__global__ __launch_bounds__(256, 2) void k_edgeout(
        const float* __restrict__ e, float* __restrict__ out, int E, int nTiles) {
    extern __shared__ char sm[];
    uint32_t sb = smem_u32(sm);
    int tid = threadIdx.x, lane = tid & 31, wid = tid >> 5;
    int rm = (wid & 3) * 16, cn = (wid >> 2) * 64;
    int r_in = lane >> 2, c2 = 2 * (lane & 3);

    copy_Bh256(5, sm + EO_B);   // Wo fp16
    if (tid < 128) {
        ((float*)(sm + EO_SC))[tid] = g_scale_e[tid];
        ((float*)(sm + EO_SH))[tid] = g_shift_e[tid];
    }
    float2 cv2[8];
#pragma unroll
    for (int nf = 0; nf < 8; nf++) cv2[nf] = *(const float2*)(g_cvec + cn + nf * 8 + c2);

    int t0 = blockIdx.x;
    if (t0 < nTiles) stage64_h(sb, g_epre, t0 * 64, E);
    __syncthreads();

    for (int t = t0; t < nTiles; t += gridDim.x) {
        int e0 = t * 64;
        CP_WAIT0();
        __syncthreads();
        convert_bn64(sm);
        {
            int row = tid >> 2, part = (tid & 3) * 32;
            if (e0 + row < E) pf_l2(e + (size_t)(e0 + row) * H + part);
        }
        __syncthreads();

        int nxt = t + gridDim.x;
        if (nxt < nTiles) stage64_h(sb, g_epre, nxt * 64, E);

        float C[8][4];
        gemm64_f16(sb + EO_A, sb + EO_B, C);

#pragma unroll
        for (int nf = 0; nf < 8; nf++) {
#pragma unroll
            for (int hf = 0; hf < 2; hf++) {
                int ei = e0 + rm + hf * 8 + r_in;
                if (ei < E) {
                    int col = cn + nf * 8 + c2;
                    float2 ev = *(const float2*)(e + (size_t)ei * H + col);
                    float2 o = make_float2(ev.x + C[nf][2 * hf] + cv2[nf].x,
                                           ev.y + C[nf][2 * hf + 1] + cv2[nf].y);
                    *(float2*)(out + (size_t)ei * H + col) = o;
                }
            }
        }
    }
}

// ---------------------------------------------------------------------------
__global__ void k_nstats(int rows) {
    int tid = threadIdx.x;
    int cg = tid & 31, wr = tid >> 5;
    float4 s = make_float4(0.f, 0.f, 0.f, 0.f);
    float4 qq = make_float4(0.f, 0.f, 0.f, 0.f);
    const float4* s4 = (const float4*)g_agg;
    for (int r = blockIdx.x * 8 + wr; r < rows; r += gridDim.x * 8) {
        float4 x = s4[(size_t)r * 32 + cg];
        s.x += x.x; s.y += x.y; s.z += x.z; s.w += x.w;
        qq.x += x.x * x.x; qq.y += x.y * x.y; qq.z += x.z * x.z; qq.w += x.w * x.w;
    }
    __shared__ float sh1[8][128], sh2[8][128];
    *(float4*)&sh1[wr][cg * 4] = s;
    *(float4*)&sh2[wr][cg * 4] = qq;
    __syncthreads();
    if (tid < 128) {
        float a = 0.f, b = 0.f;
#pragma unroll
        for (int ww = 0; ww < 8; ww++) { a += sh1[ww][tid]; b += sh2[ww][tid]; }
        atomicAdd(&g_stats[tid], a);
        atomicAdd(&g_stats[H + tid], b);
    }
}

// ---------------------------------------------------------------------------
__global__ void k_finalize(const float* __restrict__ gh, const float* __restrict__ bh,
                           const float* __restrict__ ge, const float* __restrict__ be,
                           int V, int E) {
    int j = threadIdx.x;
    float invV = 1.0f / (float)V, invE = 1.0f / (float)E;
    float mh = g_stats[j] * invV;
    float vh = g_stats[H + j] * invV - mh * mh;
    float sc = gh[j] * rsqrtf(vh + 1e-5f);
    g_scale_h[j] = sc;
    g_shift_h[j] = bh[j] - mh * sc;
    float me = g_stats[2 * H + j] * invE;
    float ve = g_stats[3 * H + j] * invE - me * me;
    float se = ge[j] * rsqrtf(ve + 1e-5f);
    g_scale_e[j] = se;
    g_shift_e[j] = be[j] - me * se;
}

// ---------------------------------------------------------------------------
__global__ void k_nodeout(const float* __restrict__ h, float* __restrict__ out, int V) {
    int idx = blockIdx.x * blockDim.x + threadIdx.x;
    int total = V * (H / 4);
    if (idx >= total) return;
    int j = (idx & 31) * 4;
    float4 a  = *(const float4*)&g_agg[(size_t)idx * 4];
    float4 sc = *(const float4*)&g_scale_h[j];
    float4 sh = *(const float4*)&g_shift_h[j];
    float4 hv = *(const float4*)&h[(size_t)idx * 4];
    float4 r;
    r.x = hv.x + fmaxf(fmaf(a.x, sc.x, sh.x), 0.f);
    r.y = hv.y + fmaxf(fmaf(a.y, sc.y, sh.y), 0.f);
    r.z = hv.z + fmaxf(fmaf(a.z, sc.z, sh.z), 0.f);
    r.w = hv.w + fmaxf(fmaf(a.w, sc.w, sh.w), 0.f);
    *(float4*)&out[(size_t)idx * 4] = r;
}

// ---------------------------------------------------------------------------
extern "C" void kernel_launch(void* const* d_in, const int* in_sizes, int n_in,
                              void* d_out, int out_size) {
    const float* h        = (const float*)d_in[0];
    const float* e        = (const float*)d_in[1];
    const float* time_emb = (const float*)d_in[2];
    const int*   eidx     = (const int*)d_in[3];
    const float* WU = (const float*)d_in[4];  const float* bU = (const float*)d_in[5];
    const float* WV = (const float*)d_in[6];  const float* bV = (const float*)d_in[7];
    const float* WA = (const float*)d_in[8];  const float* bA = (const float*)d_in[9];
    const float* WB = (const float*)d_in[10]; const float* bB = (const float*)d_in[11];
    const float* WC = (const float*)d_in[12]; const float* bC = (const float*)d_in[13];
    const float* Wt = (const float*)d_in[14]; const float* bt = (const float*)d_in[15];
    const float* Wo = (const float*)d_in[16]; const float* bo = (const float*)d_in[17];
    const float* gh = (const float*)d_in[18]; const float* bh = (const float*)d_in[19];
    const float* ge = (const float*)d_in[20]; const float* be = (const float*)d_in[21];

    int V = in_sizes[0] / H;
    int E = in_sizes[3] / 2;

    float* xout = (float*)d_out;
    float* eout = xout + (size_t)V * H;

    cudaFuncSetAttribute(k_node4,   cudaFuncAttributeMaxDynamicSharedMemorySize, N4_SMEM);
    cudaFuncSetAttribute(k_edge,    cudaFuncAttributeMaxDynamicSharedMemorySize, E_SMEM);
    cudaFuncSetAttribute(k_edgeout, cudaFuncAttributeMaxDynamicSharedMemorySize, EO_SMEM);

    int vTiles   = (V + 127) / 128;
    int eTiles64 = (E + 63) / 64;
    int gxNode = vTiles < 148 ? vTiles : 148;
    int gxE64 = eTiles64 < 296 ? eTiles64 : 296;

    k_init<<<1, 128>>>(time_emb, Wt, bt, Wo, bo);
    k_prep<<<dim3(6, 8), 256>>>(WU, WV, WA, WB, WC, Wo);
    k_node4<<<gxNode, NT, N4_SMEM>>>(h, bV, bA, bB, bU, V, vTiles);
    k_edge<<<gxE64, 256, E_SMEM>>>(e, bC, eidx, E, eTiles64);
    k_nstats<<<512, 256>>>(V);
    k_finalize<<<1, 128>>>(gh, bh, ge, be, V, E);
    k_nodeout<<<(V * (H / 4) + 255) / 256, 256>>>(h, xout, V);
    k_edgeout<<<gxE64, 256, EO_SMEM>>>(e, eout, E, eTiles64);
}